// round 1
// baseline (speedup 1.0000x reference)
#include <cuda_runtime.h>
#include <math.h>

#define D_MODEL  1024
#define N_HEADS  16
#define HEAD_DIM 64
#define B_SIZE   4
#define T_SEQ    2048
#define M_ROWS   (B_SIZE * T_SEQ)   // 8192

#define NEG_INF  (__int_as_float(0xff800000))

// Scratch (device globals: no allocations allowed)
__device__ float g_q[(size_t)B_SIZE * N_HEADS * T_SEQ * HEAD_DIM];   // (B,H,T,hd)
__device__ float g_attn[(size_t)M_ROWS * D_MODEL];                   // (B,T,D)

// ---------------------------------------------------------------------------
// C = A(M=8192, K=1024) @ W(N=1024, K=1024)^T
// split==0: C row-major (M,N).  split==1: C in (B,H,T,hd) head-split layout.
// Tile 64x64, BK=16, 256 threads, 4x4 microtile. Smem stored k-major so
// fragment loads are contiguous float4.
// ---------------------------------------------------------------------------
__global__ void __launch_bounds__(256) gemm_tn(const float* __restrict__ A,
                                               const float* __restrict__ W,
                                               float* __restrict__ C,
                                               int split)
{
    __shared__ float As[16][68];
    __shared__ float Ws[16][68];

    const int tid = threadIdx.x;
    const int tx  = tid & 15;          // 0..15 -> output cols
    const int ty  = tid >> 4;          // 0..15 -> output rows
    const int row0 = blockIdx.y * 64;
    const int col0 = blockIdx.x * 64;

    // loader mapping: each thread loads one float4 of A and one of W per k-step
    const int lr = tid >> 2;           // 0..63 tile row
    const int lc = (tid & 3) * 4;      // 0,4,8,12 k-offset

    float c[4][4];
#pragma unroll
    for (int i = 0; i < 4; i++)
#pragma unroll
        for (int j = 0; j < 4; j++) c[i][j] = 0.f;

    const float* Aptr = A + (size_t)(row0 + lr) * 1024 + lc;
    const float* Wptr = W + (size_t)(col0 + lr) * 1024 + lc;

    for (int k0 = 0; k0 < 1024; k0 += 16) {
        float4 a4 = *(const float4*)(Aptr + k0);
        float4 w4 = *(const float4*)(Wptr + k0);
        As[lc + 0][lr] = a4.x; As[lc + 1][lr] = a4.y;
        As[lc + 2][lr] = a4.z; As[lc + 3][lr] = a4.w;
        Ws[lc + 0][lr] = w4.x; Ws[lc + 1][lr] = w4.y;
        Ws[lc + 2][lr] = w4.z; Ws[lc + 3][lr] = w4.w;
        __syncthreads();

#pragma unroll
        for (int kk = 0; kk < 16; kk++) {
            float4 av = *(const float4*)&As[kk][ty * 4];
            float4 wv = *(const float4*)&Ws[kk][tx * 4];
            float a[4] = {av.x, av.y, av.z, av.w};
            float w[4] = {wv.x, wv.y, wv.z, wv.w};
#pragma unroll
            for (int i = 0; i < 4; i++)
#pragma unroll
                for (int j = 0; j < 4; j++)
                    c[i][j] += a[i] * w[j];
        }
        __syncthreads();
    }

    if (split) {
#pragma unroll
        for (int i = 0; i < 4; i++) {
            const int m = row0 + ty * 4 + i;
            const int b = m >> 11;          // / T_SEQ
            const int t = m & 2047;
#pragma unroll
            for (int j = 0; j < 4; j++) {
                const int n = col0 + tx * 4 + j;
                const int h = n >> 6;
                const int d = n & 63;
                C[(((size_t)b * N_HEADS + h) * T_SEQ + t) * HEAD_DIM + d] = c[i][j];
            }
        }
    } else {
#pragma unroll
        for (int i = 0; i < 4; i++) {
            const int m = row0 + ty * 4 + i;
#pragma unroll
            for (int j = 0; j < 4; j++) {
                const int n = col0 + tx * 4 + j;
                C[(size_t)m * D_MODEL + n] = c[i][j];
            }
        }
    }
}

// ---------------------------------------------------------------------------
// Flash attention, causal. 1 thread = 1 query row.
// BQ=128 queries per block, BKV=64 keys per tile.
// q/k/v in (B,H,T,hd); output written into (B,T,D) for the O-projection GEMM.
// ---------------------------------------------------------------------------
#define BQ  128
#define BKV 64
#define KPAD 68      // row stride (floats) for K/V tiles: 16B aligned, low conflict
#define SPAD 65      // row stride for score tile

__global__ void __launch_bounds__(BQ) attn_kernel(const float* __restrict__ q,
                                                  const float* __restrict__ k,
                                                  const float* __restrict__ v,
                                                  float* __restrict__ o)
{
    extern __shared__ float smem[];
    float* Ksh = smem;                       // [BKV][KPAD]
    float* Vsh = Ksh + BKV * KPAD;           // [BKV][KPAD]
    float* Ssh = Vsh + BKV * KPAD;           // [BQ][SPAD]

    const int b  = blockIdx.z;
    const int h  = blockIdx.y;
    const int qb = blockIdx.x;
    const int i  = threadIdx.x;              // query row within tile
    const int qi = qb * BQ + i;

    const size_t head_off = ((size_t)b * N_HEADS + h) * T_SEQ * HEAD_DIM;
    const float* qrow  = q + head_off + (size_t)qi * HEAD_DIM;
    const float* kbase = k + head_off;
    const float* vbase = v + head_off;

    float qreg[HEAD_DIM];
#pragma unroll
    for (int d = 0; d < HEAD_DIM; d += 4) {
        float4 q4 = *(const float4*)(qrow + d);
        qreg[d + 0] = q4.x * 0.125f;   // 1/sqrt(64)
        qreg[d + 1] = q4.y * 0.125f;
        qreg[d + 2] = q4.z * 0.125f;
        qreg[d + 3] = q4.w * 0.125f;
    }

    float acc[HEAD_DIM];
#pragma unroll
    for (int d = 0; d < HEAD_DIM; d++) acc[d] = 0.f;
    float mrun = NEG_INF;
    float lrun = 0.f;

    const int nkb = 2 * qb + 2;   // key tiles needed (BQ = 2*BKV)

    // tile loader mapping: 128 threads load 64x64 floats -> 32 each
    const int lr = i >> 1;
    const int lc0 = (i & 1) * 32;

    for (int kb = 0; kb < nkb; kb++) {
        const float* kr = kbase + ((size_t)kb * BKV + lr) * HEAD_DIM + lc0;
        const float* vr = vbase + ((size_t)kb * BKV + lr) * HEAD_DIM + lc0;
#pragma unroll
        for (int c = 0; c < 32; c += 4) {
            *(float4*)&Ksh[lr * KPAD + lc0 + c] = *(const float4*)(kr + c);
            *(float4*)&Vsh[lr * KPAD + lc0 + c] = *(const float4*)(vr + c);
        }
        __syncthreads();

        // scores for this tile
        float tilemax = NEG_INF;
        for (int j = 0; j < BKV; j++) {
            const int kj = kb * BKV + j;
            float s = NEG_INF;
            if (kj <= qi) {
                s = 0.f;
                const float* krow = &Ksh[j * KPAD];
#pragma unroll
                for (int d = 0; d < HEAD_DIM; d += 4) {
                    float4 k4 = *(const float4*)(krow + d);
                    s += qreg[d + 0] * k4.x + qreg[d + 1] * k4.y
                       + qreg[d + 2] * k4.z + qreg[d + 3] * k4.w;
                }
            }
            Ssh[i * SPAD + j] = s;
            tilemax = fmaxf(tilemax, s);
        }

        const float mnew = fmaxf(mrun, tilemax);
        const float corr = __expf(mrun - mnew);
        lrun *= corr;
#pragma unroll
        for (int d = 0; d < HEAD_DIM; d++) acc[d] *= corr;

        for (int j = 0; j < BKV; j++) {
            const float p = __expf(Ssh[i * SPAD + j] - mnew);
            lrun += p;
            const float* vrow = &Vsh[j * KPAD];
#pragma unroll
            for (int d = 0; d < HEAD_DIM; d += 4) {
                float4 v4 = *(const float4*)(vrow + d);
                acc[d + 0] += p * v4.x;
                acc[d + 1] += p * v4.y;
                acc[d + 2] += p * v4.z;
                acc[d + 3] += p * v4.w;
            }
        }
        mrun = mnew;
        __syncthreads();
    }

    const float inv = 1.f / lrun;
    float* orow = o + ((size_t)b * T_SEQ + qi) * D_MODEL + h * HEAD_DIM;
#pragma unroll
    for (int d = 0; d < HEAD_DIM; d += 4) {
        float4 r;
        r.x = acc[d + 0] * inv;
        r.y = acc[d + 1] * inv;
        r.z = acc[d + 2] * inv;
        r.w = acc[d + 3] * inv;
        *(float4*)(orow + d) = r;
    }
}

// ---------------------------------------------------------------------------
extern "C" void kernel_launch(void* const* d_in, const int* in_sizes, int n_in,
                              void* d_out, int out_size)
{
    const float* x  = (const float*)d_in[0];
    const float* Wq = (const float*)d_in[1];
    const float* Wk = (const float*)d_in[2];
    const float* Wv = (const float*)d_in[3];
    const float* Wo = (const float*)d_in[4];

    float* out  = (float*)d_out;                          // (B,T,D)
    float* kout = out  + (size_t)M_ROWS * D_MODEL;        // (B,H,T,hd)
    float* vout = kout + (size_t)M_ROWS * D_MODEL;        // (B,H,T,hd)

    float *gq, *gattn;
    cudaGetSymbolAddress((void**)&gq, g_q);
    cudaGetSymbolAddress((void**)&gattn, g_attn);

    dim3 gg(D_MODEL / 64, M_ROWS / 64);
    gemm_tn<<<gg, 256>>>(x, Wq, gq,   1);
    gemm_tn<<<gg, 256>>>(x, Wk, kout, 1);
    gemm_tn<<<gg, 256>>>(x, Wv, vout, 1);

    const int attn_smem = (BKV * KPAD + BKV * KPAD + BQ * SPAD) * (int)sizeof(float);
    cudaFuncSetAttribute(attn_kernel, cudaFuncAttributeMaxDynamicSharedMemorySize,
                         attn_smem);
    attn_kernel<<<dim3(T_SEQ / BQ, N_HEADS, B_SIZE), BQ, attn_smem>>>(gq, kout, vout, gattn);

    gemm_tn<<<gg, 256>>>(gattn, Wo, out, 0);
}

// round 3
// speedup vs baseline: 1.5088x; 1.5088x over previous
#include <cuda_runtime.h>
#include <cuda_bf16.h>
#include <cstdint>
#include <math.h>

#define D_MODEL  1024
#define N_HEADS  16
#define HEAD_DIM 64
#define B_SIZE   4
#define T_SEQ    2048
#define M_ROWS   (B_SIZE * T_SEQ)   // 8192
#define KDIM     1024

#define NEG_INF  (__int_as_float(0xff800000))

// ---------------------------------------------------------------------------
// Scratch (device globals: no allocations allowed)
// ---------------------------------------------------------------------------
__device__ float g_q[(size_t)B_SIZE * N_HEADS * T_SEQ * HEAD_DIM];   // (B,H,T,hd)
__device__ float g_attn[(size_t)M_ROWS * D_MODEL];                   // (B,T,D)

__device__ __nv_bfloat16 g_xh[(size_t)M_ROWS * D_MODEL];
__device__ __nv_bfloat16 g_xl[(size_t)M_ROWS * D_MODEL];
__device__ __nv_bfloat16 g_wqh[(size_t)D_MODEL * D_MODEL];
__device__ __nv_bfloat16 g_wql[(size_t)D_MODEL * D_MODEL];
__device__ __nv_bfloat16 g_wkh[(size_t)D_MODEL * D_MODEL];
__device__ __nv_bfloat16 g_wkl[(size_t)D_MODEL * D_MODEL];
__device__ __nv_bfloat16 g_wvh[(size_t)D_MODEL * D_MODEL];
__device__ __nv_bfloat16 g_wvl[(size_t)D_MODEL * D_MODEL];
__device__ __nv_bfloat16 g_woh[(size_t)D_MODEL * D_MODEL];
__device__ __nv_bfloat16 g_wol[(size_t)D_MODEL * D_MODEL];
__device__ __nv_bfloat16 g_ah[(size_t)M_ROWS * D_MODEL];
__device__ __nv_bfloat16 g_al[(size_t)M_ROWS * D_MODEL];

// ---------------------------------------------------------------------------
// PTX helpers (base ISA only — NO 'a'-gated instructions)
// ---------------------------------------------------------------------------
__device__ __forceinline__ uint32_t smem_to_u32(const void* p) {
    uint32_t a;
    asm("{ .reg .u64 t; cvta.to.shared.u64 t, %1; cvt.u32.u64 %0, t; }"
        : "=r"(a) : "l"(p));
    return a;
}

#define CP_ASYNC16(dst, src) \
    asm volatile("cp.async.cg.shared.global [%0], [%1], 16;" :: "r"(dst), "l"(src))
#define CP_COMMIT() asm volatile("cp.async.commit_group;" ::: "memory")
#define CP_WAIT(n)  asm volatile("cp.async.wait_group %0;" :: "n"(n) : "memory")

#define LDSM_X4(r0, r1, r2, r3, addr) \
    asm volatile("ldmatrix.sync.aligned.m8n8.x4.shared.b16 {%0,%1,%2,%3}, [%4];" \
                 : "=r"(r0), "=r"(r1), "=r"(r2), "=r"(r3) : "r"(addr))

#define MMA_BF16(c, a, b) \
    asm volatile("mma.sync.aligned.m16n8k16.row.col.f32.bf16.bf16.f32 " \
                 "{%0,%1,%2,%3}, {%4,%5,%6,%7}, {%8,%9}, {%0,%1,%2,%3};" \
                 : "+f"((c)[0]), "+f"((c)[1]), "+f"((c)[2]), "+f"((c)[3]) \
                 : "r"((a)[0]), "r"((a)[1]), "r"((a)[2]), "r"((a)[3]), \
                   "r"((b)[0]), "r"((b)[1]))

// ---------------------------------------------------------------------------
// fp32 -> (bf16 hi, bf16 lo) splitter.  n4 = element count / 4.
// ---------------------------------------------------------------------------
__global__ void __launch_bounds__(256) split_bf16(const float* __restrict__ x,
                                                  __nv_bfloat16* __restrict__ hi,
                                                  __nv_bfloat16* __restrict__ lo,
                                                  int n4)
{
    int i = blockIdx.x * blockDim.x + threadIdx.x;
    if (i >= n4) return;
    float4 v = ((const float4*)x)[i];
    __nv_bfloat16 h0 = __float2bfloat16(v.x);
    __nv_bfloat16 h1 = __float2bfloat16(v.y);
    __nv_bfloat16 h2 = __float2bfloat16(v.z);
    __nv_bfloat16 h3 = __float2bfloat16(v.w);
    __nv_bfloat162* hp = (__nv_bfloat162*)hi;
    __nv_bfloat162* lp = (__nv_bfloat162*)lo;
    hp[i * 2 + 0] = __nv_bfloat162(h0, h1);
    hp[i * 2 + 1] = __nv_bfloat162(h2, h3);
    lp[i * 2 + 0] = __nv_bfloat162(__float2bfloat16(v.x - __bfloat162float(h0)),
                                   __float2bfloat16(v.y - __bfloat162float(h1)));
    lp[i * 2 + 1] = __nv_bfloat162(__float2bfloat16(v.z - __bfloat162float(h2)),
                                   __float2bfloat16(v.w - __bfloat162float(h3)));
}

// ---------------------------------------------------------------------------
// mma.sync split-bf16 GEMM:  C(8192x1024) = A @ W^T  via  Ah*Wh + Ah*Wl + Al*Wh
// (all three products accumulated into one fp32 register fragment).
// CTA tile 128x128, BK=32, 256 threads (8 warps, warp tile 64x32),
// cp.async 2-stage double buffer, ldmatrix fragment loads.
// split==1: C written in (B,H,T,hd) layout.  split==0: row-major (M,N).
// ---------------------------------------------------------------------------
#define BM 128
#define BN 128
#define BK 32
#define NKI (KDIM / BK)          // 32
#define SKP 40                   // smem row stride in bf16 (pad 8 -> conflict-free)
#define TILE_B (BM * SKP * 2)    // 10240 bytes per tile
#define STAGE_B (4 * TILE_B)     // Ah, Al, Bh, Bl
#define GEMM_SMEM_BYTES (2 * STAGE_B)

__global__ void __launch_bounds__(256) gemm_bf16x3(
    const __nv_bfloat16* __restrict__ Ah, const __nv_bfloat16* __restrict__ Al,
    const __nv_bfloat16* __restrict__ Bh, const __nv_bfloat16* __restrict__ Bl,
    float* __restrict__ C, int split)
{
    extern __shared__ char smem_raw[];
    const uint32_t smem = smem_to_u32(smem_raw);

    const int tid  = threadIdx.x;
    const int wid  = tid >> 5;
    const int lane = tid & 31;
    const int row0 = blockIdx.y * BM;
    const int col0 = blockIdx.x * BN;

    const int wm = wid & 1;          // 0..1 -> m offset 0/64
    const int wn = wid >> 1;         // 0..3 -> n offset 0/32/64/96
    const int m0 = wm * 64;
    const int n0 = wn * 32;

    // ---- global->smem load mapping: thread t handles row t/2, 16B-chunk pair
    const int lrow   = tid >> 1;            // 0..127
    const int lcol16 = (tid & 1) * 16;      // 0 or 16 (bf16 elements)
    const size_t a_goff = (size_t)(row0 + lrow) * KDIM + lcol16;
    const size_t b_goff = (size_t)(col0 + lrow) * KDIM + lcol16;
    const uint32_t sdst0 = (uint32_t)(lrow * SKP + lcol16) * 2;   // byte offset in tile

    auto load_stage = [&](int stage, int kt) {
        const uint32_t sb = smem + (uint32_t)stage * STAGE_B;
        const size_t ko = (size_t)kt * BK;
        const char* s0 = (const char*)(Ah + a_goff + ko);
        const char* s1 = (const char*)(Al + a_goff + ko);
        const char* s2 = (const char*)(Bh + b_goff + ko);
        const char* s3 = (const char*)(Bl + b_goff + ko);
#pragma unroll
        for (int c = 0; c < 2; c++) {
            CP_ASYNC16(sb + 0 * TILE_B + sdst0 + c * 16, s0 + c * 16);
            CP_ASYNC16(sb + 1 * TILE_B + sdst0 + c * 16, s1 + c * 16);
            CP_ASYNC16(sb + 2 * TILE_B + sdst0 + c * 16, s2 + c * 16);
            CP_ASYNC16(sb + 3 * TILE_B + sdst0 + c * 16, s3 + c * 16);
        }
        CP_COMMIT();
    };

    // ---- ldmatrix per-thread address components
    // A frag (16x16): row = m0 + am*16 + (lane%16), col = ks*16 + (lane/16)*8
    const uint32_t a_ld = (uint32_t)((m0 + (lane & 15)) * SKP + (lane >> 4) * 8) * 2;
    // B frag pair (k16 x n16): row = n0 + bp*16 + (lane%8) + ((lane/16)*8),
    //                          col = ks*16 + ((lane/8)%2)*8
    const uint32_t b_ld = (uint32_t)((n0 + (lane & 7) + ((lane >> 4) << 3)) * SKP
                                     + (((lane >> 3) & 1) << 3)) * 2;

    float acc[4][4][4];
#pragma unroll
    for (int i = 0; i < 4; i++)
#pragma unroll
        for (int j = 0; j < 4; j++)
#pragma unroll
            for (int r = 0; r < 4; r++) acc[i][j][r] = 0.f;

    load_stage(0, 0);

    for (int kt = 0; kt < NKI; kt++) {
        const int cur = kt & 1;
        if (kt + 1 < NKI) {
            load_stage(cur ^ 1, kt + 1);
            CP_WAIT(1);
        } else {
            CP_WAIT(0);
        }
        __syncthreads();

        const uint32_t sb  = smem + (uint32_t)cur * STAGE_B;
        const uint32_t sAh = sb + 0 * TILE_B;
        const uint32_t sAl = sb + 1 * TILE_B;
        const uint32_t sBh = sb + 2 * TILE_B;
        const uint32_t sBl = sb + 3 * TILE_B;

#pragma unroll
        for (int ks = 0; ks < 2; ks++) {
            const uint32_t kso = (uint32_t)(ks * 16) * 2;
            uint32_t fAh[4][4], fAl[4][4];
            uint32_t fBh[4][2], fBl[4][2];
#pragma unroll
            for (int am = 0; am < 4; am++) {
                const uint32_t off = (uint32_t)(am * 16 * SKP) * 2 + kso;
                LDSM_X4(fAh[am][0], fAh[am][1], fAh[am][2], fAh[am][3], sAh + a_ld + off);
                LDSM_X4(fAl[am][0], fAl[am][1], fAl[am][2], fAl[am][3], sAl + a_ld + off);
            }
#pragma unroll
            for (int bp = 0; bp < 2; bp++) {
                const uint32_t off = (uint32_t)(bp * 16 * SKP) * 2 + kso;
                LDSM_X4(fBh[2 * bp][0], fBh[2 * bp][1], fBh[2 * bp + 1][0], fBh[2 * bp + 1][1],
                        sBh + b_ld + off);
                LDSM_X4(fBl[2 * bp][0], fBl[2 * bp][1], fBl[2 * bp + 1][0], fBl[2 * bp + 1][1],
                        sBl + b_ld + off);
            }
#pragma unroll
            for (int am = 0; am < 4; am++)
#pragma unroll
                for (int na = 0; na < 4; na++) {
                    MMA_BF16(acc[am][na], fAh[am], fBh[na]);
                    MMA_BF16(acc[am][na], fAh[am], fBl[na]);
                    MMA_BF16(acc[am][na], fAl[am], fBh[na]);
                }
        }
        __syncthreads();
    }

    // ---- epilogue: fragment rows (l/4, l/4+8), cols (l%4)*2 .. +1
    const int lr4 = lane >> 2;
    const int lc2 = (lane & 3) * 2;
#pragma unroll
    for (int am = 0; am < 4; am++) {
        const int mA = row0 + m0 + am * 16 + lr4;       // and +8
#pragma unroll
        for (int na = 0; na < 4; na++) {
            const int n = col0 + n0 + na * 8 + lc2;
#pragma unroll
            for (int half = 0; half < 2; half++) {
                const int m = mA + half * 8;
                float2 v = make_float2(acc[am][na][half * 2 + 0],
                                       acc[am][na][half * 2 + 1]);
                if (split) {
                    const int b = m >> 11, t = m & 2047;
                    const int h = n >> 6, d = n & 63;
                    *(float2*)&C[(((size_t)b * N_HEADS + h) * T_SEQ + t) * HEAD_DIM + d] = v;
                } else {
                    *(float2*)&C[(size_t)m * D_MODEL + n] = v;
                }
            }
        }
    }
}

// ---------------------------------------------------------------------------
// Flash attention, causal (unchanged from R1).
// ---------------------------------------------------------------------------
#define BQ  128
#define BKV 64
#define KPAD 68
#define SPAD 65

__global__ void __launch_bounds__(BQ) attn_kernel(const float* __restrict__ q,
                                                  const float* __restrict__ k,
                                                  const float* __restrict__ v,
                                                  float* __restrict__ o)
{
    extern __shared__ float smem[];
    float* Ksh = smem;
    float* Vsh = Ksh + BKV * KPAD;
    float* Ssh = Vsh + BKV * KPAD;

    const int b  = blockIdx.z;
    const int h  = blockIdx.y;
    const int qb = blockIdx.x;
    const int i  = threadIdx.x;
    const int qi = qb * BQ + i;

    const size_t head_off = ((size_t)b * N_HEADS + h) * T_SEQ * HEAD_DIM;
    const float* qrow  = q + head_off + (size_t)qi * HEAD_DIM;
    const float* kbase = k + head_off;
    const float* vbase = v + head_off;

    float qreg[HEAD_DIM];
#pragma unroll
    for (int d = 0; d < HEAD_DIM; d += 4) {
        float4 q4 = *(const float4*)(qrow + d);
        qreg[d + 0] = q4.x * 0.125f;
        qreg[d + 1] = q4.y * 0.125f;
        qreg[d + 2] = q4.z * 0.125f;
        qreg[d + 3] = q4.w * 0.125f;
    }

    float acc[HEAD_DIM];
#pragma unroll
    for (int d = 0; d < HEAD_DIM; d++) acc[d] = 0.f;
    float mrun = NEG_INF;
    float lrun = 0.f;

    const int nkb = 2 * qb + 2;
    const int lr  = i >> 1;
    const int lc0 = (i & 1) * 32;

    for (int kb = 0; kb < nkb; kb++) {
        const float* kr = kbase + ((size_t)kb * BKV + lr) * HEAD_DIM + lc0;
        const float* vr = vbase + ((size_t)kb * BKV + lr) * HEAD_DIM + lc0;
#pragma unroll
        for (int c = 0; c < 32; c += 4) {
            *(float4*)&Ksh[lr * KPAD + lc0 + c] = *(const float4*)(kr + c);
            *(float4*)&Vsh[lr * KPAD + lc0 + c] = *(const float4*)(vr + c);
        }
        __syncthreads();

        float tilemax = NEG_INF;
        for (int j = 0; j < BKV; j++) {
            const int kj = kb * BKV + j;
            float s = NEG_INF;
            if (kj <= qi) {
                s = 0.f;
                const float* krow = &Ksh[j * KPAD];
#pragma unroll
                for (int d = 0; d < HEAD_DIM; d += 4) {
                    float4 k4 = *(const float4*)(krow + d);
                    s += qreg[d + 0] * k4.x + qreg[d + 1] * k4.y
                       + qreg[d + 2] * k4.z + qreg[d + 3] * k4.w;
                }
            }
            Ssh[i * SPAD + j] = s;
            tilemax = fmaxf(tilemax, s);
        }

        const float mnew = fmaxf(mrun, tilemax);
        const float corr = __expf(mrun - mnew);
        lrun *= corr;
#pragma unroll
        for (int d = 0; d < HEAD_DIM; d++) acc[d] *= corr;

        for (int j = 0; j < BKV; j++) {
            const float p = __expf(Ssh[i * SPAD + j] - mnew);
            lrun += p;
            const float* vrow = &Vsh[j * KPAD];
#pragma unroll
            for (int d = 0; d < HEAD_DIM; d += 4) {
                float4 v4 = *(const float4*)(vrow + d);
                acc[d + 0] += p * v4.x;
                acc[d + 1] += p * v4.y;
                acc[d + 2] += p * v4.z;
                acc[d + 3] += p * v4.w;
            }
        }
        mrun = mnew;
        __syncthreads();
    }

    const float inv = 1.f / lrun;
    float* orow = o + ((size_t)b * T_SEQ + qi) * D_MODEL + h * HEAD_DIM;
#pragma unroll
    for (int d = 0; d < HEAD_DIM; d += 4) {
        float4 r;
        r.x = acc[d + 0] * inv;
        r.y = acc[d + 1] * inv;
        r.z = acc[d + 2] * inv;
        r.w = acc[d + 3] * inv;
        *(float4*)(orow + d) = r;
    }
}

// ---------------------------------------------------------------------------
extern "C" void kernel_launch(void* const* d_in, const int* in_sizes, int n_in,
                              void* d_out, int out_size)
{
    const float* x  = (const float*)d_in[0];
    const float* Wq = (const float*)d_in[1];
    const float* Wk = (const float*)d_in[2];
    const float* Wv = (const float*)d_in[3];
    const float* Wo = (const float*)d_in[4];

    float* out  = (float*)d_out;
    float* kout = out  + (size_t)M_ROWS * D_MODEL;
    float* vout = kout + (size_t)M_ROWS * D_MODEL;

    float *gq, *gattn;
    cudaGetSymbolAddress((void**)&gq, g_q);
    cudaGetSymbolAddress((void**)&gattn, g_attn);
    __nv_bfloat16 *xh, *xl, *wqh, *wql, *wkh, *wkl, *wvh, *wvl, *woh, *wol, *ah, *al;
    cudaGetSymbolAddress((void**)&xh,  g_xh);
    cudaGetSymbolAddress((void**)&xl,  g_xl);
    cudaGetSymbolAddress((void**)&wqh, g_wqh);
    cudaGetSymbolAddress((void**)&wql, g_wql);
    cudaGetSymbolAddress((void**)&wkh, g_wkh);
    cudaGetSymbolAddress((void**)&wkl, g_wkl);
    cudaGetSymbolAddress((void**)&wvh, g_wvh);
    cudaGetSymbolAddress((void**)&wvl, g_wvl);
    cudaGetSymbolAddress((void**)&woh, g_woh);
    cudaGetSymbolAddress((void**)&wol, g_wol);
    cudaGetSymbolAddress((void**)&ah,  g_ah);
    cudaGetSymbolAddress((void**)&al,  g_al);

    cudaFuncSetAttribute(gemm_bf16x3, cudaFuncAttributeMaxDynamicSharedMemorySize,
                         GEMM_SMEM_BYTES);

    const int nx4 = M_ROWS * D_MODEL / 4;
    const int nw4 = D_MODEL * D_MODEL / 4;
    split_bf16<<<(nx4 + 255) / 256, 256>>>(x,  xh,  xl,  nx4);
    split_bf16<<<(nw4 + 255) / 256, 256>>>(Wq, wqh, wql, nw4);
    split_bf16<<<(nw4 + 255) / 256, 256>>>(Wk, wkh, wkl, nw4);
    split_bf16<<<(nw4 + 255) / 256, 256>>>(Wv, wvh, wvl, nw4);
    split_bf16<<<(nw4 + 255) / 256, 256>>>(Wo, woh, wol, nw4);

    dim3 gg(D_MODEL / BN, M_ROWS / BM);        // (8, 64)
    gemm_bf16x3<<<gg, 256, GEMM_SMEM_BYTES>>>(xh, xl, wqh, wql, gq,   1);
    gemm_bf16x3<<<gg, 256, GEMM_SMEM_BYTES>>>(xh, xl, wkh, wkl, kout, 1);
    gemm_bf16x3<<<gg, 256, GEMM_SMEM_BYTES>>>(xh, xl, wvh, wvl, vout, 1);

    const int attn_smem = (BKV * KPAD + BKV * KPAD + BQ * SPAD) * (int)sizeof(float);
    cudaFuncSetAttribute(attn_kernel, cudaFuncAttributeMaxDynamicSharedMemorySize,
                         attn_smem);
    attn_kernel<<<dim3(T_SEQ / BQ, N_HEADS, B_SIZE), BQ, attn_smem>>>(gq, kout, vout, gattn);

    split_bf16<<<(nx4 + 255) / 256, 256>>>(gattn, ah, al, nx4);
    gemm_bf16x3<<<gg, 256, GEMM_SMEM_BYTES>>>(ah, al, woh, wol, out, 0);
}

// round 4
// speedup vs baseline: 2.7727x; 1.8377x over previous
#include <cuda_runtime.h>
#include <cuda_bf16.h>
#include <cstdint>
#include <math.h>

#define D_MODEL  1024
#define N_HEADS  16
#define HEAD_DIM 64
#define B_SIZE   4
#define T_SEQ    2048
#define M_ROWS   (B_SIZE * T_SEQ)   // 8192
#define KDIM     1024

#define NEG_INF  (__int_as_float(0xff800000))

// ---------------------------------------------------------------------------
// Scratch (device globals: no allocations allowed)
// ---------------------------------------------------------------------------
__device__ __nv_bfloat16 g_xh[(size_t)M_ROWS * D_MODEL];
__device__ __nv_bfloat16 g_xl[(size_t)M_ROWS * D_MODEL];
__device__ __nv_bfloat16 g_wqh[(size_t)D_MODEL * D_MODEL];
__device__ __nv_bfloat16 g_wql[(size_t)D_MODEL * D_MODEL];
__device__ __nv_bfloat16 g_wkh[(size_t)D_MODEL * D_MODEL];
__device__ __nv_bfloat16 g_wkl[(size_t)D_MODEL * D_MODEL];
__device__ __nv_bfloat16 g_wvh[(size_t)D_MODEL * D_MODEL];
__device__ __nv_bfloat16 g_wvl[(size_t)D_MODEL * D_MODEL];
__device__ __nv_bfloat16 g_woh[(size_t)D_MODEL * D_MODEL];
__device__ __nv_bfloat16 g_wol[(size_t)D_MODEL * D_MODEL];

__device__ __nv_bfloat16 g_qh[(size_t)M_ROWS * D_MODEL];   // (B,H,T,hd), pre-scaled
__device__ __nv_bfloat16 g_ql[(size_t)M_ROWS * D_MODEL];
__device__ __nv_bfloat16 g_kh[(size_t)M_ROWS * D_MODEL];
__device__ __nv_bfloat16 g_kl[(size_t)M_ROWS * D_MODEL];
__device__ __nv_bfloat16 g_vh[(size_t)M_ROWS * D_MODEL];
__device__ __nv_bfloat16 g_vl[(size_t)M_ROWS * D_MODEL];
__device__ __nv_bfloat16 g_ah[(size_t)M_ROWS * D_MODEL];   // attn out (B,T,D)
__device__ __nv_bfloat16 g_al[(size_t)M_ROWS * D_MODEL];

// ---------------------------------------------------------------------------
// PTX helpers (base ISA only)
// ---------------------------------------------------------------------------
__device__ __forceinline__ uint32_t smem_to_u32(const void* p) {
    uint32_t a;
    asm("{ .reg .u64 t; cvta.to.shared.u64 t, %1; cvt.u32.u64 %0, t; }"
        : "=r"(a) : "l"(p));
    return a;
}

#define CP_ASYNC16(dst, src) \
    asm volatile("cp.async.cg.shared.global [%0], [%1], 16;" :: "r"(dst), "l"(src))
#define CP_COMMIT() asm volatile("cp.async.commit_group;" ::: "memory")
#define CP_WAIT(n)  asm volatile("cp.async.wait_group %0;" :: "n"(n) : "memory")

#define LDSM_X4(r0, r1, r2, r3, addr) \
    asm volatile("ldmatrix.sync.aligned.m8n8.x4.shared.b16 {%0,%1,%2,%3}, [%4];" \
                 : "=r"(r0), "=r"(r1), "=r"(r2), "=r"(r3) : "r"(addr))
#define LDSM_X4_T(r0, r1, r2, r3, addr) \
    asm volatile("ldmatrix.sync.aligned.m8n8.x4.trans.shared.b16 {%0,%1,%2,%3}, [%4];" \
                 : "=r"(r0), "=r"(r1), "=r"(r2), "=r"(r3) : "r"(addr))

#define MMA_BF16(c, a, b) \
    asm volatile("mma.sync.aligned.m16n8k16.row.col.f32.bf16.bf16.f32 " \
                 "{%0,%1,%2,%3}, {%4,%5,%6,%7}, {%8,%9}, {%0,%1,%2,%3};" \
                 : "+f"((c)[0]), "+f"((c)[1]), "+f"((c)[2]), "+f"((c)[3]) \
                 : "r"((a)[0]), "r"((a)[1]), "r"((a)[2]), "r"((a)[3]), \
                   "r"((b)[0]), "r"((b)[1]))

// pack two fp32 -> bf16x2 reg: lower half = lo, upper half = hi
__device__ __forceinline__ uint32_t pack_bf16(float lo, float hi) {
    uint32_t r;
    asm("cvt.rn.bf16x2.f32 %0, %1, %2;" : "=r"(r) : "f"(hi), "f"(lo));
    return r;
}
// split a float2 into bf16 hi-pair and residual lo-pair (packed)
__device__ __forceinline__ void split_pack(float x, float y, uint32_t& hp, uint32_t& lp) {
    hp = pack_bf16(x, y);
    __nv_bfloat162 hb = *(__nv_bfloat162*)&hp;
    lp = pack_bf16(x - __bfloat162float(hb.x), y - __bfloat162float(hb.y));
}

// ---------------------------------------------------------------------------
// fp32 -> (bf16 hi, bf16 lo) splitter.  n4 = element count / 4.
// ---------------------------------------------------------------------------
__global__ void __launch_bounds__(256) split_bf16(const float* __restrict__ x,
                                                  __nv_bfloat16* __restrict__ hi,
                                                  __nv_bfloat16* __restrict__ lo,
                                                  int n4)
{
    int i = blockIdx.x * blockDim.x + threadIdx.x;
    if (i >= n4) return;
    float4 v = ((const float4*)x)[i];
    uint32_t h0, l0, h1, l1;
    split_pack(v.x, v.y, h0, l0);
    split_pack(v.z, v.w, h1, l1);
    uint32_t* hp = (uint32_t*)hi;
    uint32_t* lp = (uint32_t*)lo;
    hp[i * 2 + 0] = h0; hp[i * 2 + 1] = h1;
    lp[i * 2 + 0] = l0; lp[i * 2 + 1] = l1;
}

// ---------------------------------------------------------------------------
// mma.sync split-bf16 GEMM:  C(8192x1024) = A @ W^T  (3-pass hi/lo)
// Epilogue writes optional fp32 C and/or bf16 hi/lo C (scaled).
// split==1: (B,H,T,hd) layout.  split==0: row-major (M,N).
// ---------------------------------------------------------------------------
#define BM 128
#define BN 128
#define BK 32
#define NKI (KDIM / BK)          // 32
#define SKP 40                   // smem row stride in bf16
#define TILE_B (BM * SKP * 2)    // 10240 bytes per tile
#define STAGE_B (4 * TILE_B)
#define GEMM_SMEM_BYTES (2 * STAGE_B)

__global__ void __launch_bounds__(256) gemm_bf16x3(
    const __nv_bfloat16* __restrict__ Ah, const __nv_bfloat16* __restrict__ Al,
    const __nv_bfloat16* __restrict__ Bh, const __nv_bfloat16* __restrict__ Bl,
    float* __restrict__ Cf, __nv_bfloat16* __restrict__ Ch,
    __nv_bfloat16* __restrict__ Cl, float scale, int split)
{
    extern __shared__ char smem_raw[];
    const uint32_t smem = smem_to_u32(smem_raw);

    const int tid  = threadIdx.x;
    const int wid  = tid >> 5;
    const int lane = tid & 31;
    const int row0 = blockIdx.y * BM;
    const int col0 = blockIdx.x * BN;

    const int m0 = (wid & 1) * 64;
    const int n0 = (wid >> 1) * 32;

    const int lrow   = tid >> 1;
    const int lcol16 = (tid & 1) * 16;
    const size_t a_goff = (size_t)(row0 + lrow) * KDIM + lcol16;
    const size_t b_goff = (size_t)(col0 + lrow) * KDIM + lcol16;
    const uint32_t sdst0 = (uint32_t)(lrow * SKP + lcol16) * 2;

    auto load_stage = [&](int stage, int kt) {
        const uint32_t sb = smem + (uint32_t)stage * STAGE_B;
        const size_t ko = (size_t)kt * BK;
        const char* s0 = (const char*)(Ah + a_goff + ko);
        const char* s1 = (const char*)(Al + a_goff + ko);
        const char* s2 = (const char*)(Bh + b_goff + ko);
        const char* s3 = (const char*)(Bl + b_goff + ko);
#pragma unroll
        for (int c = 0; c < 2; c++) {
            CP_ASYNC16(sb + 0 * TILE_B + sdst0 + c * 16, s0 + c * 16);
            CP_ASYNC16(sb + 1 * TILE_B + sdst0 + c * 16, s1 + c * 16);
            CP_ASYNC16(sb + 2 * TILE_B + sdst0 + c * 16, s2 + c * 16);
            CP_ASYNC16(sb + 3 * TILE_B + sdst0 + c * 16, s3 + c * 16);
        }
        CP_COMMIT();
    };

    const uint32_t a_ld = (uint32_t)((m0 + (lane & 15)) * SKP + (lane >> 4) * 8) * 2;
    const uint32_t b_ld = (uint32_t)((n0 + (lane & 7) + ((lane >> 4) << 3)) * SKP
                                     + (((lane >> 3) & 1) << 3)) * 2;

    float acc[4][4][4];
#pragma unroll
    for (int i = 0; i < 4; i++)
#pragma unroll
        for (int j = 0; j < 4; j++)
#pragma unroll
            for (int r = 0; r < 4; r++) acc[i][j][r] = 0.f;

    load_stage(0, 0);

    for (int kt = 0; kt < NKI; kt++) {
        const int cur = kt & 1;
        if (kt + 1 < NKI) {
            load_stage(cur ^ 1, kt + 1);
            CP_WAIT(1);
        } else {
            CP_WAIT(0);
        }
        __syncthreads();

        const uint32_t sb  = smem + (uint32_t)cur * STAGE_B;
        const uint32_t sAh = sb + 0 * TILE_B;
        const uint32_t sAl = sb + 1 * TILE_B;
        const uint32_t sBh = sb + 2 * TILE_B;
        const uint32_t sBl = sb + 3 * TILE_B;

#pragma unroll
        for (int ks = 0; ks < 2; ks++) {
            const uint32_t kso = (uint32_t)(ks * 16) * 2;
            uint32_t fAh[4][4], fAl[4][4];
            uint32_t fBh[4][2], fBl[4][2];
#pragma unroll
            for (int am = 0; am < 4; am++) {
                const uint32_t off = (uint32_t)(am * 16 * SKP) * 2 + kso;
                LDSM_X4(fAh[am][0], fAh[am][1], fAh[am][2], fAh[am][3], sAh + a_ld + off);
                LDSM_X4(fAl[am][0], fAl[am][1], fAl[am][2], fAl[am][3], sAl + a_ld + off);
            }
#pragma unroll
            for (int bp = 0; bp < 2; bp++) {
                const uint32_t off = (uint32_t)(bp * 16 * SKP) * 2 + kso;
                LDSM_X4(fBh[2 * bp][0], fBh[2 * bp][1], fBh[2 * bp + 1][0], fBh[2 * bp + 1][1],
                        sBh + b_ld + off);
                LDSM_X4(fBl[2 * bp][0], fBl[2 * bp][1], fBl[2 * bp + 1][0], fBl[2 * bp + 1][1],
                        sBl + b_ld + off);
            }
#pragma unroll
            for (int am = 0; am < 4; am++)
#pragma unroll
                for (int na = 0; na < 4; na++) {
                    MMA_BF16(acc[am][na], fAh[am], fBh[na]);
                    MMA_BF16(acc[am][na], fAh[am], fBl[na]);
                    MMA_BF16(acc[am][na], fAl[am], fBh[na]);
                }
        }
        __syncthreads();
    }

    const int lr4 = lane >> 2;
    const int lc2 = (lane & 3) * 2;
#pragma unroll
    for (int am = 0; am < 4; am++) {
        const int mA = row0 + m0 + am * 16 + lr4;
#pragma unroll
        for (int na = 0; na < 4; na++) {
            const int n = col0 + n0 + na * 8 + lc2;
#pragma unroll
            for (int half = 0; half < 2; half++) {
                const int m = mA + half * 8;
                float vx = acc[am][na][half * 2 + 0] * scale;
                float vy = acc[am][na][half * 2 + 1] * scale;
                size_t idx;
                if (split) {
                    const int bb = m >> 11, t = m & 2047;
                    const int hh = n >> 6, d = n & 63;
                    idx = (((size_t)bb * N_HEADS + hh) * T_SEQ + t) * HEAD_DIM + d;
                } else {
                    idx = (size_t)m * D_MODEL + n;
                }
                if (Cf) *(float2*)&Cf[idx] = make_float2(vx, vy);
                if (Ch) {
                    uint32_t hp, lp;
                    split_pack(vx, vy, hp, lp);
                    *(uint32_t*)&Ch[idx] = hp;
                    *(uint32_t*)&Cl[idx] = lp;
                }
            }
        }
    }
}

// ---------------------------------------------------------------------------
// mma.sync flash attention, causal. BQ=64 (4 warps x m16), BKV=64.
// Q pre-scaled bf16 hi/lo, K/V bf16 hi/lo; 3-pass split on QK and PV.
// Output written as bf16 hi/lo in (B,T,D) for the Wo GEMM.
// ---------------------------------------------------------------------------
#define AST 72                       // smem row stride (bf16 elems)
#define ATILE_B (64 * AST * 2)       // 9216 bytes
#define ASMEM_BYTES (10 * ATILE_B)   // Qh,Ql + 2 stages x {Kh,Kl,Vh,Vl}

__global__ void __launch_bounds__(128) attn_mma(
    const __nv_bfloat16* __restrict__ qh, const __nv_bfloat16* __restrict__ ql,
    const __nv_bfloat16* __restrict__ kh, const __nv_bfloat16* __restrict__ kl,
    const __nv_bfloat16* __restrict__ vh, const __nv_bfloat16* __restrict__ vl,
    __nv_bfloat16* __restrict__ oh, __nv_bfloat16* __restrict__ ol)
{
    extern __shared__ char smem_raw[];
    const uint32_t smem = smem_to_u32(smem_raw);
    const uint32_t sQh = smem;
    const uint32_t sQl = smem + ATILE_B;
    const uint32_t sKV = smem + 2 * ATILE_B;   // stage s: +s*4*ATILE_B, {Kh,Kl,Vh,Vl}

    const int tid  = threadIdx.x;
    const int wid  = tid >> 5;
    const int lane = tid & 31;
    const int qb = blockIdx.x, h = blockIdx.y, b = blockIdx.z;
    const size_t head_elem = ((size_t)b * N_HEADS + h) * T_SEQ * HEAD_DIM;

    // ---- loaders: thread t -> row t/2, 32-elem half (t&1)
    const int lrow = tid >> 1;
    const int lc   = (tid & 1) * 32;
    const uint32_t sdst = (uint32_t)(lrow * AST + lc) * 2;

    { // Q tile (group 0)
        const char* p0 = (const char*)(qh + head_elem + (size_t)(qb * 64 + lrow) * 64 + lc);
        const char* p1 = (const char*)(ql + head_elem + (size_t)(qb * 64 + lrow) * 64 + lc);
#pragma unroll
        for (int c = 0; c < 4; c++) {
            CP_ASYNC16(sQh + sdst + c * 16, p0 + c * 16);
            CP_ASYNC16(sQl + sdst + c * 16, p1 + c * 16);
        }
        CP_COMMIT();
    }

    auto load_kv = [&](int stage, int kb) {
        const size_t roff = head_elem + (size_t)(kb * 64 + lrow) * 64 + lc;
        const uint32_t sb = sKV + (uint32_t)stage * (4 * ATILE_B);
        const char* p0 = (const char*)(kh + roff);
        const char* p1 = (const char*)(kl + roff);
        const char* p2 = (const char*)(vh + roff);
        const char* p3 = (const char*)(vl + roff);
#pragma unroll
        for (int c = 0; c < 4; c++) {
            CP_ASYNC16(sb + 0 * ATILE_B + sdst + c * 16, p0 + c * 16);
            CP_ASYNC16(sb + 1 * ATILE_B + sdst + c * 16, p1 + c * 16);
            CP_ASYNC16(sb + 2 * ATILE_B + sdst + c * 16, p2 + c * 16);
            CP_ASYNC16(sb + 3 * ATILE_B + sdst + c * 16, p3 + c * 16);
        }
        CP_COMMIT();
    };

    const int nt = qb + 1;
    load_kv(0, 0);
    if (nt > 1) { load_kv(1, 1); CP_WAIT(1); }
    else        { CP_WAIT(0); }
    __syncthreads();

    // ---- Q fragments (registers, whole CTA lifetime)
    uint32_t aQh[4][4], aQl[4][4];
    {
        const uint32_t a_ld = (uint32_t)((wid * 16 + (lane & 15)) * AST + (lane >> 4) * 8) * 2;
#pragma unroll
        for (int ks = 0; ks < 4; ks++) {
            LDSM_X4(aQh[ks][0], aQh[ks][1], aQh[ks][2], aQh[ks][3], sQh + a_ld + ks * 32);
            LDSM_X4(aQl[ks][0], aQl[ks][1], aQl[ks][2], aQl[ks][3], sQl + a_ld + ks * 32);
        }
    }

    const uint32_t b_ldK = (uint32_t)(((lane & 7) + ((lane >> 4) << 3)) * AST
                                      + ((lane >> 3) & 1) * 8) * 2;
    const uint32_t v_ld  = (uint32_t)((lane & 15) * AST + ((lane >> 4) << 3)) * 2;

    float O[8][4];
#pragma unroll
    for (int t = 0; t < 8; t++)
#pragma unroll
        for (int e = 0; e < 4; e++) O[t][e] = 0.f;
    float m1 = NEG_INF, m2 = NEG_INF, l1 = 0.f, l2 = 0.f;

    for (int kt = 0; kt < nt; kt++) {
        const uint32_t sb  = sKV + (uint32_t)(kt & 1) * (4 * ATILE_B);
        const uint32_t sKh = sb;
        const uint32_t sKl = sb + ATILE_B;
        const uint32_t sVh = sb + 2 * ATILE_B;
        const uint32_t sVl = sb + 3 * ATILE_B;

        // ---- S = Q K^T (3-pass)
        float S[8][4];
#pragma unroll
        for (int t = 0; t < 8; t++)
#pragma unroll
            for (int e = 0; e < 4; e++) S[t][e] = 0.f;

#pragma unroll
        for (int ks = 0; ks < 4; ks++) {
#pragma unroll
            for (int np = 0; np < 4; np++) {
                const uint32_t off = (uint32_t)(np * 16 * AST) * 2 + ks * 32;
                uint32_t h0, h1, h2, h3, c0, c1, c2, c3;
                LDSM_X4(h0, h1, h2, h3, sKh + b_ldK + off);
                LDSM_X4(c0, c1, c2, c3, sKl + b_ldK + off);
                uint32_t bh0[2] = {h0, h1}, bh1[2] = {h2, h3};
                uint32_t bl0[2] = {c0, c1}, bl1[2] = {c2, c3};
                MMA_BF16(S[2 * np],     aQh[ks], bh0);
                MMA_BF16(S[2 * np],     aQh[ks], bl0);
                MMA_BF16(S[2 * np],     aQl[ks], bh0);
                MMA_BF16(S[2 * np + 1], aQh[ks], bh1);
                MMA_BF16(S[2 * np + 1], aQh[ks], bl1);
                MMA_BF16(S[2 * np + 1], aQl[ks], bh1);
            }
        }

        // ---- causal mask (diagonal tile only)
        if (kt == qb) {
            const int rowb = wid * 16 + (lane >> 2);
            const int colb = (lane & 3) * 2;
#pragma unroll
            for (int t = 0; t < 8; t++) {
#pragma unroll
                for (int e = 0; e < 4; e++) {
                    const int col = t * 8 + colb + (e & 1);
                    const int row = rowb + (e >> 1) * 8;
                    if (col > row) S[t][e] = NEG_INF;
                }
            }
        }

        // ---- online softmax
        float mx1 = NEG_INF, mx2 = NEG_INF;
#pragma unroll
        for (int t = 0; t < 8; t++) {
            mx1 = fmaxf(mx1, fmaxf(S[t][0], S[t][1]));
            mx2 = fmaxf(mx2, fmaxf(S[t][2], S[t][3]));
        }
        mx1 = fmaxf(mx1, __shfl_xor_sync(0xffffffffu, mx1, 1));
        mx1 = fmaxf(mx1, __shfl_xor_sync(0xffffffffu, mx1, 2));
        mx2 = fmaxf(mx2, __shfl_xor_sync(0xffffffffu, mx2, 1));
        mx2 = fmaxf(mx2, __shfl_xor_sync(0xffffffffu, mx2, 2));

        const float mn1 = fmaxf(m1, mx1);
        const float mn2 = fmaxf(m2, mx2);
        const float c1 = __expf(m1 - mn1);
        const float c2 = __expf(m2 - mn2);
        l1 *= c1; l2 *= c2;
#pragma unroll
        for (int t = 0; t < 8; t++) {
            O[t][0] *= c1; O[t][1] *= c1;
            O[t][2] *= c2; O[t][3] *= c2;
        }
        float rs1 = 0.f, rs2 = 0.f;
#pragma unroll
        for (int t = 0; t < 8; t++) {
            S[t][0] = __expf(S[t][0] - mn1); rs1 += S[t][0];
            S[t][1] = __expf(S[t][1] - mn1); rs1 += S[t][1];
            S[t][2] = __expf(S[t][2] - mn2); rs2 += S[t][2];
            S[t][3] = __expf(S[t][3] - mn2); rs2 += S[t][3];
        }
        rs1 += __shfl_xor_sync(0xffffffffu, rs1, 1);
        rs1 += __shfl_xor_sync(0xffffffffu, rs1, 2);
        rs2 += __shfl_xor_sync(0xffffffffu, rs2, 1);
        rs2 += __shfl_xor_sync(0xffffffffu, rs2, 2);
        l1 += rs1; l2 += rs2;
        m1 = mn1; m2 = mn2;

        // ---- O += P V (3-pass, P split in registers)
#pragma unroll
        for (int ks = 0; ks < 4; ks++) {
            uint32_t aPh[4], aPl[4];
            split_pack(S[2 * ks][0],     S[2 * ks][1],     aPh[0], aPl[0]);
            split_pack(S[2 * ks][2],     S[2 * ks][3],     aPh[1], aPl[1]);
            split_pack(S[2 * ks + 1][0], S[2 * ks + 1][1], aPh[2], aPl[2]);
            split_pack(S[2 * ks + 1][2], S[2 * ks + 1][3], aPh[3], aPl[3]);
#pragma unroll
            for (int np = 0; np < 4; np++) {
                const uint32_t off = (uint32_t)(ks * 16 * AST) * 2 + np * 32;
                uint32_t h0, h1, h2, h3, c0, c1v, c2v, c3;
                LDSM_X4_T(h0, h1, h2, h3, sVh + v_ld + off);
                LDSM_X4_T(c0, c1v, c2v, c3, sVl + v_ld + off);
                uint32_t bh0[2] = {h0, h1}, bh1[2] = {h2, h3};
                uint32_t bl0[2] = {c0, c1v}, bl1[2] = {c2v, c3};
                MMA_BF16(O[2 * np],     aPh, bh0);
                MMA_BF16(O[2 * np],     aPh, bl0);
                MMA_BF16(O[2 * np],     aPl, bh0);
                MMA_BF16(O[2 * np + 1], aPh, bh1);
                MMA_BF16(O[2 * np + 1], aPh, bl1);
                MMA_BF16(O[2 * np + 1], aPl, bh1);
            }
        }

        // ---- pipeline advance
        if (kt + 1 < nt) {
            __syncthreads();
            if (kt + 2 < nt) { load_kv(kt & 1, kt + 2); CP_WAIT(1); }
            else             { CP_WAIT(0); }
            __syncthreads();
        }
    }

    // ---- epilogue: write bf16 hi/lo into (B,T,D)
    const float inv1 = 1.f / l1;
    const float inv2 = 1.f / l2;
    const int gr1 = qb * 64 + wid * 16 + (lane >> 2);
    const size_t obase = (size_t)b * T_SEQ * D_MODEL + (size_t)h * 64;
#pragma unroll
    for (int t = 0; t < 8; t++) {
        const int d = t * 8 + (lane & 3) * 2;
        uint32_t hp, lp;
        size_t i1 = obase + (size_t)gr1 * D_MODEL + d;
        split_pack(O[t][0] * inv1, O[t][1] * inv1, hp, lp);
        *(uint32_t*)&oh[i1] = hp;
        *(uint32_t*)&ol[i1] = lp;
        size_t i2 = obase + (size_t)(gr1 + 8) * D_MODEL + d;
        split_pack(O[t][2] * inv2, O[t][3] * inv2, hp, lp);
        *(uint32_t*)&oh[i2] = hp;
        *(uint32_t*)&ol[i2] = lp;
    }
}

// ---------------------------------------------------------------------------
extern "C" void kernel_launch(void* const* d_in, const int* in_sizes, int n_in,
                              void* d_out, int out_size)
{
    const float* x  = (const float*)d_in[0];
    const float* Wq = (const float*)d_in[1];
    const float* Wk = (const float*)d_in[2];
    const float* Wv = (const float*)d_in[3];
    const float* Wo = (const float*)d_in[4];

    float* out  = (float*)d_out;
    float* kout = out  + (size_t)M_ROWS * D_MODEL;
    float* vout = kout + (size_t)M_ROWS * D_MODEL;

    __nv_bfloat16 *xh, *xl, *wqh, *wql, *wkh, *wkl, *wvh, *wvl, *woh, *wol;
    __nv_bfloat16 *qhp, *qlp, *khp, *klp, *vhp, *vlp, *ahp, *alp;
    cudaGetSymbolAddress((void**)&xh,  g_xh);
    cudaGetSymbolAddress((void**)&xl,  g_xl);
    cudaGetSymbolAddress((void**)&wqh, g_wqh);
    cudaGetSymbolAddress((void**)&wql, g_wql);
    cudaGetSymbolAddress((void**)&wkh, g_wkh);
    cudaGetSymbolAddress((void**)&wkl, g_wkl);
    cudaGetSymbolAddress((void**)&wvh, g_wvh);
    cudaGetSymbolAddress((void**)&wvl, g_wvl);
    cudaGetSymbolAddress((void**)&woh, g_woh);
    cudaGetSymbolAddress((void**)&wol, g_wol);
    cudaGetSymbolAddress((void**)&qhp, g_qh);
    cudaGetSymbolAddress((void**)&qlp, g_ql);
    cudaGetSymbolAddress((void**)&khp, g_kh);
    cudaGetSymbolAddress((void**)&klp, g_kl);
    cudaGetSymbolAddress((void**)&vhp, g_vh);
    cudaGetSymbolAddress((void**)&vlp, g_vl);
    cudaGetSymbolAddress((void**)&ahp, g_ah);
    cudaGetSymbolAddress((void**)&alp, g_al);

    cudaFuncSetAttribute(gemm_bf16x3, cudaFuncAttributeMaxDynamicSharedMemorySize,
                         GEMM_SMEM_BYTES);
    cudaFuncSetAttribute(attn_mma, cudaFuncAttributeMaxDynamicSharedMemorySize,
                         ASMEM_BYTES);

    const int nx4 = M_ROWS * D_MODEL / 4;
    const int nw4 = D_MODEL * D_MODEL / 4;
    split_bf16<<<(nx4 + 255) / 256, 256>>>(x,  xh,  xl,  nx4);
    split_bf16<<<(nw4 + 255) / 256, 256>>>(Wq, wqh, wql, nw4);
    split_bf16<<<(nw4 + 255) / 256, 256>>>(Wk, wkh, wkl, nw4);
    split_bf16<<<(nw4 + 255) / 256, 256>>>(Wv, wvh, wvl, nw4);
    split_bf16<<<(nw4 + 255) / 256, 256>>>(Wo, woh, wol, nw4);

    dim3 gg(D_MODEL / BN, M_ROWS / BM);        // (8, 64)
    // Q: bf16 hi/lo only, pre-scaled by 1/sqrt(hd)
    gemm_bf16x3<<<gg, 256, GEMM_SMEM_BYTES>>>(xh, xl, wqh, wql,
                                              (float*)nullptr, qhp, qlp, 0.125f, 1);
    // K, V: fp32 outputs (required) + bf16 hi/lo for attention
    gemm_bf16x3<<<gg, 256, GEMM_SMEM_BYTES>>>(xh, xl, wkh, wkl,
                                              kout, khp, klp, 1.0f, 1);
    gemm_bf16x3<<<gg, 256, GEMM_SMEM_BYTES>>>(xh, xl, wvh, wvl,
                                              vout, vhp, vlp, 1.0f, 1);

    attn_mma<<<dim3(T_SEQ / 64, N_HEADS, B_SIZE), 128, ASMEM_BYTES>>>(
        qhp, qlp, khp, klp, vhp, vlp, ahp, alp);

    // O projection: fp32 output only
    gemm_bf16x3<<<gg, 256, GEMM_SMEM_BYTES>>>(ahp, alp, woh, wol,
                                              out, (__nv_bfloat16*)nullptr,
                                              (__nv_bfloat16*)nullptr, 1.0f, 0);
}

// round 5
// speedup vs baseline: 3.3529x; 1.2092x over previous
#include <cuda_runtime.h>
#include <cuda_fp16.h>
#include <cstdint>
#include <math.h>

#define D_MODEL  1024
#define N_HEADS  16
#define HEAD_DIM 64
#define B_SIZE   4
#define T_SEQ    2048
#define M_ROWS   (B_SIZE * T_SEQ)   // 8192
#define KDIM     1024

#define NEG_INF  (__int_as_float(0xff800000))

// ---------------------------------------------------------------------------
// Scratch (device globals: no allocations allowed)
// ---------------------------------------------------------------------------
__device__ __half g_xh[(size_t)M_ROWS * D_MODEL];
__device__ __half g_xl[(size_t)M_ROWS * D_MODEL];
__device__ __half g_wqh[(size_t)D_MODEL * D_MODEL];
__device__ __half g_wql[(size_t)D_MODEL * D_MODEL];
__device__ __half g_wkh[(size_t)D_MODEL * D_MODEL];
__device__ __half g_wkl[(size_t)D_MODEL * D_MODEL];
__device__ __half g_wvh[(size_t)D_MODEL * D_MODEL];
__device__ __half g_wvl[(size_t)D_MODEL * D_MODEL];
__device__ __half g_woh[(size_t)D_MODEL * D_MODEL];
__device__ __half g_wol[(size_t)D_MODEL * D_MODEL];

__device__ __half g_qh[(size_t)M_ROWS * D_MODEL];   // (B,H,T,hd), pre-scaled
__device__ __half g_ql[(size_t)M_ROWS * D_MODEL];
__device__ __half g_kh[(size_t)M_ROWS * D_MODEL];
__device__ __half g_kl[(size_t)M_ROWS * D_MODEL];
__device__ __half g_vh[(size_t)M_ROWS * D_MODEL];
__device__ __half g_vl[(size_t)M_ROWS * D_MODEL];
__device__ __half g_ah[(size_t)M_ROWS * D_MODEL];   // attn out (B,T,D), hi only

// ---------------------------------------------------------------------------
// PTX helpers (base ISA only)
// ---------------------------------------------------------------------------
__device__ __forceinline__ uint32_t smem_to_u32(const void* p) {
    uint32_t a;
    asm("{ .reg .u64 t; cvta.to.shared.u64 t, %1; cvt.u32.u64 %0, t; }"
        : "=r"(a) : "l"(p));
    return a;
}

#define CP_ASYNC16(dst, src) \
    asm volatile("cp.async.cg.shared.global [%0], [%1], 16;" :: "r"(dst), "l"(src))
#define CP_COMMIT() asm volatile("cp.async.commit_group;" ::: "memory")
#define CP_WAIT(n)  asm volatile("cp.async.wait_group %0;" :: "n"(n) : "memory")

#define LDSM_X4(r0, r1, r2, r3, addr) \
    asm volatile("ldmatrix.sync.aligned.m8n8.x4.shared.b16 {%0,%1,%2,%3}, [%4];" \
                 : "=r"(r0), "=r"(r1), "=r"(r2), "=r"(r3) : "r"(addr))
#define LDSM_X4_T(r0, r1, r2, r3, addr) \
    asm volatile("ldmatrix.sync.aligned.m8n8.x4.trans.shared.b16 {%0,%1,%2,%3}, [%4];" \
                 : "=r"(r0), "=r"(r1), "=r"(r2), "=r"(r3) : "r"(addr))

#define MMA_F16(c, a, b) \
    asm volatile("mma.sync.aligned.m16n8k16.row.col.f32.f16.f16.f32 " \
                 "{%0,%1,%2,%3}, {%4,%5,%6,%7}, {%8,%9}, {%0,%1,%2,%3};" \
                 : "+f"((c)[0]), "+f"((c)[1]), "+f"((c)[2]), "+f"((c)[3]) \
                 : "r"((a)[0]), "r"((a)[1]), "r"((a)[2]), "r"((a)[3]), \
                   "r"((b)[0]), "r"((b)[1]))

// pack two fp32 -> f16x2 reg: low half = x, high half = y
__device__ __forceinline__ uint32_t pack_f16(float x, float y) {
    uint32_t r;
    asm("cvt.rn.f16x2.f32 %0, %1, %2;" : "=r"(r) : "f"(y), "f"(x));
    return r;
}
__device__ __forceinline__ void split_pack_f16(float x, float y,
                                               uint32_t& hp, uint32_t& lp) {
    hp = pack_f16(x, y);
    __half2 hb = *(__half2*)&hp;
    lp = pack_f16(x - __half2float(hb.x), y - __half2float(hb.y));
}

// ---------------------------------------------------------------------------
// fp32 -> (f16 hi, f16 lo) splitter.  n4 = element count / 4.
// ---------------------------------------------------------------------------
__global__ void __launch_bounds__(256) split_f16(const float* __restrict__ x,
                                                 __half* __restrict__ hi,
                                                 __half* __restrict__ lo,
                                                 int n4)
{
    int i = blockIdx.x * blockDim.x + threadIdx.x;
    if (i >= n4) return;
    float4 v = ((const float4*)x)[i];
    uint32_t h0, l0, h1, l1;
    split_pack_f16(v.x, v.y, h0, l0);
    split_pack_f16(v.z, v.w, h1, l1);
    ((uint32_t*)hi)[i * 2 + 0] = h0; ((uint32_t*)hi)[i * 2 + 1] = h1;
    ((uint32_t*)lo)[i * 2 + 0] = l0; ((uint32_t*)lo)[i * 2 + 1] = l1;
}

// ---------------------------------------------------------------------------
// mma.sync split-f16 GEMM:  C(8192x1024) = A @ W^T
// npass==3: Ah*Bh + Ah*Bl + Al*Bh.   npass==2: Ah*Bh + Ah*Bl  (= Ah*B).
// blockIdx.z selects a problem slice from GemmArgs (merged QKV launch).
// 3-stage cp.async pipeline, one barrier per K-iter.
// ---------------------------------------------------------------------------
#define BM 128
#define BN 128
#define BK 32
#define NKI (KDIM / BK)          // 32
#define SKP 40                   // smem row stride in f16
#define TILE_B (BM * SKP * 2)    // 10240 bytes per tile
#define STAGE_B (4 * TILE_B)
#define GEMM_SMEM_BYTES (3 * STAGE_B)

struct GemmArgs {
    const __half* Ah;
    const __half* Al;
    const __half* Bh[3];
    const __half* Bl[3];
    float*  Cf[3];
    __half* Ch[3];
    __half* Cl[3];
    float   scale[3];
    int     np3[3];     // 1 -> 3-pass
    int     split;      // 1 -> (B,H,T,hd) output layout
};

__global__ void __launch_bounds__(256) gemm_f16(const GemmArgs args)
{
    extern __shared__ char smem_raw[];
    const uint32_t smem = smem_to_u32(smem_raw);

    const int z = blockIdx.z;
    const __half* Ah = args.Ah;
    const __half* Al = args.Al;
    const __half* Bh = args.Bh[z];
    const __half* Bl = args.Bl[z];
    const int np3 = args.np3[z];

    const int tid  = threadIdx.x;
    const int wid  = tid >> 5;
    const int lane = tid & 31;
    const int row0 = blockIdx.y * BM;
    const int col0 = blockIdx.x * BN;

    const int m0 = (wid & 1) * 64;
    const int n0 = (wid >> 1) * 32;

    const int lrow   = tid >> 1;
    const int lcol16 = (tid & 1) * 16;
    const size_t a_goff = (size_t)(row0 + lrow) * KDIM + lcol16;
    const size_t b_goff = (size_t)(col0 + lrow) * KDIM + lcol16;
    const uint32_t sdst0 = (uint32_t)(lrow * SKP + lcol16) * 2;

    auto load_stage = [&](int stage, int kt) {
        const uint32_t sb = smem + (uint32_t)stage * STAGE_B;
        const size_t ko = (size_t)kt * BK;
        const char* s0 = (const char*)(Ah + a_goff + ko);
        const char* s2 = (const char*)(Bh + b_goff + ko);
        const char* s3 = (const char*)(Bl + b_goff + ko);
#pragma unroll
        for (int c = 0; c < 2; c++) {
            CP_ASYNC16(sb + 0 * TILE_B + sdst0 + c * 16, s0 + c * 16);
            CP_ASYNC16(sb + 2 * TILE_B + sdst0 + c * 16, s2 + c * 16);
            CP_ASYNC16(sb + 3 * TILE_B + sdst0 + c * 16, s3 + c * 16);
        }
        if (np3) {
            const char* s1 = (const char*)(Al + a_goff + ko);
#pragma unroll
            for (int c = 0; c < 2; c++)
                CP_ASYNC16(sb + 1 * TILE_B + sdst0 + c * 16, s1 + c * 16);
        }
        CP_COMMIT();
    };

    const uint32_t a_ld = (uint32_t)((m0 + (lane & 15)) * SKP + (lane >> 4) * 8) * 2;
    const uint32_t b_ld = (uint32_t)((n0 + (lane & 7) + ((lane >> 4) << 3)) * SKP
                                     + (((lane >> 3) & 1) << 3)) * 2;

    float acc[4][4][4];
#pragma unroll
    for (int i = 0; i < 4; i++)
#pragma unroll
        for (int j = 0; j < 4; j++)
#pragma unroll
            for (int r = 0; r < 4; r++) acc[i][j][r] = 0.f;

    load_stage(0, 0);
    load_stage(1, 1);

    for (int kt = 0; kt < NKI; kt++) {
        if (kt + 1 < NKI) { CP_WAIT(1); } else { CP_WAIT(0); }
        __syncthreads();
        if (kt + 2 < NKI) load_stage((kt + 2) % 3, kt + 2);

        const uint32_t sb  = smem + (uint32_t)(kt % 3) * STAGE_B;
        const uint32_t sAh = sb + 0 * TILE_B;
        const uint32_t sAl = sb + 1 * TILE_B;
        const uint32_t sBh = sb + 2 * TILE_B;
        const uint32_t sBl = sb + 3 * TILE_B;

#pragma unroll
        for (int ks = 0; ks < 2; ks++) {
            const uint32_t kso = (uint32_t)(ks * 16) * 2;
            uint32_t fAh[4][4], fAl[4][4];
            uint32_t fBh[4][2], fBl[4][2];
#pragma unroll
            for (int am = 0; am < 4; am++) {
                const uint32_t off = (uint32_t)(am * 16 * SKP) * 2 + kso;
                LDSM_X4(fAh[am][0], fAh[am][1], fAh[am][2], fAh[am][3], sAh + a_ld + off);
            }
            if (np3) {
#pragma unroll
                for (int am = 0; am < 4; am++) {
                    const uint32_t off = (uint32_t)(am * 16 * SKP) * 2 + kso;
                    LDSM_X4(fAl[am][0], fAl[am][1], fAl[am][2], fAl[am][3], sAl + a_ld + off);
                }
            }
#pragma unroll
            for (int bp = 0; bp < 2; bp++) {
                const uint32_t off = (uint32_t)(bp * 16 * SKP) * 2 + kso;
                LDSM_X4(fBh[2 * bp][0], fBh[2 * bp][1], fBh[2 * bp + 1][0], fBh[2 * bp + 1][1],
                        sBh + b_ld + off);
                LDSM_X4(fBl[2 * bp][0], fBl[2 * bp][1], fBl[2 * bp + 1][0], fBl[2 * bp + 1][1],
                        sBl + b_ld + off);
            }
#pragma unroll
            for (int am = 0; am < 4; am++)
#pragma unroll
                for (int na = 0; na < 4; na++) {
                    MMA_F16(acc[am][na], fAh[am], fBh[na]);
                    MMA_F16(acc[am][na], fAh[am], fBl[na]);
                }
            if (np3) {
#pragma unroll
                for (int am = 0; am < 4; am++)
#pragma unroll
                    for (int na = 0; na < 4; na++)
                        MMA_F16(acc[am][na], fAl[am], fBh[na]);
            }
        }
    }

    float* Cf = args.Cf[z];
    __half* Ch = args.Ch[z];
    __half* Cl = args.Cl[z];
    const float scale = args.scale[z];
    const int split = args.split;

    const int lr4 = lane >> 2;
    const int lc2 = (lane & 3) * 2;
#pragma unroll
    for (int am = 0; am < 4; am++) {
        const int mA = row0 + m0 + am * 16 + lr4;
#pragma unroll
        for (int na = 0; na < 4; na++) {
            const int n = col0 + n0 + na * 8 + lc2;
#pragma unroll
            for (int half_ = 0; half_ < 2; half_++) {
                const int m = mA + half_ * 8;
                float vx = acc[am][na][half_ * 2 + 0] * scale;
                float vy = acc[am][na][half_ * 2 + 1] * scale;
                size_t idx;
                if (split) {
                    const int bb = m >> 11, t = m & 2047;
                    const int hh = n >> 6, d = n & 63;
                    idx = (((size_t)bb * N_HEADS + hh) * T_SEQ + t) * HEAD_DIM + d;
                } else {
                    idx = (size_t)m * D_MODEL + n;
                }
                if (Cf) *(float2*)&Cf[idx] = make_float2(vx, vy);
                if (Ch) {
                    uint32_t hp, lp;
                    split_pack_f16(vx, vy, hp, lp);
                    *(uint32_t*)&Ch[idx] = hp;
                    *(uint32_t*)&Cl[idx] = lp;
                }
            }
        }
    }
}

// ---------------------------------------------------------------------------
// mma.sync flash attention, causal. BQ=64 (4 warps x m16), BKV=64.
// QK^T: 3-pass split-f16.  P·V: 2-pass (P hi-only x V hi/lo).
// Output: f16 hi only, (B,T,D).
// ---------------------------------------------------------------------------
#define AST 72                       // smem row stride (f16 elems)
#define ATILE_B (64 * AST * 2)       // 9216 bytes
#define ASMEM_BYTES (10 * ATILE_B)   // Qh,Ql + 2 stages x {Kh,Kl,Vh,Vl}

__global__ void __launch_bounds__(128) attn_mma(
    const __half* __restrict__ qh, const __half* __restrict__ ql,
    const __half* __restrict__ kh, const __half* __restrict__ kl,
    const __half* __restrict__ vh, const __half* __restrict__ vl,
    __half* __restrict__ oh)
{
    extern __shared__ char smem_raw[];
    const uint32_t smem = smem_to_u32(smem_raw);
    const uint32_t sQh = smem;
    const uint32_t sQl = smem + ATILE_B;
    const uint32_t sKV = smem + 2 * ATILE_B;

    const int tid  = threadIdx.x;
    const int wid  = tid >> 5;
    const int lane = tid & 31;
    const int qb = gridDim.x - 1 - blockIdx.x;   // heaviest tiles first
    const int h = blockIdx.y, b = blockIdx.z;
    const size_t head_elem = ((size_t)b * N_HEADS + h) * T_SEQ * HEAD_DIM;

    const int lrow = tid >> 1;
    const int lc   = (tid & 1) * 32;
    const uint32_t sdst = (uint32_t)(lrow * AST + lc) * 2;

    { // Q tile
        const char* p0 = (const char*)(qh + head_elem + (size_t)(qb * 64 + lrow) * 64 + lc);
        const char* p1 = (const char*)(ql + head_elem + (size_t)(qb * 64 + lrow) * 64 + lc);
#pragma unroll
        for (int c = 0; c < 4; c++) {
            CP_ASYNC16(sQh + sdst + c * 16, p0 + c * 16);
            CP_ASYNC16(sQl + sdst + c * 16, p1 + c * 16);
        }
        CP_COMMIT();
    }

    auto load_kv = [&](int stage, int kb) {
        const size_t roff = head_elem + (size_t)(kb * 64 + lrow) * 64 + lc;
        const uint32_t sb = sKV + (uint32_t)stage * (4 * ATILE_B);
        const char* p0 = (const char*)(kh + roff);
        const char* p1 = (const char*)(kl + roff);
        const char* p2 = (const char*)(vh + roff);
        const char* p3 = (const char*)(vl + roff);
#pragma unroll
        for (int c = 0; c < 4; c++) {
            CP_ASYNC16(sb + 0 * ATILE_B + sdst + c * 16, p0 + c * 16);
            CP_ASYNC16(sb + 1 * ATILE_B + sdst + c * 16, p1 + c * 16);
            CP_ASYNC16(sb + 2 * ATILE_B + sdst + c * 16, p2 + c * 16);
            CP_ASYNC16(sb + 3 * ATILE_B + sdst + c * 16, p3 + c * 16);
        }
        CP_COMMIT();
    };

    const int nt = qb + 1;
    load_kv(0, 0);
    if (nt > 1) { load_kv(1, 1); CP_WAIT(1); }
    else        { CP_WAIT(0); }
    __syncthreads();

    uint32_t aQh[4][4], aQl[4][4];
    {
        const uint32_t a_ld = (uint32_t)((wid * 16 + (lane & 15)) * AST + (lane >> 4) * 8) * 2;
#pragma unroll
        for (int ks = 0; ks < 4; ks++) {
            LDSM_X4(aQh[ks][0], aQh[ks][1], aQh[ks][2], aQh[ks][3], sQh + a_ld + ks * 32);
            LDSM_X4(aQl[ks][0], aQl[ks][1], aQl[ks][2], aQl[ks][3], sQl + a_ld + ks * 32);
        }
    }

    const uint32_t b_ldK = (uint32_t)(((lane & 7) + ((lane >> 4) << 3)) * AST
                                      + ((lane >> 3) & 1) * 8) * 2;
    const uint32_t v_ld  = (uint32_t)((lane & 15) * AST + ((lane >> 4) << 3)) * 2;

    float O[8][4];
#pragma unroll
    for (int t = 0; t < 8; t++)
#pragma unroll
        for (int e = 0; e < 4; e++) O[t][e] = 0.f;
    float m1 = NEG_INF, m2 = NEG_INF, l1 = 0.f, l2 = 0.f;

    for (int kt = 0; kt < nt; kt++) {
        const uint32_t sb  = sKV + (uint32_t)(kt & 1) * (4 * ATILE_B);
        const uint32_t sKh = sb;
        const uint32_t sKl = sb + ATILE_B;
        const uint32_t sVh = sb + 2 * ATILE_B;
        const uint32_t sVl = sb + 3 * ATILE_B;

        float S[8][4];
#pragma unroll
        for (int t = 0; t < 8; t++)
#pragma unroll
            for (int e = 0; e < 4; e++) S[t][e] = 0.f;

#pragma unroll
        for (int ks = 0; ks < 4; ks++) {
#pragma unroll
            for (int np = 0; np < 4; np++) {
                const uint32_t off = (uint32_t)(np * 16 * AST) * 2 + ks * 32;
                uint32_t h0, h1, h2, h3, c0, c1, c2, c3;
                LDSM_X4(h0, h1, h2, h3, sKh + b_ldK + off);
                LDSM_X4(c0, c1, c2, c3, sKl + b_ldK + off);
                uint32_t bh0[2] = {h0, h1}, bh1[2] = {h2, h3};
                uint32_t bl0[2] = {c0, c1}, bl1[2] = {c2, c3};
                MMA_F16(S[2 * np],     aQh[ks], bh0);
                MMA_F16(S[2 * np],     aQh[ks], bl0);
                MMA_F16(S[2 * np],     aQl[ks], bh0);
                MMA_F16(S[2 * np + 1], aQh[ks], bh1);
                MMA_F16(S[2 * np + 1], aQh[ks], bl1);
                MMA_F16(S[2 * np + 1], aQl[ks], bh1);
            }
        }

        if (kt == qb) {
            const int rowb = wid * 16 + (lane >> 2);
            const int colb = (lane & 3) * 2;
#pragma unroll
            for (int t = 0; t < 8; t++) {
#pragma unroll
                for (int e = 0; e < 4; e++) {
                    const int col = t * 8 + colb + (e & 1);
                    const int row = rowb + (e >> 1) * 8;
                    if (col > row) S[t][e] = NEG_INF;
                }
            }
        }

        float mx1 = NEG_INF, mx2 = NEG_INF;
#pragma unroll
        for (int t = 0; t < 8; t++) {
            mx1 = fmaxf(mx1, fmaxf(S[t][0], S[t][1]));
            mx2 = fmaxf(mx2, fmaxf(S[t][2], S[t][3]));
        }
        mx1 = fmaxf(mx1, __shfl_xor_sync(0xffffffffu, mx1, 1));
        mx1 = fmaxf(mx1, __shfl_xor_sync(0xffffffffu, mx1, 2));
        mx2 = fmaxf(mx2, __shfl_xor_sync(0xffffffffu, mx2, 1));
        mx2 = fmaxf(mx2, __shfl_xor_sync(0xffffffffu, mx2, 2));

        const float mn1 = fmaxf(m1, mx1);
        const float mn2 = fmaxf(m2, mx2);
        const float c1 = __expf(m1 - mn1);
        const float c2 = __expf(m2 - mn2);
        l1 *= c1; l2 *= c2;
#pragma unroll
        for (int t = 0; t < 8; t++) {
            O[t][0] *= c1; O[t][1] *= c1;
            O[t][2] *= c2; O[t][3] *= c2;
        }
        float rs1 = 0.f, rs2 = 0.f;
#pragma unroll
        for (int t = 0; t < 8; t++) {
            S[t][0] = __expf(S[t][0] - mn1); rs1 += S[t][0];
            S[t][1] = __expf(S[t][1] - mn1); rs1 += S[t][1];
            S[t][2] = __expf(S[t][2] - mn2); rs2 += S[t][2];
            S[t][3] = __expf(S[t][3] - mn2); rs2 += S[t][3];
        }
        rs1 += __shfl_xor_sync(0xffffffffu, rs1, 1);
        rs1 += __shfl_xor_sync(0xffffffffu, rs1, 2);
        rs2 += __shfl_xor_sync(0xffffffffu, rs2, 1);
        rs2 += __shfl_xor_sync(0xffffffffu, rs2, 2);
        l1 += rs1; l2 += rs2;
        m1 = mn1; m2 = mn2;

        // ---- O += P V  (2-pass: P hi-only, V hi + lo)
#pragma unroll
        for (int ks = 0; ks < 4; ks++) {
            uint32_t aPh[4];
            aPh[0] = pack_f16(S[2 * ks][0],     S[2 * ks][1]);
            aPh[1] = pack_f16(S[2 * ks][2],     S[2 * ks][3]);
            aPh[2] = pack_f16(S[2 * ks + 1][0], S[2 * ks + 1][1]);
            aPh[3] = pack_f16(S[2 * ks + 1][2], S[2 * ks + 1][3]);
#pragma unroll
            for (int np = 0; np < 4; np++) {
                const uint32_t off = (uint32_t)(ks * 16 * AST) * 2 + np * 32;
                uint32_t h0, h1, h2, h3, c0, c1v, c2v, c3;
                LDSM_X4_T(h0, h1, h2, h3, sVh + v_ld + off);
                LDSM_X4_T(c0, c1v, c2v, c3, sVl + v_ld + off);
                uint32_t bh0[2] = {h0, h1}, bh1[2] = {h2, h3};
                uint32_t bl0[2] = {c0, c1v}, bl1[2] = {c2v, c3};
                MMA_F16(O[2 * np],     aPh, bh0);
                MMA_F16(O[2 * np],     aPh, bl0);
                MMA_F16(O[2 * np + 1], aPh, bh1);
                MMA_F16(O[2 * np + 1], aPh, bl1);
            }
        }

        if (kt + 1 < nt) {
            __syncthreads();
            if (kt + 2 < nt) { load_kv(kt & 1, kt + 2); CP_WAIT(1); }
            else             { CP_WAIT(0); }
            __syncthreads();
        }
    }

    const float inv1 = 1.f / l1;
    const float inv2 = 1.f / l2;
    const int gr1 = qb * 64 + wid * 16 + (lane >> 2);
    const size_t obase = (size_t)b * T_SEQ * D_MODEL + (size_t)h * 64;
#pragma unroll
    for (int t = 0; t < 8; t++) {
        const int d = t * 8 + (lane & 3) * 2;
        size_t i1 = obase + (size_t)gr1 * D_MODEL + d;
        *(uint32_t*)&oh[i1] = pack_f16(O[t][0] * inv1, O[t][1] * inv1);
        size_t i2 = obase + (size_t)(gr1 + 8) * D_MODEL + d;
        *(uint32_t*)&oh[i2] = pack_f16(O[t][2] * inv2, O[t][3] * inv2);
    }
}

// ---------------------------------------------------------------------------
extern "C" void kernel_launch(void* const* d_in, const int* in_sizes, int n_in,
                              void* d_out, int out_size)
{
    const float* x  = (const float*)d_in[0];
    const float* Wq = (const float*)d_in[1];
    const float* Wk = (const float*)d_in[2];
    const float* Wv = (const float*)d_in[3];
    const float* Wo = (const float*)d_in[4];

    float* out  = (float*)d_out;
    float* kout = out  + (size_t)M_ROWS * D_MODEL;
    float* vout = kout + (size_t)M_ROWS * D_MODEL;

    __half *xh, *xl, *wqh, *wql, *wkh, *wkl, *wvh, *wvl, *woh, *wol;
    __half *qhp, *qlp, *khp, *klp, *vhp, *vlp, *ahp;
    cudaGetSymbolAddress((void**)&xh,  g_xh);
    cudaGetSymbolAddress((void**)&xl,  g_xl);
    cudaGetSymbolAddress((void**)&wqh, g_wqh);
    cudaGetSymbolAddress((void**)&wql, g_wql);
    cudaGetSymbolAddress((void**)&wkh, g_wkh);
    cudaGetSymbolAddress((void**)&wkl, g_wkl);
    cudaGetSymbolAddress((void**)&wvh, g_wvh);
    cudaGetSymbolAddress((void**)&wvl, g_wvl);
    cudaGetSymbolAddress((void**)&woh, g_woh);
    cudaGetSymbolAddress((void**)&wol, g_wol);
    cudaGetSymbolAddress((void**)&qhp, g_qh);
    cudaGetSymbolAddress((void**)&qlp, g_ql);
    cudaGetSymbolAddress((void**)&khp, g_kh);
    cudaGetSymbolAddress((void**)&klp, g_kl);
    cudaGetSymbolAddress((void**)&vhp, g_vh);
    cudaGetSymbolAddress((void**)&vlp, g_vl);
    cudaGetSymbolAddress((void**)&ahp, g_ah);

    cudaFuncSetAttribute(gemm_f16, cudaFuncAttributeMaxDynamicSharedMemorySize,
                         GEMM_SMEM_BYTES);
    cudaFuncSetAttribute(attn_mma, cudaFuncAttributeMaxDynamicSharedMemorySize,
                         ASMEM_BYTES);

    const int nx4 = M_ROWS * D_MODEL / 4;
    const int nw4 = D_MODEL * D_MODEL / 4;
    split_f16<<<(nx4 + 255) / 256, 256>>>(x,  xh,  xl,  nx4);
    split_f16<<<(nw4 + 255) / 256, 256>>>(Wq, wqh, wql, nw4);
    split_f16<<<(nw4 + 255) / 256, 256>>>(Wk, wkh, wkl, nw4);
    split_f16<<<(nw4 + 255) / 256, 256>>>(Wv, wvh, wvl, nw4);
    split_f16<<<(nw4 + 255) / 256, 256>>>(Wo, woh, wol, nw4);

    // ---- merged QKV GEMM (grid.z: 0=Q 3-pass, 1=K 3-pass, 2=V 2-pass)
    GemmArgs qkv;
    qkv.Ah = xh; qkv.Al = xl;
    qkv.Bh[0] = wqh; qkv.Bl[0] = wql;
    qkv.Bh[1] = wkh; qkv.Bl[1] = wkl;
    qkv.Bh[2] = wvh; qkv.Bl[2] = wvl;
    qkv.Cf[0] = nullptr; qkv.Cf[1] = kout; qkv.Cf[2] = vout;
    qkv.Ch[0] = qhp; qkv.Cl[0] = qlp;
    qkv.Ch[1] = khp; qkv.Cl[1] = klp;
    qkv.Ch[2] = vhp; qkv.Cl[2] = vlp;
    qkv.scale[0] = 0.125f; qkv.scale[1] = 1.f; qkv.scale[2] = 1.f;
    qkv.np3[0] = 1; qkv.np3[1] = 1; qkv.np3[2] = 0;
    qkv.split = 1;
    gemm_f16<<<dim3(D_MODEL / BN, M_ROWS / BM, 3), 256, GEMM_SMEM_BYTES>>>(qkv);

    attn_mma<<<dim3(T_SEQ / 64, N_HEADS, B_SIZE), 128, ASMEM_BYTES>>>(
        qhp, qlp, khp, klp, vhp, vlp, ahp);

    // ---- O projection: 2-pass (ah x Wo hi/lo), fp32 output
    GemmArgs og;
    og.Ah = ahp; og.Al = ahp;
    og.Bh[0] = woh; og.Bl[0] = wol;
    og.Cf[0] = out; og.Ch[0] = nullptr; og.Cl[0] = nullptr;
    og.scale[0] = 1.f; og.np3[0] = 0; og.split = 0;
    og.Bh[1] = og.Bh[2] = nullptr; og.Bl[1] = og.Bl[2] = nullptr;
    og.Cf[1] = og.Cf[2] = nullptr; og.Ch[1] = og.Ch[2] = nullptr;
    og.Cl[1] = og.Cl[2] = nullptr; og.scale[1] = og.scale[2] = 1.f;
    og.np3[1] = og.np3[2] = 0;
    gemm_f16<<<dim3(D_MODEL / BN, M_ROWS / BM, 1), 256, GEMM_SMEM_BYTES>>>(og);
}

// round 6
// speedup vs baseline: 4.2574x; 1.2698x over previous
#include <cuda_runtime.h>
#include <cuda_fp16.h>
#include <cstdint>
#include <math.h>

#define D_MODEL  1024
#define N_HEADS  16
#define HEAD_DIM 64
#define B_SIZE   4
#define T_SEQ    2048
#define M_ROWS   (B_SIZE * T_SEQ)   // 8192
#define KDIM     1024

#define NEG_INF  (__int_as_float(0xff800000))

// ---------------------------------------------------------------------------
// Scratch (device globals: no allocations allowed)
// ---------------------------------------------------------------------------
__device__ __half g_xh[(size_t)M_ROWS * D_MODEL];
__device__ __half g_wqh[(size_t)D_MODEL * D_MODEL];
__device__ __half g_wql[(size_t)D_MODEL * D_MODEL];
__device__ __half g_wkh[(size_t)D_MODEL * D_MODEL];
__device__ __half g_wkl[(size_t)D_MODEL * D_MODEL];
__device__ __half g_wvh[(size_t)D_MODEL * D_MODEL];
__device__ __half g_wvl[(size_t)D_MODEL * D_MODEL];
__device__ __half g_woh[(size_t)D_MODEL * D_MODEL];
__device__ __half g_wol[(size_t)D_MODEL * D_MODEL];

__device__ __half g_qh[(size_t)M_ROWS * D_MODEL];   // (B,H,T,hd), pre-scaled
__device__ __half g_kh[(size_t)M_ROWS * D_MODEL];
__device__ __half g_kl[(size_t)M_ROWS * D_MODEL];
__device__ __half g_vh[(size_t)M_ROWS * D_MODEL];
__device__ __half g_vl[(size_t)M_ROWS * D_MODEL];
__device__ __half g_ah[(size_t)M_ROWS * D_MODEL];   // attn out (B,T,D), hi only

// ---------------------------------------------------------------------------
// PTX helpers (base ISA only)
// ---------------------------------------------------------------------------
__device__ __forceinline__ uint32_t smem_to_u32(const void* p) {
    uint32_t a;
    asm("{ .reg .u64 t; cvta.to.shared.u64 t, %1; cvt.u32.u64 %0, t; }"
        : "=r"(a) : "l"(p));
    return a;
}

#define CP_ASYNC16(dst, src) \
    asm volatile("cp.async.cg.shared.global [%0], [%1], 16;" :: "r"(dst), "l"(src))
#define CP_COMMIT() asm volatile("cp.async.commit_group;" ::: "memory")
#define CP_WAIT(n)  asm volatile("cp.async.wait_group %0;" :: "n"(n) : "memory")

#define LDSM_X4(r0, r1, r2, r3, addr) \
    asm volatile("ldmatrix.sync.aligned.m8n8.x4.shared.b16 {%0,%1,%2,%3}, [%4];" \
                 : "=r"(r0), "=r"(r1), "=r"(r2), "=r"(r3) : "r"(addr))
#define LDSM_X4_T(r0, r1, r2, r3, addr) \
    asm volatile("ldmatrix.sync.aligned.m8n8.x4.trans.shared.b16 {%0,%1,%2,%3}, [%4];" \
                 : "=r"(r0), "=r"(r1), "=r"(r2), "=r"(r3) : "r"(addr))

#define MMA_F16(c, a, b) \
    asm volatile("mma.sync.aligned.m16n8k16.row.col.f32.f16.f16.f32 " \
                 "{%0,%1,%2,%3}, {%4,%5,%6,%7}, {%8,%9}, {%0,%1,%2,%3};" \
                 : "+f"((c)[0]), "+f"((c)[1]), "+f"((c)[2]), "+f"((c)[3]) \
                 : "r"((a)[0]), "r"((a)[1]), "r"((a)[2]), "r"((a)[3]), \
                   "r"((b)[0]), "r"((b)[1]))

// pack two fp32 -> f16x2 reg: low half = x, high half = y
__device__ __forceinline__ uint32_t pack_f16(float x, float y) {
    uint32_t r;
    asm("cvt.rn.f16x2.f32 %0, %1, %2;" : "=r"(r) : "f"(y), "f"(x));
    return r;
}
__device__ __forceinline__ void split_pack_f16(float x, float y,
                                               uint32_t& hp, uint32_t& lp) {
    hp = pack_f16(x, y);
    __half2 hb = *(__half2*)&hp;
    lp = pack_f16(x - __half2float(hb.x), y - __half2float(hb.y));
}

// ---------------------------------------------------------------------------
// fp32 -> f16 converter (hi only) for x.
// ---------------------------------------------------------------------------
__global__ void __launch_bounds__(256) cvt_f16(const float* __restrict__ x,
                                               __half* __restrict__ hi, int n4)
{
    int i = blockIdx.x * blockDim.x + threadIdx.x;
    if (i >= n4) return;
    float4 v = ((const float4*)x)[i];
    ((uint32_t*)hi)[i * 2 + 0] = pack_f16(v.x, v.y);
    ((uint32_t*)hi)[i * 2 + 1] = pack_f16(v.z, v.w);
}

// ---------------------------------------------------------------------------
// fp32 -> (f16 hi, f16 lo) splitter for the 4 weight matrices (grid.z picks).
// ---------------------------------------------------------------------------
struct SplitArgs {
    const float* src[4];
    __half* hi[4];
    __half* lo[4];
};
__global__ void __launch_bounds__(256) split_f16w(const SplitArgs a, int n4)
{
    const int z = blockIdx.z;
    const float* x = a.src[z];
    __half* hi = a.hi[z];
    __half* lo = a.lo[z];
    int i = blockIdx.x * blockDim.x + threadIdx.x;
    if (i >= n4) return;
    float4 v = ((const float4*)x)[i];
    uint32_t h0, l0, h1, l1;
    split_pack_f16(v.x, v.y, h0, l0);
    split_pack_f16(v.z, v.w, h1, l1);
    ((uint32_t*)hi)[i * 2 + 0] = h0; ((uint32_t*)hi)[i * 2 + 1] = h1;
    ((uint32_t*)lo)[i * 2 + 0] = l0; ((uint32_t*)lo)[i * 2 + 1] = l1;
}

// ---------------------------------------------------------------------------
// mma.sync 2-pass f16 GEMM:  C(8192x1024) = A @ W^T  =  Ah*Bh + Ah*Bl
// blockIdx.z selects a problem slice (merged QKV launch).
// 3-stage cp.async pipeline, one barrier per K-iter.
// ---------------------------------------------------------------------------
#define BM 128
#define BN 128
#define BK 32
#define NKI (KDIM / BK)          // 32
#define SKP 40                   // smem row stride in f16
#define TILE_B (BM * SKP * 2)    // 10240 bytes per tile
#define STAGE_B (3 * TILE_B)     // Ah, Bh, Bl
#define GEMM_SMEM_BYTES (3 * STAGE_B)

struct GemmArgs {
    const __half* Ah;
    const __half* Bh[3];
    const __half* Bl[3];
    float*  Cf[3];
    __half* Ch[3];
    __half* Cl[3];      // null -> hi-only f16 store
    float   scale[3];
    int     split;      // 1 -> (B,H,T,hd) output layout
};

__global__ void __launch_bounds__(256) gemm_f16(const GemmArgs args)
{
    extern __shared__ char smem_raw[];
    const uint32_t smem = smem_to_u32(smem_raw);

    const int z = blockIdx.z;
    const __half* Ah = args.Ah;
    const __half* Bh = args.Bh[z];
    const __half* Bl = args.Bl[z];

    const int tid  = threadIdx.x;
    const int wid  = tid >> 5;
    const int lane = tid & 31;
    const int row0 = blockIdx.y * BM;
    const int col0 = blockIdx.x * BN;

    const int m0 = (wid & 1) * 64;
    const int n0 = (wid >> 1) * 32;

    const int lrow   = tid >> 1;
    const int lcol16 = (tid & 1) * 16;
    const size_t a_goff = (size_t)(row0 + lrow) * KDIM + lcol16;
    const size_t b_goff = (size_t)(col0 + lrow) * KDIM + lcol16;
    const uint32_t sdst0 = (uint32_t)(lrow * SKP + lcol16) * 2;

    auto load_stage = [&](int stage, int kt) {
        const uint32_t sb = smem + (uint32_t)stage * STAGE_B;
        const size_t ko = (size_t)kt * BK;
        const char* s0 = (const char*)(Ah + a_goff + ko);
        const char* s2 = (const char*)(Bh + b_goff + ko);
        const char* s3 = (const char*)(Bl + b_goff + ko);
#pragma unroll
        for (int c = 0; c < 2; c++) {
            CP_ASYNC16(sb + 0 * TILE_B + sdst0 + c * 16, s0 + c * 16);
            CP_ASYNC16(sb + 1 * TILE_B + sdst0 + c * 16, s2 + c * 16);
            CP_ASYNC16(sb + 2 * TILE_B + sdst0 + c * 16, s3 + c * 16);
        }
        CP_COMMIT();
    };

    const uint32_t a_ld = (uint32_t)((m0 + (lane & 15)) * SKP + (lane >> 4) * 8) * 2;
    const uint32_t b_ld = (uint32_t)((n0 + (lane & 7) + ((lane >> 4) << 3)) * SKP
                                     + (((lane >> 3) & 1) << 3)) * 2;

    float acc[4][4][4];
#pragma unroll
    for (int i = 0; i < 4; i++)
#pragma unroll
        for (int j = 0; j < 4; j++)
#pragma unroll
            for (int r = 0; r < 4; r++) acc[i][j][r] = 0.f;

    load_stage(0, 0);
    load_stage(1, 1);

    for (int kt = 0; kt < NKI; kt++) {
        if (kt + 1 < NKI) { CP_WAIT(1); } else { CP_WAIT(0); }
        __syncthreads();
        if (kt + 2 < NKI) load_stage((kt + 2) % 3, kt + 2);

        const uint32_t sb  = smem + (uint32_t)(kt % 3) * STAGE_B;
        const uint32_t sAh = sb + 0 * TILE_B;
        const uint32_t sBh = sb + 1 * TILE_B;
        const uint32_t sBl = sb + 2 * TILE_B;

#pragma unroll
        for (int ks = 0; ks < 2; ks++) {
            const uint32_t kso = (uint32_t)(ks * 16) * 2;
            uint32_t fAh[4][4];
            uint32_t fBh[4][2], fBl[4][2];
#pragma unroll
            for (int am = 0; am < 4; am++) {
                const uint32_t off = (uint32_t)(am * 16 * SKP) * 2 + kso;
                LDSM_X4(fAh[am][0], fAh[am][1], fAh[am][2], fAh[am][3], sAh + a_ld + off);
            }
#pragma unroll
            for (int bp = 0; bp < 2; bp++) {
                const uint32_t off = (uint32_t)(bp * 16 * SKP) * 2 + kso;
                LDSM_X4(fBh[2 * bp][0], fBh[2 * bp][1], fBh[2 * bp + 1][0], fBh[2 * bp + 1][1],
                        sBh + b_ld + off);
                LDSM_X4(fBl[2 * bp][0], fBl[2 * bp][1], fBl[2 * bp + 1][0], fBl[2 * bp + 1][1],
                        sBl + b_ld + off);
            }
#pragma unroll
            for (int am = 0; am < 4; am++)
#pragma unroll
                for (int na = 0; na < 4; na++) {
                    MMA_F16(acc[am][na], fAh[am], fBh[na]);
                    MMA_F16(acc[am][na], fAh[am], fBl[na]);
                }
        }
    }

    float* Cf = args.Cf[z];
    __half* Ch = args.Ch[z];
    __half* Cl = args.Cl[z];
    const float scale = args.scale[z];
    const int split = args.split;

    const int lr4 = lane >> 2;
    const int lc2 = (lane & 3) * 2;
#pragma unroll
    for (int am = 0; am < 4; am++) {
        const int mA = row0 + m0 + am * 16 + lr4;
#pragma unroll
        for (int na = 0; na < 4; na++) {
            const int n = col0 + n0 + na * 8 + lc2;
#pragma unroll
            for (int half_ = 0; half_ < 2; half_++) {
                const int m = mA + half_ * 8;
                float vx = acc[am][na][half_ * 2 + 0] * scale;
                float vy = acc[am][na][half_ * 2 + 1] * scale;
                size_t idx;
                if (split) {
                    const int bb = m >> 11, t = m & 2047;
                    const int hh = n >> 6, d = n & 63;
                    idx = (((size_t)bb * N_HEADS + hh) * T_SEQ + t) * HEAD_DIM + d;
                } else {
                    idx = (size_t)m * D_MODEL + n;
                }
                if (Cf) *(float2*)&Cf[idx] = make_float2(vx, vy);
                if (Ch) {
                    if (Cl) {
                        uint32_t hp, lp;
                        split_pack_f16(vx, vy, hp, lp);
                        *(uint32_t*)&Ch[idx] = hp;
                        *(uint32_t*)&Cl[idx] = lp;
                    } else {
                        *(uint32_t*)&Ch[idx] = pack_f16(vx, vy);
                    }
                }
            }
        }
    }
}

// ---------------------------------------------------------------------------
// mma.sync flash attention, causal. BQ=64 (4 warps x m16), BKV=64.
// QK^T: 2-pass (Q hi x K hi/lo).  P·V: 2-pass (P hi x V hi/lo).
// Output: f16 hi only, (B,T,D).
// ---------------------------------------------------------------------------
#define AST 72                       // smem row stride (f16 elems)
#define ATILE_B (64 * AST * 2)       // 9216 bytes
#define ASMEM_BYTES (9 * ATILE_B)    // Qh + 2 stages x {Kh,Kl,Vh,Vl}

__global__ void __launch_bounds__(128) attn_mma(
    const __half* __restrict__ qh,
    const __half* __restrict__ kh, const __half* __restrict__ kl,
    const __half* __restrict__ vh, const __half* __restrict__ vl,
    __half* __restrict__ oh)
{
    extern __shared__ char smem_raw[];
    const uint32_t smem = smem_to_u32(smem_raw);
    const uint32_t sQh = smem;
    const uint32_t sKV = smem + ATILE_B;

    const int tid  = threadIdx.x;
    const int wid  = tid >> 5;
    const int lane = tid & 31;
    const int qb = gridDim.x - 1 - blockIdx.x;   // heaviest tiles first
    const int h = blockIdx.y, b = blockIdx.z;
    const size_t head_elem = ((size_t)b * N_HEADS + h) * T_SEQ * HEAD_DIM;

    const int lrow = tid >> 1;
    const int lc   = (tid & 1) * 32;
    const uint32_t sdst = (uint32_t)(lrow * AST + lc) * 2;

    { // Q tile (hi only)
        const char* p0 = (const char*)(qh + head_elem + (size_t)(qb * 64 + lrow) * 64 + lc);
#pragma unroll
        for (int c = 0; c < 4; c++)
            CP_ASYNC16(sQh + sdst + c * 16, p0 + c * 16);
        CP_COMMIT();
    }

    auto load_kv = [&](int stage, int kb) {
        const size_t roff = head_elem + (size_t)(kb * 64 + lrow) * 64 + lc;
        const uint32_t sb = sKV + (uint32_t)stage * (4 * ATILE_B);
        const char* p0 = (const char*)(kh + roff);
        const char* p1 = (const char*)(kl + roff);
        const char* p2 = (const char*)(vh + roff);
        const char* p3 = (const char*)(vl + roff);
#pragma unroll
        for (int c = 0; c < 4; c++) {
            CP_ASYNC16(sb + 0 * ATILE_B + sdst + c * 16, p0 + c * 16);
            CP_ASYNC16(sb + 1 * ATILE_B + sdst + c * 16, p1 + c * 16);
            CP_ASYNC16(sb + 2 * ATILE_B + sdst + c * 16, p2 + c * 16);
            CP_ASYNC16(sb + 3 * ATILE_B + sdst + c * 16, p3 + c * 16);
        }
        CP_COMMIT();
    };

    const int nt = qb + 1;
    load_kv(0, 0);
    if (nt > 1) { load_kv(1, 1); CP_WAIT(1); }
    else        { CP_WAIT(0); }
    __syncthreads();

    uint32_t aQh[4][4];
    {
        const uint32_t a_ld = (uint32_t)((wid * 16 + (lane & 15)) * AST + (lane >> 4) * 8) * 2;
#pragma unroll
        for (int ks = 0; ks < 4; ks++)
            LDSM_X4(aQh[ks][0], aQh[ks][1], aQh[ks][2], aQh[ks][3], sQh + a_ld + ks * 32);
    }

    const uint32_t b_ldK = (uint32_t)(((lane & 7) + ((lane >> 4) << 3)) * AST
                                      + ((lane >> 3) & 1) * 8) * 2;
    const uint32_t v_ld  = (uint32_t)((lane & 15) * AST + ((lane >> 4) << 3)) * 2;

    float O[8][4];
#pragma unroll
    for (int t = 0; t < 8; t++)
#pragma unroll
        for (int e = 0; e < 4; e++) O[t][e] = 0.f;
    float m1 = NEG_INF, m2 = NEG_INF, l1 = 0.f, l2 = 0.f;

    for (int kt = 0; kt < nt; kt++) {
        const uint32_t sb  = sKV + (uint32_t)(kt & 1) * (4 * ATILE_B);
        const uint32_t sKh = sb;
        const uint32_t sKl = sb + ATILE_B;
        const uint32_t sVh = sb + 2 * ATILE_B;
        const uint32_t sVl = sb + 3 * ATILE_B;

        float S[8][4];
#pragma unroll
        for (int t = 0; t < 8; t++)
#pragma unroll
            for (int e = 0; e < 4; e++) S[t][e] = 0.f;

#pragma unroll
        for (int ks = 0; ks < 4; ks++) {
#pragma unroll
            for (int np = 0; np < 4; np++) {
                const uint32_t off = (uint32_t)(np * 16 * AST) * 2 + ks * 32;
                uint32_t h0, h1, h2, h3, c0, c1, c2, c3;
                LDSM_X4(h0, h1, h2, h3, sKh + b_ldK + off);
                LDSM_X4(c0, c1, c2, c3, sKl + b_ldK + off);
                uint32_t bh0[2] = {h0, h1}, bh1[2] = {h2, h3};
                uint32_t bl0[2] = {c0, c1}, bl1[2] = {c2, c3};
                MMA_F16(S[2 * np],     aQh[ks], bh0);
                MMA_F16(S[2 * np],     aQh[ks], bl0);
                MMA_F16(S[2 * np + 1], aQh[ks], bh1);
                MMA_F16(S[2 * np + 1], aQh[ks], bl1);
            }
        }

        if (kt == qb) {
            const int rowb = wid * 16 + (lane >> 2);
            const int colb = (lane & 3) * 2;
#pragma unroll
            for (int t = 0; t < 8; t++) {
#pragma unroll
                for (int e = 0; e < 4; e++) {
                    const int col = t * 8 + colb + (e & 1);
                    const int row = rowb + (e >> 1) * 8;
                    if (col > row) S[t][e] = NEG_INF;
                }
            }
        }

        float mx1 = NEG_INF, mx2 = NEG_INF;
#pragma unroll
        for (int t = 0; t < 8; t++) {
            mx1 = fmaxf(mx1, fmaxf(S[t][0], S[t][1]));
            mx2 = fmaxf(mx2, fmaxf(S[t][2], S[t][3]));
        }
        mx1 = fmaxf(mx1, __shfl_xor_sync(0xffffffffu, mx1, 1));
        mx1 = fmaxf(mx1, __shfl_xor_sync(0xffffffffu, mx1, 2));
        mx2 = fmaxf(mx2, __shfl_xor_sync(0xffffffffu, mx2, 1));
        mx2 = fmaxf(mx2, __shfl_xor_sync(0xffffffffu, mx2, 2));

        const float mn1 = fmaxf(m1, mx1);
        const float mn2 = fmaxf(m2, mx2);
        const float c1 = __expf(m1 - mn1);
        const float c2 = __expf(m2 - mn2);
        l1 *= c1; l2 *= c2;
#pragma unroll
        for (int t = 0; t < 8; t++) {
            O[t][0] *= c1; O[t][1] *= c1;
            O[t][2] *= c2; O[t][3] *= c2;
        }
        float rs1 = 0.f, rs2 = 0.f;
#pragma unroll
        for (int t = 0; t < 8; t++) {
            S[t][0] = __expf(S[t][0] - mn1); rs1 += S[t][0];
            S[t][1] = __expf(S[t][1] - mn1); rs1 += S[t][1];
            S[t][2] = __expf(S[t][2] - mn2); rs2 += S[t][2];
            S[t][3] = __expf(S[t][3] - mn2); rs2 += S[t][3];
        }
        rs1 += __shfl_xor_sync(0xffffffffu, rs1, 1);
        rs1 += __shfl_xor_sync(0xffffffffu, rs1, 2);
        rs2 += __shfl_xor_sync(0xffffffffu, rs2, 1);
        rs2 += __shfl_xor_sync(0xffffffffu, rs2, 2);
        l1 += rs1; l2 += rs2;
        m1 = mn1; m2 = mn2;

        // ---- O += P V  (2-pass: P hi-only, V hi + lo)
#pragma unroll
        for (int ks = 0; ks < 4; ks++) {
            uint32_t aPh[4];
            aPh[0] = pack_f16(S[2 * ks][0],     S[2 * ks][1]);
            aPh[1] = pack_f16(S[2 * ks][2],     S[2 * ks][3]);
            aPh[2] = pack_f16(S[2 * ks + 1][0], S[2 * ks + 1][1]);
            aPh[3] = pack_f16(S[2 * ks + 1][2], S[2 * ks + 1][3]);
#pragma unroll
            for (int np = 0; np < 4; np++) {
                const uint32_t off = (uint32_t)(ks * 16 * AST) * 2 + np * 32;
                uint32_t h0, h1, h2, h3, c0, c1v, c2v, c3;
                LDSM_X4_T(h0, h1, h2, h3, sVh + v_ld + off);
                LDSM_X4_T(c0, c1v, c2v, c3, sVl + v_ld + off);
                uint32_t bh0[2] = {h0, h1}, bh1[2] = {h2, h3};
                uint32_t bl0[2] = {c0, c1v}, bl1[2] = {c2v, c3};
                MMA_F16(O[2 * np],     aPh, bh0);
                MMA_F16(O[2 * np],     aPh, bl0);
                MMA_F16(O[2 * np + 1], aPh, bh1);
                MMA_F16(O[2 * np + 1], aPh, bl1);
            }
        }

        if (kt + 1 < nt) {
            __syncthreads();
            if (kt + 2 < nt) { load_kv(kt & 1, kt + 2); CP_WAIT(1); }
            else             { CP_WAIT(0); }
            __syncthreads();
        }
    }

    const float inv1 = 1.f / l1;
    const float inv2 = 1.f / l2;
    const int gr1 = qb * 64 + wid * 16 + (lane >> 2);
    const size_t obase = (size_t)b * T_SEQ * D_MODEL + (size_t)h * 64;
#pragma unroll
    for (int t = 0; t < 8; t++) {
        const int d = t * 8 + (lane & 3) * 2;
        size_t i1 = obase + (size_t)gr1 * D_MODEL + d;
        *(uint32_t*)&oh[i1] = pack_f16(O[t][0] * inv1, O[t][1] * inv1);
        size_t i2 = obase + (size_t)(gr1 + 8) * D_MODEL + d;
        *(uint32_t*)&oh[i2] = pack_f16(O[t][2] * inv2, O[t][3] * inv2);
    }
}

// ---------------------------------------------------------------------------
extern "C" void kernel_launch(void* const* d_in, const int* in_sizes, int n_in,
                              void* d_out, int out_size)
{
    const float* x  = (const float*)d_in[0];
    const float* Wq = (const float*)d_in[1];
    const float* Wk = (const float*)d_in[2];
    const float* Wv = (const float*)d_in[3];
    const float* Wo = (const float*)d_in[4];

    float* out  = (float*)d_out;
    float* kout = out  + (size_t)M_ROWS * D_MODEL;
    float* vout = kout + (size_t)M_ROWS * D_MODEL;

    __half *xh, *wqh, *wql, *wkh, *wkl, *wvh, *wvl, *woh, *wol;
    __half *qhp, *khp, *klp, *vhp, *vlp, *ahp;
    cudaGetSymbolAddress((void**)&xh,  g_xh);
    cudaGetSymbolAddress((void**)&wqh, g_wqh);
    cudaGetSymbolAddress((void**)&wql, g_wql);
    cudaGetSymbolAddress((void**)&wkh, g_wkh);
    cudaGetSymbolAddress((void**)&wkl, g_wkl);
    cudaGetSymbolAddress((void**)&wvh, g_wvh);
    cudaGetSymbolAddress((void**)&wvl, g_wvl);
    cudaGetSymbolAddress((void**)&woh, g_woh);
    cudaGetSymbolAddress((void**)&wol, g_wol);
    cudaGetSymbolAddress((void**)&qhp, g_qh);
    cudaGetSymbolAddress((void**)&khp, g_kh);
    cudaGetSymbolAddress((void**)&klp, g_kl);
    cudaGetSymbolAddress((void**)&vhp, g_vh);
    cudaGetSymbolAddress((void**)&vlp, g_vl);
    cudaGetSymbolAddress((void**)&ahp, g_ah);

    cudaFuncSetAttribute(gemm_f16, cudaFuncAttributeMaxDynamicSharedMemorySize,
                         GEMM_SMEM_BYTES);
    cudaFuncSetAttribute(attn_mma, cudaFuncAttributeMaxDynamicSharedMemorySize,
                         ASMEM_BYTES);

    const int nx4 = M_ROWS * D_MODEL / 4;
    const int nw4 = D_MODEL * D_MODEL / 4;
    cvt_f16<<<(nx4 + 255) / 256, 256>>>(x, xh, nx4);

    SplitArgs sa;
    sa.src[0] = Wq; sa.hi[0] = wqh; sa.lo[0] = wql;
    sa.src[1] = Wk; sa.hi[1] = wkh; sa.lo[1] = wkl;
    sa.src[2] = Wv; sa.hi[2] = wvh; sa.lo[2] = wvl;
    sa.src[3] = Wo; sa.hi[3] = woh; sa.lo[3] = wol;
    split_f16w<<<dim3((nw4 + 255) / 256, 1, 4), 256>>>(sa, nw4);

    // ---- merged QKV GEMM (grid.z: 0=Q, 1=K, 2=V; all 2-pass)
    GemmArgs qkv;
    qkv.Ah = xh;
    qkv.Bh[0] = wqh; qkv.Bl[0] = wql;
    qkv.Bh[1] = wkh; qkv.Bl[1] = wkl;
    qkv.Bh[2] = wvh; qkv.Bl[2] = wvl;
    qkv.Cf[0] = nullptr; qkv.Cf[1] = kout; qkv.Cf[2] = vout;
    qkv.Ch[0] = qhp; qkv.Cl[0] = nullptr;          // Q: hi only, pre-scaled
    qkv.Ch[1] = khp; qkv.Cl[1] = klp;
    qkv.Ch[2] = vhp; qkv.Cl[2] = vlp;
    qkv.scale[0] = 0.125f; qkv.scale[1] = 1.f; qkv.scale[2] = 1.f;
    qkv.split = 1;
    gemm_f16<<<dim3(D_MODEL / BN, M_ROWS / BM, 3), 256, GEMM_SMEM_BYTES>>>(qkv);

    attn_mma<<<dim3(T_SEQ / 64, N_HEADS, B_SIZE), 128, ASMEM_BYTES>>>(
        qhp, khp, klp, vhp, vlp, ahp);

    // ---- O projection: 2-pass (ah x Wo hi/lo), fp32 output
    GemmArgs og;
    og.Ah = ahp;
    og.Bh[0] = woh; og.Bl[0] = wol;
    og.Cf[0] = out; og.Ch[0] = nullptr; og.Cl[0] = nullptr;
    og.scale[0] = 1.f; og.split = 0;
    og.Bh[1] = og.Bh[2] = nullptr; og.Bl[1] = og.Bl[2] = nullptr;
    og.Cf[1] = og.Cf[2] = nullptr; og.Ch[1] = og.Ch[2] = nullptr;
    og.Cl[1] = og.Cl[2] = nullptr; og.scale[1] = og.scale[2] = 1.f;
    gemm_f16<<<dim3(D_MODEL / BN, M_ROWS / BM, 1), 256, GEMM_SMEM_BYTES>>>(og);
}

// round 9
// speedup vs baseline: 4.8620x; 1.1420x over previous
#include <cuda_runtime.h>
#include <cuda_fp16.h>
#include <cstdint>
#include <math.h>

#define D_MODEL  1024
#define N_HEADS  16
#define HEAD_DIM 64
#define B_SIZE   4
#define T_SEQ    2048
#define M_ROWS   (B_SIZE * T_SEQ)   // 8192
#define KDIM     1024

#define NEG_INF  (__int_as_float(0xff800000))

// ---------------------------------------------------------------------------
// Scratch (device globals: no allocations allowed)
// ---------------------------------------------------------------------------
__device__ __half g_xh[(size_t)M_ROWS * D_MODEL];
__device__ __half g_wqh[(size_t)D_MODEL * D_MODEL];
__device__ __half g_wql[(size_t)D_MODEL * D_MODEL];
__device__ __half g_wkh[(size_t)D_MODEL * D_MODEL];
__device__ __half g_wkl[(size_t)D_MODEL * D_MODEL];
__device__ __half g_wvh[(size_t)D_MODEL * D_MODEL];
__device__ __half g_wvl[(size_t)D_MODEL * D_MODEL];
__device__ __half g_woh[(size_t)D_MODEL * D_MODEL];
__device__ __half g_wol[(size_t)D_MODEL * D_MODEL];

__device__ __half g_qh[(size_t)M_ROWS * D_MODEL];   // (B,H,T,hd), pre-scaled
__device__ __half g_kh[(size_t)M_ROWS * D_MODEL];
__device__ __half g_kl[(size_t)M_ROWS * D_MODEL];
__device__ __half g_vh[(size_t)M_ROWS * D_MODEL];
__device__ __half g_vl[(size_t)M_ROWS * D_MODEL];
__device__ __half g_ah[(size_t)M_ROWS * D_MODEL];   // attn out (B,T,D), hi only

// ---------------------------------------------------------------------------
// PTX helpers (base ISA only)
// ---------------------------------------------------------------------------
__device__ __forceinline__ uint32_t smem_to_u32(const void* p) {
    uint32_t a;
    asm("{ .reg .u64 t; cvta.to.shared.u64 t, %1; cvt.u32.u64 %0, t; }"
        : "=r"(a) : "l"(p));
    return a;
}

#define CP_ASYNC16(dst, src) \
    asm volatile("cp.async.cg.shared.global [%0], [%1], 16;" :: "r"(dst), "l"(src))
#define CP_COMMIT() asm volatile("cp.async.commit_group;" ::: "memory")
#define CP_WAIT(n)  asm volatile("cp.async.wait_group %0;" :: "n"(n) : "memory")

#define LDSM_X4(r0, r1, r2, r3, addr) \
    asm volatile("ldmatrix.sync.aligned.m8n8.x4.shared.b16 {%0,%1,%2,%3}, [%4];" \
                 : "=r"(r0), "=r"(r1), "=r"(r2), "=r"(r3) : "r"(addr))
#define LDSM_X4_T(r0, r1, r2, r3, addr) \
    asm volatile("ldmatrix.sync.aligned.m8n8.x4.trans.shared.b16 {%0,%1,%2,%3}, [%4];" \
                 : "=r"(r0), "=r"(r1), "=r"(r2), "=r"(r3) : "r"(addr))

#define MMA_F16(c, a, b) \
    asm volatile("mma.sync.aligned.m16n8k16.row.col.f32.f16.f16.f32 " \
                 "{%0,%1,%2,%3}, {%4,%5,%6,%7}, {%8,%9}, {%0,%1,%2,%3};" \
                 : "+f"((c)[0]), "+f"((c)[1]), "+f"((c)[2]), "+f"((c)[3]) \
                 : "r"((a)[0]), "r"((a)[1]), "r"((a)[2]), "r"((a)[3]), \
                   "r"((b)[0]), "r"((b)[1]))

// pack two fp32 -> f16x2 reg: low half = x, high half = y
__device__ __forceinline__ uint32_t pack_f16(float x, float y) {
    uint32_t r;
    asm("cvt.rn.f16x2.f32 %0, %1, %2;" : "=r"(r) : "f"(y), "f"(x));
    return r;
}
__device__ __forceinline__ void split_pack_f16(float x, float y,
                                               uint32_t& hp, uint32_t& lp) {
    hp = pack_f16(x, y);
    __half2 hb = *(__half2*)&hp;
    lp = pack_f16(x - __half2float(hb.x), y - __half2float(hb.y));
}

// ---------------------------------------------------------------------------
// fp32 -> f16 converter (hi only) for x.
// ---------------------------------------------------------------------------
__global__ void __launch_bounds__(256) cvt_f16(const float* __restrict__ x,
                                               __half* __restrict__ hi, int n4)
{
    int i = blockIdx.x * blockDim.x + threadIdx.x;
    if (i >= n4) return;
    float4 v = ((const float4*)x)[i];
    ((uint32_t*)hi)[i * 2 + 0] = pack_f16(v.x, v.y);
    ((uint32_t*)hi)[i * 2 + 1] = pack_f16(v.z, v.w);
}

// ---------------------------------------------------------------------------
// fp32 -> (f16 hi, f16 lo) splitter for the 4 weight matrices (grid.z picks).
// ---------------------------------------------------------------------------
struct SplitArgs {
    const float* src[4];
    __half* hi[4];
    __half* lo[4];
};
__global__ void __launch_bounds__(256) split_f16w(const SplitArgs a, int n4)
{
    const int z = blockIdx.z;
    const float* x = a.src[z];
    __half* hi = a.hi[z];
    __half* lo = a.lo[z];
    int i = blockIdx.x * blockDim.x + threadIdx.x;
    if (i >= n4) return;
    float4 v = ((const float4*)x)[i];
    uint32_t h0, l0, h1, l1;
    split_pack_f16(v.x, v.y, h0, l0);
    split_pack_f16(v.z, v.w, h1, l1);
    ((uint32_t*)hi)[i * 2 + 0] = h0; ((uint32_t*)hi)[i * 2 + 1] = h1;
    ((uint32_t*)lo)[i * 2 + 0] = l0; ((uint32_t*)lo)[i * 2 + 1] = l1;
}

// ---------------------------------------------------------------------------
// mma.sync 2-pass f16 GEMM:  C(8192x1024) = A @ W^T  =  Ah*Bh + Ah*Bl
// ---------------------------------------------------------------------------
#define BM 128
#define BN 128
#define BK 32
#define NKI (KDIM / BK)          // 32
#define SKP 40                   // smem row stride in f16
#define TILE_B (BM * SKP * 2)    // 10240 bytes per tile
#define STAGE_B (3 * TILE_B)     // Ah, Bh, Bl
#define GEMM_SMEM_BYTES (3 * STAGE_B)

struct GemmArgs {
    const __half* Ah;
    const __half* Bh[3];
    const __half* Bl[3];
    float*  Cf[3];
    __half* Ch[3];
    __half* Cl[3];      // null -> hi-only f16 store
    float   scale[3];
    int     split;      // 1 -> (B,H,T,hd) output layout
};

__global__ void __launch_bounds__(256) gemm_f16(const GemmArgs args)
{
    extern __shared__ char smem_raw[];
    const uint32_t smem = smem_to_u32(smem_raw);

    const int z = blockIdx.z;
    const __half* Ah = args.Ah;
    const __half* Bh = args.Bh[z];
    const __half* Bl = args.Bl[z];

    const int tid  = threadIdx.x;
    const int wid  = tid >> 5;
    const int lane = tid & 31;
    const int row0 = blockIdx.y * BM;
    const int col0 = blockIdx.x * BN;

    const int m0 = (wid & 1) * 64;
    const int n0 = (wid >> 1) * 32;

    const int lrow   = tid >> 1;
    const int lcol16 = (tid & 1) * 16;
    const size_t a_goff = (size_t)(row0 + lrow) * KDIM + lcol16;
    const size_t b_goff = (size_t)(col0 + lrow) * KDIM + lcol16;
    const uint32_t sdst0 = (uint32_t)(lrow * SKP + lcol16) * 2;

    auto load_stage = [&](int stage, int kt) {
        const uint32_t sb = smem + (uint32_t)stage * STAGE_B;
        const size_t ko = (size_t)kt * BK;
        const char* s0 = (const char*)(Ah + a_goff + ko);
        const char* s2 = (const char*)(Bh + b_goff + ko);
        const char* s3 = (const char*)(Bl + b_goff + ko);
#pragma unroll
        for (int c = 0; c < 2; c++) {
            CP_ASYNC16(sb + 0 * TILE_B + sdst0 + c * 16, s0 + c * 16);
            CP_ASYNC16(sb + 1 * TILE_B + sdst0 + c * 16, s2 + c * 16);
            CP_ASYNC16(sb + 2 * TILE_B + sdst0 + c * 16, s3 + c * 16);
        }
        CP_COMMIT();
    };

    const uint32_t a_ld = (uint32_t)((m0 + (lane & 15)) * SKP + (lane >> 4) * 8) * 2;
    const uint32_t b_ld = (uint32_t)((n0 + (lane & 7) + ((lane >> 4) << 3)) * SKP
                                     + (((lane >> 3) & 1) << 3)) * 2;

    float acc[4][4][4];
#pragma unroll
    for (int i = 0; i < 4; i++)
#pragma unroll
        for (int j = 0; j < 4; j++)
#pragma unroll
            for (int r = 0; r < 4; r++) acc[i][j][r] = 0.f;

    load_stage(0, 0);
    load_stage(1, 1);

    for (int kt = 0; kt < NKI; kt++) {
        if (kt + 1 < NKI) { CP_WAIT(1); } else { CP_WAIT(0); }
        __syncthreads();
        if (kt + 2 < NKI) load_stage((kt + 2) % 3, kt + 2);

        const uint32_t sb  = smem + (uint32_t)(kt % 3) * STAGE_B;
        const uint32_t sAh = sb + 0 * TILE_B;
        const uint32_t sBh = sb + 1 * TILE_B;
        const uint32_t sBl = sb + 2 * TILE_B;

#pragma unroll
        for (int ks = 0; ks < 2; ks++) {
            const uint32_t kso = (uint32_t)(ks * 16) * 2;
            uint32_t fAh[4][4];
            uint32_t fBh[4][2], fBl[4][2];
#pragma unroll
            for (int am = 0; am < 4; am++) {
                const uint32_t off = (uint32_t)(am * 16 * SKP) * 2 + kso;
                LDSM_X4(fAh[am][0], fAh[am][1], fAh[am][2], fAh[am][3], sAh + a_ld + off);
            }
#pragma unroll
            for (int bp = 0; bp < 2; bp++) {
                const uint32_t off = (uint32_t)(bp * 16 * SKP) * 2 + kso;
                LDSM_X4(fBh[2 * bp][0], fBh[2 * bp][1], fBh[2 * bp + 1][0], fBh[2 * bp + 1][1],
                        sBh + b_ld + off);
                LDSM_X4(fBl[2 * bp][0], fBl[2 * bp][1], fBl[2 * bp + 1][0], fBl[2 * bp + 1][1],
                        sBl + b_ld + off);
            }
            // hi pass: 16 independent accumulators, then lo pass
#pragma unroll
            for (int am = 0; am < 4; am++)
#pragma unroll
                for (int na = 0; na < 4; na++)
                    MMA_F16(acc[am][na], fAh[am], fBh[na]);
#pragma unroll
            for (int am = 0; am < 4; am++)
#pragma unroll
                for (int na = 0; na < 4; na++)
                    MMA_F16(acc[am][na], fAh[am], fBl[na]);
        }
    }

    float* Cf = args.Cf[z];
    __half* Ch = args.Ch[z];
    __half* Cl = args.Cl[z];
    const float scale = args.scale[z];
    const int split = args.split;

    const int lr4 = lane >> 2;
    const int lc2 = (lane & 3) * 2;
#pragma unroll
    for (int am = 0; am < 4; am++) {
        const int mA = row0 + m0 + am * 16 + lr4;
#pragma unroll
        for (int na = 0; na < 4; na++) {
            const int n = col0 + n0 + na * 8 + lc2;
#pragma unroll
            for (int half_ = 0; half_ < 2; half_++) {
                const int m = mA + half_ * 8;
                float vx = acc[am][na][half_ * 2 + 0] * scale;
                float vy = acc[am][na][half_ * 2 + 1] * scale;
                size_t idx;
                if (split) {
                    const int bb = m >> 11, t = m & 2047;
                    const int hh = n >> 6, d = n & 63;
                    idx = (((size_t)bb * N_HEADS + hh) * T_SEQ + t) * HEAD_DIM + d;
                } else {
                    idx = (size_t)m * D_MODEL + n;
                }
                if (Cf) *(float2*)&Cf[idx] = make_float2(vx, vy);
                if (Ch) {
                    if (Cl) {
                        uint32_t hp, lp;
                        split_pack_f16(vx, vy, hp, lp);
                        *(uint32_t*)&Ch[idx] = hp;
                        *(uint32_t*)&Cl[idx] = lp;
                    } else {
                        *(uint32_t*)&Ch[idx] = pack_f16(vx, vy);
                    }
                }
            }
        }
    }
}

// ---------------------------------------------------------------------------
// mma.sync flash attention, causal. BQ=128 (8 warps x m16), BKV=64, 256 thr.
// Fragment semantics identical to the 858us passing version; the K/V loader
// now issues 2x16B per array per thread (full 64x64 tile coverage).
// ---------------------------------------------------------------------------
#define AST 72                        // smem row stride (f16 elems)
#define ATILE_B (64 * AST * 2)        // 9216 bytes (64-row K/V tile)
#define QTILE_B (128 * AST * 2)       // 18432 bytes (128-row Q tile)
#define ASMEM_BYTES (QTILE_B + 8 * ATILE_B)   // Q + 2 stages x {Kh,Kl,Vh,Vl}

__global__ void __launch_bounds__(256, 2) attn_mma(
    const __half* __restrict__ qh,
    const __half* __restrict__ kh, const __half* __restrict__ kl,
    const __half* __restrict__ vh, const __half* __restrict__ vl,
    __half* __restrict__ oh)
{
    extern __shared__ char smem_raw[];
    const uint32_t smem = smem_to_u32(smem_raw);
    const uint32_t sQh = smem;
    const uint32_t sKV = smem + QTILE_B;

    const int tid  = threadIdx.x;
    const int wid  = tid >> 5;
    const int lane = tid & 31;
    const int qb = gridDim.x - 1 - blockIdx.x;   // heaviest tiles first
    const int h = blockIdx.y, b = blockIdx.z;
    const size_t head_elem = ((size_t)b * N_HEADS + h) * T_SEQ * HEAD_DIM;

    { // Q tile loader: 128 rows, thread -> row tid/2, 32-half chunk
        const int qrow = tid >> 1;
        const int qc   = (tid & 1) * 32;
        const uint32_t qdst = (uint32_t)(qrow * AST + qc) * 2;
        const char* p0 = (const char*)(qh + head_elem + (size_t)(qb * 128 + qrow) * 64 + qc);
#pragma unroll
        for (int c = 0; c < 4; c++)
            CP_ASYNC16(sQh + qdst + c * 16, p0 + c * 16);
        CP_COMMIT();
    }

    // K/V loader: 64 rows, thread -> row tid/4, 16-half (32-byte) chunk
    const int lrow = tid >> 2;
    const int lc   = (tid & 3) * 16;
    const uint32_t sdst = (uint32_t)(lrow * AST + lc) * 2;

    auto load_kv = [&](int stage, int kb) {
        const size_t roff = head_elem + (size_t)(kb * 64 + lrow) * 64 + lc;
        const uint32_t sb = sKV + (uint32_t)stage * (4 * ATILE_B);
        const char* p0 = (const char*)(kh + roff);
        const char* p1 = (const char*)(kl + roff);
        const char* p2 = (const char*)(vh + roff);
        const char* p3 = (const char*)(vl + roff);
#pragma unroll
        for (int c = 0; c < 2; c++) {
            CP_ASYNC16(sb + 0 * ATILE_B + sdst + c * 16, p0 + c * 16);
            CP_ASYNC16(sb + 1 * ATILE_B + sdst + c * 16, p1 + c * 16);
            CP_ASYNC16(sb + 2 * ATILE_B + sdst + c * 16, p2 + c * 16);
            CP_ASYNC16(sb + 3 * ATILE_B + sdst + c * 16, p3 + c * 16);
        }
        CP_COMMIT();
    };

    const int nt = 2 * qb + 2;
    load_kv(0, 0);
    load_kv(1, 1);
    CP_WAIT(1);
    __syncthreads();

    // Q fragments: warp w -> rows w*16..w*16+15
    uint32_t aQh[4][4];
    {
        const uint32_t a_ld = (uint32_t)((wid * 16 + (lane & 15)) * AST + (lane >> 4) * 8) * 2;
#pragma unroll
        for (int ks = 0; ks < 4; ks++)
            LDSM_X4(aQh[ks][0], aQh[ks][1], aQh[ks][2], aQh[ks][3], sQh + a_ld + ks * 32);
    }

    const uint32_t b_ldK = (uint32_t)(((lane & 7) + ((lane >> 4) << 3)) * AST
                                      + ((lane >> 3) & 1) * 8) * 2;
    const uint32_t v_ld  = (uint32_t)((lane & 15) * AST + ((lane >> 4) << 3)) * 2;

    float O[8][4];
#pragma unroll
    for (int t = 0; t < 8; t++)
#pragma unroll
        for (int e = 0; e < 4; e++) O[t][e] = 0.f;
    float m1 = NEG_INF, m2 = NEG_INF, l1 = 0.f, l2 = 0.f;

    const int rowg1 = qb * 128 + wid * 16 + (lane >> 2);   // global query row (e<2)
    const int colb  = (lane & 3) * 2;

    for (int kt = 0; kt < nt; kt++) {
        const uint32_t sb  = sKV + (uint32_t)(kt & 1) * (4 * ATILE_B);
        const uint32_t sKh = sb;
        const uint32_t sKl = sb + ATILE_B;
        const uint32_t sVh = sb + 2 * ATILE_B;
        const uint32_t sVl = sb + 3 * ATILE_B;

        float S[8][4];
#pragma unroll
        for (int t = 0; t < 8; t++)
#pragma unroll
            for (int e = 0; e < 4; e++) S[t][e] = 0.f;

        // ---- S = Q K^T : per ks, prefetch all fragments then hi/lo passes.
#pragma unroll
        for (int ks = 0; ks < 4; ks++) {
            uint32_t fKh[4][4], fKl[4][4];
#pragma unroll
            for (int np = 0; np < 4; np++) {
                const uint32_t off = (uint32_t)(np * 16 * AST) * 2 + ks * 32;
                LDSM_X4(fKh[np][0], fKh[np][1], fKh[np][2], fKh[np][3], sKh + b_ldK + off);
                LDSM_X4(fKl[np][0], fKl[np][1], fKl[np][2], fKl[np][3], sKl + b_ldK + off);
            }
#pragma unroll
            for (int np = 0; np < 4; np++) {
                uint32_t b0[2] = {fKh[np][0], fKh[np][1]};
                MMA_F16(S[2 * np], aQh[ks], b0);
            }
#pragma unroll
            for (int np = 0; np < 4; np++) {
                uint32_t b1[2] = {fKh[np][2], fKh[np][3]};
                MMA_F16(S[2 * np + 1], aQh[ks], b1);
            }
#pragma unroll
            for (int np = 0; np < 4; np++) {
                uint32_t b0[2] = {fKl[np][0], fKl[np][1]};
                MMA_F16(S[2 * np], aQh[ks], b0);
            }
#pragma unroll
            for (int np = 0; np < 4; np++) {
                uint32_t b1[2] = {fKl[np][2], fKl[np][3]};
                MMA_F16(S[2 * np + 1], aQh[ks], b1);
            }
        }

        // ---- causal mask (last two tiles cross the diagonal for this CTA)
        if (kt >= nt - 2) {
#pragma unroll
            for (int t = 0; t < 8; t++) {
#pragma unroll
                for (int e = 0; e < 4; e++) {
                    const int col = kt * 64 + t * 8 + colb + (e & 1);
                    const int row = rowg1 + (e >> 1) * 8;
                    if (col > row) S[t][e] = NEG_INF;
                }
            }
        }

        // ---- online softmax
        float mx1 = NEG_INF, mx2 = NEG_INF;
#pragma unroll
        for (int t = 0; t < 8; t++) {
            mx1 = fmaxf(mx1, fmaxf(S[t][0], S[t][1]));
            mx2 = fmaxf(mx2, fmaxf(S[t][2], S[t][3]));
        }
        mx1 = fmaxf(mx1, __shfl_xor_sync(0xffffffffu, mx1, 1));
        mx1 = fmaxf(mx1, __shfl_xor_sync(0xffffffffu, mx1, 2));
        mx2 = fmaxf(mx2, __shfl_xor_sync(0xffffffffu, mx2, 1));
        mx2 = fmaxf(mx2, __shfl_xor_sync(0xffffffffu, mx2, 2));

        const float mn1 = fmaxf(m1, mx1);
        const float mn2 = fmaxf(m2, mx2);
        const float c1 = __expf(m1 - mn1);
        const float c2 = __expf(m2 - mn2);
        l1 *= c1; l2 *= c2;
#pragma unroll
        for (int t = 0; t < 8; t++) {
            O[t][0] *= c1; O[t][1] *= c1;
            O[t][2] *= c2; O[t][3] *= c2;
        }
        float rs1 = 0.f, rs2 = 0.f;
#pragma unroll
        for (int t = 0; t < 8; t++) {
            S[t][0] = __expf(S[t][0] - mn1); rs1 += S[t][0];
            S[t][1] = __expf(S[t][1] - mn1); rs1 += S[t][1];
            S[t][2] = __expf(S[t][2] - mn2); rs2 += S[t][2];
            S[t][3] = __expf(S[t][3] - mn2); rs2 += S[t][3];
        }
        rs1 += __shfl_xor_sync(0xffffffffu, rs1, 1);
        rs1 += __shfl_xor_sync(0xffffffffu, rs1, 2);
        rs2 += __shfl_xor_sync(0xffffffffu, rs2, 1);
        rs2 += __shfl_xor_sync(0xffffffffu, rs2, 2);
        l1 += rs1; l2 += rs2;
        m1 = mn1; m2 = mn2;

        // ---- O += P V : per ks, prefetch V fragments then hi/lo passes.
#pragma unroll
        for (int ks = 0; ks < 4; ks++) {
            uint32_t aPh[4];
            aPh[0] = pack_f16(S[2 * ks][0],     S[2 * ks][1]);
            aPh[1] = pack_f16(S[2 * ks][2],     S[2 * ks][3]);
            aPh[2] = pack_f16(S[2 * ks + 1][0], S[2 * ks + 1][1]);
            aPh[3] = pack_f16(S[2 * ks + 1][2], S[2 * ks + 1][3]);
            uint32_t fVh[4][4], fVl[4][4];
#pragma unroll
            for (int np = 0; np < 4; np++) {
                const uint32_t off = (uint32_t)(ks * 16 * AST) * 2 + np * 32;
                LDSM_X4_T(fVh[np][0], fVh[np][1], fVh[np][2], fVh[np][3], sVh + v_ld + off);
                LDSM_X4_T(fVl[np][0], fVl[np][1], fVl[np][2], fVl[np][3], sVl + v_ld + off);
            }
#pragma unroll
            for (int np = 0; np < 4; np++) {
                uint32_t b0[2] = {fVh[np][0], fVh[np][1]};
                MMA_F16(O[2 * np], aPh, b0);
            }
#pragma unroll
            for (int np = 0; np < 4; np++) {
                uint32_t b1[2] = {fVh[np][2], fVh[np][3]};
                MMA_F16(O[2 * np + 1], aPh, b1);
            }
#pragma unroll
            for (int np = 0; np < 4; np++) {
                uint32_t b0[2] = {fVl[np][0], fVl[np][1]};
                MMA_F16(O[2 * np], aPh, b0);
            }
#pragma unroll
            for (int np = 0; np < 4; np++) {
                uint32_t b1[2] = {fVl[np][2], fVl[np][3]};
                MMA_F16(O[2 * np + 1], aPh, b1);
            }
        }

        // ---- pipeline advance
        if (kt + 1 < nt) {
            __syncthreads();
            if (kt + 2 < nt) { load_kv(kt & 1, kt + 2); CP_WAIT(1); }
            else             { CP_WAIT(0); }
            __syncthreads();
        }
    }

    // ---- epilogue: write f16 hi into (B,T,D)
    const float inv1 = 1.f / l1;
    const float inv2 = 1.f / l2;
    const size_t obase = (size_t)b * T_SEQ * D_MODEL + (size_t)h * 64;
#pragma unroll
    for (int t = 0; t < 8; t++) {
        const int d = t * 8 + colb;
        size_t i1 = obase + (size_t)rowg1 * D_MODEL + d;
        *(uint32_t*)&oh[i1] = pack_f16(O[t][0] * inv1, O[t][1] * inv1);
        size_t i2 = obase + (size_t)(rowg1 + 8) * D_MODEL + d;
        *(uint32_t*)&oh[i2] = pack_f16(O[t][2] * inv2, O[t][3] * inv2);
    }
}

// ---------------------------------------------------------------------------
extern "C" void kernel_launch(void* const* d_in, const int* in_sizes, int n_in,
                              void* d_out, int out_size)
{
    const float* x  = (const float*)d_in[0];
    const float* Wq = (const float*)d_in[1];
    const float* Wk = (const float*)d_in[2];
    const float* Wv = (const float*)d_in[3];
    const float* Wo = (const float*)d_in[4];

    float* out  = (float*)d_out;
    float* kout = out  + (size_t)M_ROWS * D_MODEL;
    float* vout = kout + (size_t)M_ROWS * D_MODEL;

    __half *xh, *wqh, *wql, *wkh, *wkl, *wvh, *wvl, *woh, *wol;
    __half *qhp, *khp, *klp, *vhp, *vlp, *ahp;
    cudaGetSymbolAddress((void**)&xh,  g_xh);
    cudaGetSymbolAddress((void**)&wqh, g_wqh);
    cudaGetSymbolAddress((void**)&wql, g_wql);
    cudaGetSymbolAddress((void**)&wkh, g_wkh);
    cudaGetSymbolAddress((void**)&wkl, g_wkl);
    cudaGetSymbolAddress((void**)&wvh, g_wvh);
    cudaGetSymbolAddress((void**)&wvl, g_wvl);
    cudaGetSymbolAddress((void**)&woh, g_woh);
    cudaGetSymbolAddress((void**)&wol, g_wol);
    cudaGetSymbolAddress((void**)&qhp, g_qh);
    cudaGetSymbolAddress((void**)&khp, g_kh);
    cudaGetSymbolAddress((void**)&klp, g_kl);
    cudaGetSymbolAddress((void**)&vhp, g_vh);
    cudaGetSymbolAddress((void**)&vlp, g_vl);
    cudaGetSymbolAddress((void**)&ahp, g_ah);

    cudaFuncSetAttribute(gemm_f16, cudaFuncAttributeMaxDynamicSharedMemorySize,
                         GEMM_SMEM_BYTES);
    cudaFuncSetAttribute(attn_mma, cudaFuncAttributeMaxDynamicSharedMemorySize,
                         ASMEM_BYTES);

    const int nx4 = M_ROWS * D_MODEL / 4;
    const int nw4 = D_MODEL * D_MODEL / 4;
    cvt_f16<<<(nx4 + 255) / 256, 256>>>(x, xh, nx4);

    SplitArgs sa;
    sa.src[0] = Wq; sa.hi[0] = wqh; sa.lo[0] = wql;
    sa.src[1] = Wk; sa.hi[1] = wkh; sa.lo[1] = wkl;
    sa.src[2] = Wv; sa.hi[2] = wvh; sa.lo[2] = wvl;
    sa.src[3] = Wo; sa.hi[3] = woh; sa.lo[3] = wol;
    split_f16w<<<dim3((nw4 + 255) / 256, 1, 4), 256>>>(sa, nw4);

    // ---- merged QKV GEMM (grid.z: 0=Q, 1=K, 2=V; all 2-pass)
    GemmArgs qkv;
    qkv.Ah = xh;
    qkv.Bh[0] = wqh; qkv.Bl[0] = wql;
    qkv.Bh[1] = wkh; qkv.Bl[1] = wkl;
    qkv.Bh[2] = wvh; qkv.Bl[2] = wvl;
    qkv.Cf[0] = nullptr; qkv.Cf[1] = kout; qkv.Cf[2] = vout;
    qkv.Ch[0] = qhp; qkv.Cl[0] = nullptr;          // Q: hi only, pre-scaled
    qkv.Ch[1] = khp; qkv.Cl[1] = klp;
    qkv.Ch[2] = vhp; qkv.Cl[2] = vlp;
    qkv.scale[0] = 0.125f; qkv.scale[1] = 1.f; qkv.scale[2] = 1.f;
    qkv.split = 1;
    gemm_f16<<<dim3(D_MODEL / BN, M_ROWS / BM, 3), 256, GEMM_SMEM_BYTES>>>(qkv);

    attn_mma<<<dim3(T_SEQ / 128, N_HEADS, B_SIZE), 256, ASMEM_BYTES>>>(
        qhp, khp, klp, vhp, vlp, ahp);

    // ---- O projection: 2-pass (ah x Wo hi/lo), fp32 output
    GemmArgs og;
    og.Ah = ahp;
    og.Bh[0] = woh; og.Bl[0] = wol;
    og.Cf[0] = out; og.Ch[0] = nullptr; og.Cl[0] = nullptr;
    og.scale[0] = 1.f; og.split = 0;
    og.Bh[1] = og.Bh[2] = nullptr; og.Bl[1] = og.Bl[2] = nullptr;
    og.Cf[1] = og.Cf[2] = nullptr; og.Ch[1] = og.Ch[2] = nullptr;
    og.Cl[1] = og.Cl[2] = nullptr; og.scale[1] = og.scale[2] = 1.f;
    gemm_f16<<<dim3(D_MODEL / BN, M_ROWS / BM, 1), 256, GEMM_SMEM_BYTES>>>(og);
}

// round 10
// speedup vs baseline: 6.0267x; 1.2395x over previous
#include <cuda_runtime.h>
#include <cuda_fp16.h>
#include <cstdint>
#include <math.h>

#define D_MODEL  1024
#define N_HEADS  16
#define HEAD_DIM 64
#define B_SIZE   4
#define T_SEQ    2048
#define M_ROWS   (B_SIZE * T_SEQ)   // 8192
#define KDIM     1024

#define NEG_INF  (__int_as_float(0xff800000))

// ---------------------------------------------------------------------------
// Scratch (device globals: no allocations allowed)
// ---------------------------------------------------------------------------
__device__ __half g_xh[(size_t)M_ROWS * D_MODEL];
__device__ __half g_wqh[(size_t)D_MODEL * D_MODEL];
__device__ __half g_wql[(size_t)D_MODEL * D_MODEL];
__device__ __half g_wkh[(size_t)D_MODEL * D_MODEL];
__device__ __half g_wkl[(size_t)D_MODEL * D_MODEL];
__device__ __half g_wvh[(size_t)D_MODEL * D_MODEL];
__device__ __half g_wvl[(size_t)D_MODEL * D_MODEL];   // written by splitter, unused
__device__ __half g_woh[(size_t)D_MODEL * D_MODEL];
__device__ __half g_wol[(size_t)D_MODEL * D_MODEL];   // written by splitter, unused

__device__ __half g_qh[(size_t)M_ROWS * D_MODEL];   // (B,H,T,hd), pre-scaled
__device__ __half g_kh[(size_t)M_ROWS * D_MODEL];
__device__ __half g_kl[(size_t)M_ROWS * D_MODEL];
__device__ __half g_vh[(size_t)M_ROWS * D_MODEL];
__device__ __half g_ah[(size_t)M_ROWS * D_MODEL];   // attn out (B,T,D), hi only

// ---------------------------------------------------------------------------
// PTX helpers (base ISA only)
// ---------------------------------------------------------------------------
__device__ __forceinline__ uint32_t smem_to_u32(const void* p) {
    uint32_t a;
    asm("{ .reg .u64 t; cvta.to.shared.u64 t, %1; cvt.u32.u64 %0, t; }"
        : "=r"(a) : "l"(p));
    return a;
}

#define CP_ASYNC16(dst, src) \
    asm volatile("cp.async.cg.shared.global [%0], [%1], 16;" :: "r"(dst), "l"(src))
#define CP_COMMIT() asm volatile("cp.async.commit_group;" ::: "memory")
#define CP_WAIT(n)  asm volatile("cp.async.wait_group %0;" :: "n"(n) : "memory")

#define LDSM_X4(r0, r1, r2, r3, addr) \
    asm volatile("ldmatrix.sync.aligned.m8n8.x4.shared.b16 {%0,%1,%2,%3}, [%4];" \
                 : "=r"(r0), "=r"(r1), "=r"(r2), "=r"(r3) : "r"(addr))
#define LDSM_X4_T(r0, r1, r2, r3, addr) \
    asm volatile("ldmatrix.sync.aligned.m8n8.x4.trans.shared.b16 {%0,%1,%2,%3}, [%4];" \
                 : "=r"(r0), "=r"(r1), "=r"(r2), "=r"(r3) : "r"(addr))

#define MMA_F16(c, a, b) \
    asm volatile("mma.sync.aligned.m16n8k16.row.col.f32.f16.f16.f32 " \
                 "{%0,%1,%2,%3}, {%4,%5,%6,%7}, {%8,%9}, {%0,%1,%2,%3};" \
                 : "+f"((c)[0]), "+f"((c)[1]), "+f"((c)[2]), "+f"((c)[3]) \
                 : "r"((a)[0]), "r"((a)[1]), "r"((a)[2]), "r"((a)[3]), \
                   "r"((b)[0]), "r"((b)[1]))

// pack two fp32 -> f16x2 reg: low half = x, high half = y
__device__ __forceinline__ uint32_t pack_f16(float x, float y) {
    uint32_t r;
    asm("cvt.rn.f16x2.f32 %0, %1, %2;" : "=r"(r) : "f"(y), "f"(x));
    return r;
}
__device__ __forceinline__ void split_pack_f16(float x, float y,
                                               uint32_t& hp, uint32_t& lp) {
    hp = pack_f16(x, y);
    __half2 hb = *(__half2*)&hp;
    lp = pack_f16(x - __half2float(hb.x), y - __half2float(hb.y));
}

// ---------------------------------------------------------------------------
// fp32 -> f16 converter (hi only) for x.
// ---------------------------------------------------------------------------
__global__ void __launch_bounds__(256) cvt_f16(const float* __restrict__ x,
                                               __half* __restrict__ hi, int n4)
{
    int i = blockIdx.x * blockDim.x + threadIdx.x;
    if (i >= n4) return;
    float4 v = ((const float4*)x)[i];
    ((uint32_t*)hi)[i * 2 + 0] = pack_f16(v.x, v.y);
    ((uint32_t*)hi)[i * 2 + 1] = pack_f16(v.z, v.w);
}

// ---------------------------------------------------------------------------
// fp32 -> (f16 hi, f16 lo) splitter for the 4 weight matrices (grid.z picks).
// ---------------------------------------------------------------------------
struct SplitArgs {
    const float* src[4];
    __half* hi[4];
    __half* lo[4];
};
__global__ void __launch_bounds__(256) split_f16w(const SplitArgs a, int n4)
{
    const int z = blockIdx.z;
    const float* x = a.src[z];
    __half* hi = a.hi[z];
    __half* lo = a.lo[z];
    int i = blockIdx.x * blockDim.x + threadIdx.x;
    if (i >= n4) return;
    float4 v = ((const float4*)x)[i];
    uint32_t h0, l0, h1, l1;
    split_pack_f16(v.x, v.y, h0, l0);
    split_pack_f16(v.z, v.w, h1, l1);
    ((uint32_t*)hi)[i * 2 + 0] = h0; ((uint32_t*)hi)[i * 2 + 1] = h1;
    ((uint32_t*)lo)[i * 2 + 0] = l0; ((uint32_t*)lo)[i * 2 + 1] = l1;
}

// ---------------------------------------------------------------------------
// mma.sync f16 GEMM:  C(8192x1024) = A @ W^T
// Bl != null -> 2-pass Ah*Bh + Ah*Bl (exact B).  Bl == null -> 1-pass Ah*Bh.
// ---------------------------------------------------------------------------
#define BM 128
#define BN 128
#define BK 32
#define NKI (KDIM / BK)          // 32
#define SKP 40                   // smem row stride in f16
#define TILE_B (BM * SKP * 2)    // 10240 bytes per tile
#define STAGE_B (3 * TILE_B)     // Ah, Bh, Bl
#define GEMM_SMEM_BYTES (3 * STAGE_B)

struct GemmArgs {
    const __half* Ah;
    const __half* Bh[3];
    const __half* Bl[3];
    float*  Cf[3];
    __half* Ch[3];
    __half* Cl[3];      // null -> hi-only f16 store
    float   scale[3];
    int     split;      // 1 -> (B,H,T,hd) output layout
};

__global__ void __launch_bounds__(256) gemm_f16(const GemmArgs args)
{
    extern __shared__ char smem_raw[];
    const uint32_t smem = smem_to_u32(smem_raw);

    const int z = blockIdx.z;
    const __half* Ah = args.Ah;
    const __half* Bh = args.Bh[z];
    const __half* Bl = args.Bl[z];
    const bool two = (Bl != nullptr);

    const int tid  = threadIdx.x;
    const int wid  = tid >> 5;
    const int lane = tid & 31;
    const int row0 = blockIdx.y * BM;
    const int col0 = blockIdx.x * BN;

    const int m0 = (wid & 1) * 64;
    const int n0 = (wid >> 1) * 32;

    const int lrow   = tid >> 1;
    const int lcol16 = (tid & 1) * 16;
    const size_t a_goff = (size_t)(row0 + lrow) * KDIM + lcol16;
    const size_t b_goff = (size_t)(col0 + lrow) * KDIM + lcol16;
    const uint32_t sdst0 = (uint32_t)(lrow * SKP + lcol16) * 2;

    auto load_stage = [&](int stage, int kt) {
        const uint32_t sb = smem + (uint32_t)stage * STAGE_B;
        const size_t ko = (size_t)kt * BK;
        const char* s0 = (const char*)(Ah + a_goff + ko);
        const char* s2 = (const char*)(Bh + b_goff + ko);
#pragma unroll
        for (int c = 0; c < 2; c++) {
            CP_ASYNC16(sb + 0 * TILE_B + sdst0 + c * 16, s0 + c * 16);
            CP_ASYNC16(sb + 1 * TILE_B + sdst0 + c * 16, s2 + c * 16);
        }
        if (two) {
            const char* s3 = (const char*)(Bl + b_goff + ko);
#pragma unroll
            for (int c = 0; c < 2; c++)
                CP_ASYNC16(sb + 2 * TILE_B + sdst0 + c * 16, s3 + c * 16);
        }
        CP_COMMIT();
    };

    const uint32_t a_ld = (uint32_t)((m0 + (lane & 15)) * SKP + (lane >> 4) * 8) * 2;
    const uint32_t b_ld = (uint32_t)((n0 + (lane & 7) + ((lane >> 4) << 3)) * SKP
                                     + (((lane >> 3) & 1) << 3)) * 2;

    float acc[4][4][4];
#pragma unroll
    for (int i = 0; i < 4; i++)
#pragma unroll
        for (int j = 0; j < 4; j++)
#pragma unroll
            for (int r = 0; r < 4; r++) acc[i][j][r] = 0.f;

    load_stage(0, 0);
    load_stage(1, 1);

    for (int kt = 0; kt < NKI; kt++) {
        if (kt + 1 < NKI) { CP_WAIT(1); } else { CP_WAIT(0); }
        __syncthreads();
        if (kt + 2 < NKI) load_stage((kt + 2) % 3, kt + 2);

        const uint32_t sb  = smem + (uint32_t)(kt % 3) * STAGE_B;
        const uint32_t sAh = sb + 0 * TILE_B;
        const uint32_t sBh = sb + 1 * TILE_B;
        const uint32_t sBl = sb + 2 * TILE_B;

#pragma unroll
        for (int ks = 0; ks < 2; ks++) {
            const uint32_t kso = (uint32_t)(ks * 16) * 2;
            uint32_t fAh[4][4];
            uint32_t fBh[4][2];
#pragma unroll
            for (int am = 0; am < 4; am++) {
                const uint32_t off = (uint32_t)(am * 16 * SKP) * 2 + kso;
                LDSM_X4(fAh[am][0], fAh[am][1], fAh[am][2], fAh[am][3], sAh + a_ld + off);
            }
#pragma unroll
            for (int bp = 0; bp < 2; bp++) {
                const uint32_t off = (uint32_t)(bp * 16 * SKP) * 2 + kso;
                LDSM_X4(fBh[2 * bp][0], fBh[2 * bp][1], fBh[2 * bp + 1][0], fBh[2 * bp + 1][1],
                        sBh + b_ld + off);
            }
            // hi pass: 16 independent accumulators
#pragma unroll
            for (int am = 0; am < 4; am++)
#pragma unroll
                for (int na = 0; na < 4; na++)
                    MMA_F16(acc[am][na], fAh[am], fBh[na]);
            if (two) {
                uint32_t fBl[4][2];
#pragma unroll
                for (int bp = 0; bp < 2; bp++) {
                    const uint32_t off = (uint32_t)(bp * 16 * SKP) * 2 + kso;
                    LDSM_X4(fBl[2 * bp][0], fBl[2 * bp][1], fBl[2 * bp + 1][0], fBl[2 * bp + 1][1],
                            sBl + b_ld + off);
                }
#pragma unroll
                for (int am = 0; am < 4; am++)
#pragma unroll
                    for (int na = 0; na < 4; na++)
                        MMA_F16(acc[am][na], fAh[am], fBl[na]);
            }
        }
    }

    float* Cf = args.Cf[z];
    __half* Ch = args.Ch[z];
    __half* Cl = args.Cl[z];
    const float scale = args.scale[z];
    const int split = args.split;

    const int lr4 = lane >> 2;
    const int lc2 = (lane & 3) * 2;
#pragma unroll
    for (int am = 0; am < 4; am++) {
        const int mA = row0 + m0 + am * 16 + lr4;
#pragma unroll
        for (int na = 0; na < 4; na++) {
            const int n = col0 + n0 + na * 8 + lc2;
#pragma unroll
            for (int half_ = 0; half_ < 2; half_++) {
                const int m = mA + half_ * 8;
                float vx = acc[am][na][half_ * 2 + 0] * scale;
                float vy = acc[am][na][half_ * 2 + 1] * scale;
                size_t idx;
                if (split) {
                    const int bb = m >> 11, t = m & 2047;
                    const int hh = n >> 6, d = n & 63;
                    idx = (((size_t)bb * N_HEADS + hh) * T_SEQ + t) * HEAD_DIM + d;
                } else {
                    idx = (size_t)m * D_MODEL + n;
                }
                if (Cf) *(float2*)&Cf[idx] = make_float2(vx, vy);
                if (Ch) {
                    if (Cl) {
                        uint32_t hp, lp;
                        split_pack_f16(vx, vy, hp, lp);
                        *(uint32_t*)&Ch[idx] = hp;
                        *(uint32_t*)&Cl[idx] = lp;
                    } else {
                        *(uint32_t*)&Ch[idx] = pack_f16(vx, vy);
                    }
                }
            }
        }
    }
}

// ---------------------------------------------------------------------------
// mma.sync flash attention, causal. BQ=128 (8 warps x m16), BKV=64, 256 thr.
// QK^T: 2-pass (Q hi x K hi/lo).  P·V: 1-pass (P hi x V hi).
// Output: f16 hi only, (B,T,D).
// ---------------------------------------------------------------------------
#define AST 72                        // smem row stride (f16 elems)
#define ATILE_B (64 * AST * 2)        // 9216 bytes (64-row K/V tile)
#define QTILE_B (128 * AST * 2)       // 18432 bytes (128-row Q tile)
#define ASMEM_BYTES (QTILE_B + 6 * ATILE_B)   // Q + 2 stages x {Kh,Kl,Vh}

__global__ void __launch_bounds__(256, 2) attn_mma(
    const __half* __restrict__ qh,
    const __half* __restrict__ kh, const __half* __restrict__ kl,
    const __half* __restrict__ vh,
    __half* __restrict__ oh)
{
    extern __shared__ char smem_raw[];
    const uint32_t smem = smem_to_u32(smem_raw);
    const uint32_t sQh = smem;
    const uint32_t sKV = smem + QTILE_B;

    const int tid  = threadIdx.x;
    const int wid  = tid >> 5;
    const int lane = tid & 31;
    const int qb = gridDim.x - 1 - blockIdx.x;   // heaviest tiles first
    const int h = blockIdx.y, b = blockIdx.z;
    const size_t head_elem = ((size_t)b * N_HEADS + h) * T_SEQ * HEAD_DIM;

    { // Q tile loader: 128 rows, thread -> row tid/2, 32-half chunk
        const int qrow = tid >> 1;
        const int qc   = (tid & 1) * 32;
        const uint32_t qdst = (uint32_t)(qrow * AST + qc) * 2;
        const char* p0 = (const char*)(qh + head_elem + (size_t)(qb * 128 + qrow) * 64 + qc);
#pragma unroll
        for (int c = 0; c < 4; c++)
            CP_ASYNC16(sQh + qdst + c * 16, p0 + c * 16);
        CP_COMMIT();
    }

    // K/V loader: 64 rows, thread -> row tid/4, 16-half (32-byte) chunk
    const int lrow = tid >> 2;
    const int lc   = (tid & 3) * 16;
    const uint32_t sdst = (uint32_t)(lrow * AST + lc) * 2;

    auto load_kv = [&](int stage, int kb) {
        const size_t roff = head_elem + (size_t)(kb * 64 + lrow) * 64 + lc;
        const uint32_t sb = sKV + (uint32_t)stage * (3 * ATILE_B);
        const char* p0 = (const char*)(kh + roff);
        const char* p1 = (const char*)(kl + roff);
        const char* p2 = (const char*)(vh + roff);
#pragma unroll
        for (int c = 0; c < 2; c++) {
            CP_ASYNC16(sb + 0 * ATILE_B + sdst + c * 16, p0 + c * 16);
            CP_ASYNC16(sb + 1 * ATILE_B + sdst + c * 16, p1 + c * 16);
            CP_ASYNC16(sb + 2 * ATILE_B + sdst + c * 16, p2 + c * 16);
        }
        CP_COMMIT();
    };

    const int nt = 2 * qb + 2;
    load_kv(0, 0);
    load_kv(1, 1);
    CP_WAIT(1);
    __syncthreads();

    // Q fragments: warp w -> rows w*16..w*16+15
    uint32_t aQh[4][4];
    {
        const uint32_t a_ld = (uint32_t)((wid * 16 + (lane & 15)) * AST + (lane >> 4) * 8) * 2;
#pragma unroll
        for (int ks = 0; ks < 4; ks++)
            LDSM_X4(aQh[ks][0], aQh[ks][1], aQh[ks][2], aQh[ks][3], sQh + a_ld + ks * 32);
    }

    const uint32_t b_ldK = (uint32_t)(((lane & 7) + ((lane >> 4) << 3)) * AST
                                      + ((lane >> 3) & 1) * 8) * 2;
    const uint32_t v_ld  = (uint32_t)((lane & 15) * AST + ((lane >> 4) << 3)) * 2;

    float O[8][4];
#pragma unroll
    for (int t = 0; t < 8; t++)
#pragma unroll
        for (int e = 0; e < 4; e++) O[t][e] = 0.f;
    float m1 = NEG_INF, m2 = NEG_INF, l1 = 0.f, l2 = 0.f;

    const int rowg1 = qb * 128 + wid * 16 + (lane >> 2);   // global query row (e<2)
    const int colb  = (lane & 3) * 2;

    for (int kt = 0; kt < nt; kt++) {
        const uint32_t sb  = sKV + (uint32_t)(kt & 1) * (3 * ATILE_B);
        const uint32_t sKh = sb;
        const uint32_t sKl = sb + ATILE_B;
        const uint32_t sVh = sb + 2 * ATILE_B;

        float S[8][4];
#pragma unroll
        for (int t = 0; t < 8; t++)
#pragma unroll
            for (int e = 0; e < 4; e++) S[t][e] = 0.f;

        // ---- S = Q K^T : per ks, prefetch all fragments then hi/lo passes.
#pragma unroll
        for (int ks = 0; ks < 4; ks++) {
            uint32_t fKh[4][4], fKl[4][4];
#pragma unroll
            for (int np = 0; np < 4; np++) {
                const uint32_t off = (uint32_t)(np * 16 * AST) * 2 + ks * 32;
                LDSM_X4(fKh[np][0], fKh[np][1], fKh[np][2], fKh[np][3], sKh + b_ldK + off);
                LDSM_X4(fKl[np][0], fKl[np][1], fKl[np][2], fKl[np][3], sKl + b_ldK + off);
            }
#pragma unroll
            for (int np = 0; np < 4; np++) {
                uint32_t b0[2] = {fKh[np][0], fKh[np][1]};
                MMA_F16(S[2 * np], aQh[ks], b0);
            }
#pragma unroll
            for (int np = 0; np < 4; np++) {
                uint32_t b1[2] = {fKh[np][2], fKh[np][3]};
                MMA_F16(S[2 * np + 1], aQh[ks], b1);
            }
#pragma unroll
            for (int np = 0; np < 4; np++) {
                uint32_t b0[2] = {fKl[np][0], fKl[np][1]};
                MMA_F16(S[2 * np], aQh[ks], b0);
            }
#pragma unroll
            for (int np = 0; np < 4; np++) {
                uint32_t b1[2] = {fKl[np][2], fKl[np][3]};
                MMA_F16(S[2 * np + 1], aQh[ks], b1);
            }
        }

        // ---- causal mask (last two tiles cross the diagonal for this CTA)
        if (kt >= nt - 2) {
#pragma unroll
            for (int t = 0; t < 8; t++) {
#pragma unroll
                for (int e = 0; e < 4; e++) {
                    const int col = kt * 64 + t * 8 + colb + (e & 1);
                    const int row = rowg1 + (e >> 1) * 8;
                    if (col > row) S[t][e] = NEG_INF;
                }
            }
        }

        // ---- online softmax
        float mx1 = NEG_INF, mx2 = NEG_INF;
#pragma unroll
        for (int t = 0; t < 8; t++) {
            mx1 = fmaxf(mx1, fmaxf(S[t][0], S[t][1]));
            mx2 = fmaxf(mx2, fmaxf(S[t][2], S[t][3]));
        }
        mx1 = fmaxf(mx1, __shfl_xor_sync(0xffffffffu, mx1, 1));
        mx1 = fmaxf(mx1, __shfl_xor_sync(0xffffffffu, mx1, 2));
        mx2 = fmaxf(mx2, __shfl_xor_sync(0xffffffffu, mx2, 1));
        mx2 = fmaxf(mx2, __shfl_xor_sync(0xffffffffu, mx2, 2));

        const float mn1 = fmaxf(m1, mx1);
        const float mn2 = fmaxf(m2, mx2);
        const float c1 = __expf(m1 - mn1);
        const float c2 = __expf(m2 - mn2);
        l1 *= c1; l2 *= c2;
#pragma unroll
        for (int t = 0; t < 8; t++) {
            O[t][0] *= c1; O[t][1] *= c1;
            O[t][2] *= c2; O[t][3] *= c2;
        }
        float rs1 = 0.f, rs2 = 0.f;
#pragma unroll
        for (int t = 0; t < 8; t++) {
            S[t][0] = __expf(S[t][0] - mn1); rs1 += S[t][0];
            S[t][1] = __expf(S[t][1] - mn1); rs1 += S[t][1];
            S[t][2] = __expf(S[t][2] - mn2); rs2 += S[t][2];
            S[t][3] = __expf(S[t][3] - mn2); rs2 += S[t][3];
        }
        rs1 += __shfl_xor_sync(0xffffffffu, rs1, 1);
        rs1 += __shfl_xor_sync(0xffffffffu, rs1, 2);
        rs2 += __shfl_xor_sync(0xffffffffu, rs2, 1);
        rs2 += __shfl_xor_sync(0xffffffffu, rs2, 2);
        l1 += rs1; l2 += rs2;
        m1 = mn1; m2 = mn2;

        // ---- O += P V : 1-pass (P hi x V hi)
#pragma unroll
        for (int ks = 0; ks < 4; ks++) {
            uint32_t aPh[4];
            aPh[0] = pack_f16(S[2 * ks][0],     S[2 * ks][1]);
            aPh[1] = pack_f16(S[2 * ks][2],     S[2 * ks][3]);
            aPh[2] = pack_f16(S[2 * ks + 1][0], S[2 * ks + 1][1]);
            aPh[3] = pack_f16(S[2 * ks + 1][2], S[2 * ks + 1][3]);
            uint32_t fVh[4][4];
#pragma unroll
            for (int np = 0; np < 4; np++) {
                const uint32_t off = (uint32_t)(ks * 16 * AST) * 2 + np * 32;
                LDSM_X4_T(fVh[np][0], fVh[np][1], fVh[np][2], fVh[np][3], sVh + v_ld + off);
            }
#pragma unroll
            for (int np = 0; np < 4; np++) {
                uint32_t b0[2] = {fVh[np][0], fVh[np][1]};
                MMA_F16(O[2 * np], aPh, b0);
            }
#pragma unroll
            for (int np = 0; np < 4; np++) {
                uint32_t b1[2] = {fVh[np][2], fVh[np][3]};
                MMA_F16(O[2 * np + 1], aPh, b1);
            }
        }

        // ---- pipeline advance
        if (kt + 1 < nt) {
            __syncthreads();
            if (kt + 2 < nt) { load_kv(kt & 1, kt + 2); CP_WAIT(1); }
            else             { CP_WAIT(0); }
            __syncthreads();
        }
    }

    // ---- epilogue: write f16 hi into (B,T,D)
    const float inv1 = 1.f / l1;
    const float inv2 = 1.f / l2;
    const size_t obase = (size_t)b * T_SEQ * D_MODEL + (size_t)h * 64;
#pragma unroll
    for (int t = 0; t < 8; t++) {
        const int d = t * 8 + colb;
        size_t i1 = obase + (size_t)rowg1 * D_MODEL + d;
        *(uint32_t*)&oh[i1] = pack_f16(O[t][0] * inv1, O[t][1] * inv1);
        size_t i2 = obase + (size_t)(rowg1 + 8) * D_MODEL + d;
        *(uint32_t*)&oh[i2] = pack_f16(O[t][2] * inv2, O[t][3] * inv2);
    }
}

// ---------------------------------------------------------------------------
extern "C" void kernel_launch(void* const* d_in, const int* in_sizes, int n_in,
                              void* d_out, int out_size)
{
    const float* x  = (const float*)d_in[0];
    const float* Wq = (const float*)d_in[1];
    const float* Wk = (const float*)d_in[2];
    const float* Wv = (const float*)d_in[3];
    const float* Wo = (const float*)d_in[4];

    float* out  = (float*)d_out;
    float* kout = out  + (size_t)M_ROWS * D_MODEL;
    float* vout = kout + (size_t)M_ROWS * D_MODEL;

    __half *xh, *wqh, *wql, *wkh, *wkl, *wvh, *wvl, *woh, *wol;
    __half *qhp, *khp, *klp, *vhp, *ahp;
    cudaGetSymbolAddress((void**)&xh,  g_xh);
    cudaGetSymbolAddress((void**)&wqh, g_wqh);
    cudaGetSymbolAddress((void**)&wql, g_wql);
    cudaGetSymbolAddress((void**)&wkh, g_wkh);
    cudaGetSymbolAddress((void**)&wkl, g_wkl);
    cudaGetSymbolAddress((void**)&wvh, g_wvh);
    cudaGetSymbolAddress((void**)&wvl, g_wvl);
    cudaGetSymbolAddress((void**)&woh, g_woh);
    cudaGetSymbolAddress((void**)&wol, g_wol);
    cudaGetSymbolAddress((void**)&qhp, g_qh);
    cudaGetSymbolAddress((void**)&khp, g_kh);
    cudaGetSymbolAddress((void**)&klp, g_kl);
    cudaGetSymbolAddress((void**)&vhp, g_vh);
    cudaGetSymbolAddress((void**)&ahp, g_ah);

    cudaFuncSetAttribute(gemm_f16, cudaFuncAttributeMaxDynamicSharedMemorySize,
                         GEMM_SMEM_BYTES);
    cudaFuncSetAttribute(attn_mma, cudaFuncAttributeMaxDynamicSharedMemorySize,
                         ASMEM_BYTES);

    const int nx4 = M_ROWS * D_MODEL / 4;
    const int nw4 = D_MODEL * D_MODEL / 4;
    cvt_f16<<<(nx4 + 255) / 256, 256>>>(x, xh, nx4);

    SplitArgs sa;
    sa.src[0] = Wq; sa.hi[0] = wqh; sa.lo[0] = wql;
    sa.src[1] = Wk; sa.hi[1] = wkh; sa.lo[1] = wkl;
    sa.src[2] = Wv; sa.hi[2] = wvh; sa.lo[2] = wvl;
    sa.src[3] = Wo; sa.hi[3] = woh; sa.lo[3] = wol;
    split_f16w<<<dim3((nw4 + 255) / 256, 1, 4), 256>>>(sa, nw4);

    // ---- merged QKV GEMM (grid.z: 0=Q 2-pass, 1=K 2-pass, 2=V 1-pass)
    GemmArgs qkv;
    qkv.Ah = xh;
    qkv.Bh[0] = wqh; qkv.Bl[0] = wql;
    qkv.Bh[1] = wkh; qkv.Bl[1] = wkl;
    qkv.Bh[2] = wvh; qkv.Bl[2] = nullptr;          // V: 1-pass
    qkv.Cf[0] = nullptr; qkv.Cf[1] = kout; qkv.Cf[2] = vout;
    qkv.Ch[0] = qhp; qkv.Cl[0] = nullptr;          // Q: hi only, pre-scaled
    qkv.Ch[1] = khp; qkv.Cl[1] = klp;
    qkv.Ch[2] = vhp; qkv.Cl[2] = nullptr;          // V: hi only
    qkv.scale[0] = 0.125f; qkv.scale[1] = 1.f; qkv.scale[2] = 1.f;
    qkv.split = 1;
    gemm_f16<<<dim3(D_MODEL / BN, M_ROWS / BM, 3), 256, GEMM_SMEM_BYTES>>>(qkv);

    attn_mma<<<dim3(T_SEQ / 128, N_HEADS, B_SIZE), 256, ASMEM_BYTES>>>(
        qhp, khp, klp, vhp, ahp);

    // ---- O projection: 1-pass (ah x Wo hi), fp32 output
    GemmArgs og;
    og.Ah = ahp;
    og.Bh[0] = woh; og.Bl[0] = nullptr;
    og.Cf[0] = out; og.Ch[0] = nullptr; og.Cl[0] = nullptr;
    og.scale[0] = 1.f; og.split = 0;
    og.Bh[1] = og.Bh[2] = nullptr; og.Bl[1] = og.Bl[2] = nullptr;
    og.Cf[1] = og.Cf[2] = nullptr; og.Ch[1] = og.Ch[2] = nullptr;
    og.Cl[1] = og.Cl[2] = nullptr; og.scale[1] = og.scale[2] = 1.f;
    gemm_f16<<<dim3(D_MODEL / BN, M_ROWS / BM, 1), 256, GEMM_SMEM_BYTES>>>(og);
}

// round 11
// speedup vs baseline: 7.1525x; 1.1868x over previous
#include <cuda_runtime.h>
#include <cuda_fp16.h>
#include <cstdint>
#include <math.h>

#define D_MODEL  1024
#define N_HEADS  16
#define HEAD_DIM 64
#define B_SIZE   4
#define T_SEQ    2048
#define M_ROWS   (B_SIZE * T_SEQ)   // 8192
#define KDIM     1024

#define NEG_INF  (__int_as_float(0xff800000))

// ---------------------------------------------------------------------------
// Scratch (device globals: no allocations allowed)
// ---------------------------------------------------------------------------
__device__ __half g_xh[(size_t)M_ROWS * D_MODEL];
__device__ __half g_wqh[(size_t)D_MODEL * D_MODEL];
__device__ __half g_wql[(size_t)D_MODEL * D_MODEL];
__device__ __half g_wkh[(size_t)D_MODEL * D_MODEL];
__device__ __half g_wvh[(size_t)D_MODEL * D_MODEL];
__device__ __half g_woh[(size_t)D_MODEL * D_MODEL];

__device__ __half g_qh[(size_t)M_ROWS * D_MODEL];   // (B,H,T,hd), pre-scaled
__device__ __half g_kh[(size_t)M_ROWS * D_MODEL];
__device__ __half g_vh[(size_t)M_ROWS * D_MODEL];
__device__ __half g_ah[(size_t)M_ROWS * D_MODEL];   // attn out (B,T,D), hi only

// ---------------------------------------------------------------------------
// PTX helpers (base ISA only)
// ---------------------------------------------------------------------------
__device__ __forceinline__ uint32_t smem_to_u32(const void* p) {
    uint32_t a;
    asm("{ .reg .u64 t; cvta.to.shared.u64 t, %1; cvt.u32.u64 %0, t; }"
        : "=r"(a) : "l"(p));
    return a;
}

#define CP_ASYNC16(dst, src) \
    asm volatile("cp.async.cg.shared.global [%0], [%1], 16;" :: "r"(dst), "l"(src))
#define CP_COMMIT() asm volatile("cp.async.commit_group;" ::: "memory")
#define CP_WAIT(n)  asm volatile("cp.async.wait_group %0;" :: "n"(n) : "memory")

#define LDSM_X4(r0, r1, r2, r3, addr) \
    asm volatile("ldmatrix.sync.aligned.m8n8.x4.shared.b16 {%0,%1,%2,%3}, [%4];" \
                 : "=r"(r0), "=r"(r1), "=r"(r2), "=r"(r3) : "r"(addr))
#define LDSM_X4_T(r0, r1, r2, r3, addr) \
    asm volatile("ldmatrix.sync.aligned.m8n8.x4.trans.shared.b16 {%0,%1,%2,%3}, [%4];" \
                 : "=r"(r0), "=r"(r1), "=r"(r2), "=r"(r3) : "r"(addr))

#define MMA_F16(c, a, b) \
    asm volatile("mma.sync.aligned.m16n8k16.row.col.f32.f16.f16.f32 " \
                 "{%0,%1,%2,%3}, {%4,%5,%6,%7}, {%8,%9}, {%0,%1,%2,%3};" \
                 : "+f"((c)[0]), "+f"((c)[1]), "+f"((c)[2]), "+f"((c)[3]) \
                 : "r"((a)[0]), "r"((a)[1]), "r"((a)[2]), "r"((a)[3]), \
                   "r"((b)[0]), "r"((b)[1]))

// pack two fp32 -> f16x2 reg: low half = x, high half = y
__device__ __forceinline__ uint32_t pack_f16(float x, float y) {
    uint32_t r;
    asm("cvt.rn.f16x2.f32 %0, %1, %2;" : "=r"(r) : "f"(y), "f"(x));
    return r;
}
__device__ __forceinline__ void split_pack_f16(float x, float y,
                                               uint32_t& hp, uint32_t& lp) {
    hp = pack_f16(x, y);
    __half2 hb = *(__half2*)&hp;
    lp = pack_f16(x - __half2float(hb.x), y - __half2float(hb.y));
}

// ---------------------------------------------------------------------------
// fp32 -> f16 converter (hi only), grid.z picks among up to 4 sources.
// ---------------------------------------------------------------------------
struct CvtArgs {
    const float* src[4];
    __half* hi[4];
};
__global__ void __launch_bounds__(256) cvt_f16m(const CvtArgs a, int n4)
{
    const int z = blockIdx.z;
    const float* x = a.src[z];
    __half* hi = a.hi[z];
    int i = blockIdx.x * blockDim.x + threadIdx.x;
    if (i >= n4) return;
    float4 v = ((const float4*)x)[i];
    ((uint32_t*)hi)[i * 2 + 0] = pack_f16(v.x, v.y);
    ((uint32_t*)hi)[i * 2 + 1] = pack_f16(v.z, v.w);
}

__global__ void __launch_bounds__(256) cvt_f16(const float* __restrict__ x,
                                               __half* __restrict__ hi, int n4)
{
    int i = blockIdx.x * blockDim.x + threadIdx.x;
    if (i >= n4) return;
    float4 v = ((const float4*)x)[i];
    ((uint32_t*)hi)[i * 2 + 0] = pack_f16(v.x, v.y);
    ((uint32_t*)hi)[i * 2 + 1] = pack_f16(v.z, v.w);
}

// fp32 -> (f16 hi, f16 lo) splitter (Wq only now)
__global__ void __launch_bounds__(256) split_f16w(const float* __restrict__ x,
                                                  __half* __restrict__ hi,
                                                  __half* __restrict__ lo, int n4)
{
    int i = blockIdx.x * blockDim.x + threadIdx.x;
    if (i >= n4) return;
    float4 v = ((const float4*)x)[i];
    uint32_t h0, l0, h1, l1;
    split_pack_f16(v.x, v.y, h0, l0);
    split_pack_f16(v.z, v.w, h1, l1);
    ((uint32_t*)hi)[i * 2 + 0] = h0; ((uint32_t*)hi)[i * 2 + 1] = h1;
    ((uint32_t*)lo)[i * 2 + 0] = l0; ((uint32_t*)lo)[i * 2 + 1] = l1;
}

// ---------------------------------------------------------------------------
// mma.sync f16 GEMM:  C(8192x1024) = A @ W^T
// Bl != null -> 2-pass Ah*Bh + Ah*Bl (exact B).  Bl == null -> 1-pass Ah*Bh.
// ---------------------------------------------------------------------------
#define BM 128
#define BN 128
#define BK 32
#define NKI (KDIM / BK)          // 32
#define SKP 40                   // smem row stride in f16
#define TILE_B (BM * SKP * 2)    // 10240 bytes per tile
#define STAGE_B (3 * TILE_B)     // Ah, Bh, Bl
#define GEMM_SMEM_BYTES (3 * STAGE_B)

struct GemmArgs {
    const __half* Ah;
    const __half* Bh[3];
    const __half* Bl[3];
    float*  Cf[3];
    __half* Ch[3];
    __half* Cl[3];      // null -> hi-only f16 store
    float   scale[3];
    int     split;      // 1 -> (B,H,T,hd) output layout
};

__global__ void __launch_bounds__(256) gemm_f16(const GemmArgs args)
{
    extern __shared__ char smem_raw[];
    const uint32_t smem = smem_to_u32(smem_raw);

    const int z = blockIdx.z;
    const __half* Ah = args.Ah;
    const __half* Bh = args.Bh[z];
    const __half* Bl = args.Bl[z];
    const bool two = (Bl != nullptr);

    const int tid  = threadIdx.x;
    const int wid  = tid >> 5;
    const int lane = tid & 31;
    const int row0 = blockIdx.y * BM;
    const int col0 = blockIdx.x * BN;

    const int m0 = (wid & 1) * 64;
    const int n0 = (wid >> 1) * 32;

    const int lrow   = tid >> 1;
    const int lcol16 = (tid & 1) * 16;
    const size_t a_goff = (size_t)(row0 + lrow) * KDIM + lcol16;
    const size_t b_goff = (size_t)(col0 + lrow) * KDIM + lcol16;
    const uint32_t sdst0 = (uint32_t)(lrow * SKP + lcol16) * 2;

    auto load_stage = [&](int stage, int kt) {
        const uint32_t sb = smem + (uint32_t)stage * STAGE_B;
        const size_t ko = (size_t)kt * BK;
        const char* s0 = (const char*)(Ah + a_goff + ko);
        const char* s2 = (const char*)(Bh + b_goff + ko);
#pragma unroll
        for (int c = 0; c < 2; c++) {
            CP_ASYNC16(sb + 0 * TILE_B + sdst0 + c * 16, s0 + c * 16);
            CP_ASYNC16(sb + 1 * TILE_B + sdst0 + c * 16, s2 + c * 16);
        }
        if (two) {
            const char* s3 = (const char*)(Bl + b_goff + ko);
#pragma unroll
            for (int c = 0; c < 2; c++)
                CP_ASYNC16(sb + 2 * TILE_B + sdst0 + c * 16, s3 + c * 16);
        }
        CP_COMMIT();
    };

    const uint32_t a_ld = (uint32_t)((m0 + (lane & 15)) * SKP + (lane >> 4) * 8) * 2;
    const uint32_t b_ld = (uint32_t)((n0 + (lane & 7) + ((lane >> 4) << 3)) * SKP
                                     + (((lane >> 3) & 1) << 3)) * 2;

    float acc[4][4][4];
#pragma unroll
    for (int i = 0; i < 4; i++)
#pragma unroll
        for (int j = 0; j < 4; j++)
#pragma unroll
            for (int r = 0; r < 4; r++) acc[i][j][r] = 0.f;

    load_stage(0, 0);
    load_stage(1, 1);

    for (int kt = 0; kt < NKI; kt++) {
        if (kt + 1 < NKI) { CP_WAIT(1); } else { CP_WAIT(0); }
        __syncthreads();
        if (kt + 2 < NKI) load_stage((kt + 2) % 3, kt + 2);

        const uint32_t sb  = smem + (uint32_t)(kt % 3) * STAGE_B;
        const uint32_t sAh = sb + 0 * TILE_B;
        const uint32_t sBh = sb + 1 * TILE_B;
        const uint32_t sBl = sb + 2 * TILE_B;

#pragma unroll
        for (int ks = 0; ks < 2; ks++) {
            const uint32_t kso = (uint32_t)(ks * 16) * 2;
            uint32_t fAh[4][4];
            uint32_t fBh[4][2];
#pragma unroll
            for (int am = 0; am < 4; am++) {
                const uint32_t off = (uint32_t)(am * 16 * SKP) * 2 + kso;
                LDSM_X4(fAh[am][0], fAh[am][1], fAh[am][2], fAh[am][3], sAh + a_ld + off);
            }
#pragma unroll
            for (int bp = 0; bp < 2; bp++) {
                const uint32_t off = (uint32_t)(bp * 16 * SKP) * 2 + kso;
                LDSM_X4(fBh[2 * bp][0], fBh[2 * bp][1], fBh[2 * bp + 1][0], fBh[2 * bp + 1][1],
                        sBh + b_ld + off);
            }
#pragma unroll
            for (int am = 0; am < 4; am++)
#pragma unroll
                for (int na = 0; na < 4; na++)
                    MMA_F16(acc[am][na], fAh[am], fBh[na]);
            if (two) {
                uint32_t fBl[4][2];
#pragma unroll
                for (int bp = 0; bp < 2; bp++) {
                    const uint32_t off = (uint32_t)(bp * 16 * SKP) * 2 + kso;
                    LDSM_X4(fBl[2 * bp][0], fBl[2 * bp][1], fBl[2 * bp + 1][0], fBl[2 * bp + 1][1],
                            sBl + b_ld + off);
                }
#pragma unroll
                for (int am = 0; am < 4; am++)
#pragma unroll
                    for (int na = 0; na < 4; na++)
                        MMA_F16(acc[am][na], fAh[am], fBl[na]);
            }
        }
    }

    float* Cf = args.Cf[z];
    __half* Ch = args.Ch[z];
    __half* Cl = args.Cl[z];
    const float scale = args.scale[z];
    const int split = args.split;

    const int lr4 = lane >> 2;
    const int lc2 = (lane & 3) * 2;
#pragma unroll
    for (int am = 0; am < 4; am++) {
        const int mA = row0 + m0 + am * 16 + lr4;
#pragma unroll
        for (int na = 0; na < 4; na++) {
            const int n = col0 + n0 + na * 8 + lc2;
#pragma unroll
            for (int half_ = 0; half_ < 2; half_++) {
                const int m = mA + half_ * 8;
                float vx = acc[am][na][half_ * 2 + 0] * scale;
                float vy = acc[am][na][half_ * 2 + 1] * scale;
                size_t idx;
                if (split) {
                    const int bb = m >> 11, t = m & 2047;
                    const int hh = n >> 6, d = n & 63;
                    idx = (((size_t)bb * N_HEADS + hh) * T_SEQ + t) * HEAD_DIM + d;
                } else {
                    idx = (size_t)m * D_MODEL + n;
                }
                if (Cf) *(float2*)&Cf[idx] = make_float2(vx, vy);
                if (Ch) {
                    if (Cl) {
                        uint32_t hp, lp;
                        split_pack_f16(vx, vy, hp, lp);
                        *(uint32_t*)&Ch[idx] = hp;
                        *(uint32_t*)&Cl[idx] = lp;
                    } else {
                        *(uint32_t*)&Ch[idx] = pack_f16(vx, vy);
                    }
                }
            }
        }
    }
}

// ---------------------------------------------------------------------------
// mma.sync flash attention, causal. BQ=128 (8 warps x m16), BKV=64, 256 thr.
// QK^T: 1-pass (Q hi x K hi).  P·V: 1-pass (P hi x V hi).
// Output: f16 hi only, (B,T,D).
// ---------------------------------------------------------------------------
#define AST 72                        // smem row stride (f16 elems)
#define ATILE_B (64 * AST * 2)        // 9216 bytes (64-row K/V tile)
#define QTILE_B (128 * AST * 2)       // 18432 bytes (128-row Q tile)
#define ASMEM_BYTES (QTILE_B + 4 * ATILE_B)   // Q + 2 stages x {Kh,Vh}

__global__ void __launch_bounds__(256, 2) attn_mma(
    const __half* __restrict__ qh,
    const __half* __restrict__ kh,
    const __half* __restrict__ vh,
    __half* __restrict__ oh)
{
    extern __shared__ char smem_raw[];
    const uint32_t smem = smem_to_u32(smem_raw);
    const uint32_t sQh = smem;
    const uint32_t sKV = smem + QTILE_B;

    const int tid  = threadIdx.x;
    const int wid  = tid >> 5;
    const int lane = tid & 31;
    const int qb = gridDim.x - 1 - blockIdx.x;   // heaviest tiles first
    const int h = blockIdx.y, b = blockIdx.z;
    const size_t head_elem = ((size_t)b * N_HEADS + h) * T_SEQ * HEAD_DIM;

    { // Q tile loader: 128 rows, thread -> row tid/2, 32-half chunk
        const int qrow = tid >> 1;
        const int qc   = (tid & 1) * 32;
        const uint32_t qdst = (uint32_t)(qrow * AST + qc) * 2;
        const char* p0 = (const char*)(qh + head_elem + (size_t)(qb * 128 + qrow) * 64 + qc);
#pragma unroll
        for (int c = 0; c < 4; c++)
            CP_ASYNC16(sQh + qdst + c * 16, p0 + c * 16);
        CP_COMMIT();
    }

    // K/V loader: 64 rows, thread -> row tid/4, 16-half (32-byte) chunk
    const int lrow = tid >> 2;
    const int lc   = (tid & 3) * 16;
    const uint32_t sdst = (uint32_t)(lrow * AST + lc) * 2;

    auto load_kv = [&](int stage, int kb) {
        const size_t roff = head_elem + (size_t)(kb * 64 + lrow) * 64 + lc;
        const uint32_t sb = sKV + (uint32_t)stage * (2 * ATILE_B);
        const char* p0 = (const char*)(kh + roff);
        const char* p2 = (const char*)(vh + roff);
#pragma unroll
        for (int c = 0; c < 2; c++) {
            CP_ASYNC16(sb + 0 * ATILE_B + sdst + c * 16, p0 + c * 16);
            CP_ASYNC16(sb + 1 * ATILE_B + sdst + c * 16, p2 + c * 16);
        }
        CP_COMMIT();
    };

    const int nt = 2 * qb + 2;
    load_kv(0, 0);
    load_kv(1, 1);
    CP_WAIT(1);
    __syncthreads();

    // Q fragments: warp w -> rows w*16..w*16+15
    uint32_t aQh[4][4];
    {
        const uint32_t a_ld = (uint32_t)((wid * 16 + (lane & 15)) * AST + (lane >> 4) * 8) * 2;
#pragma unroll
        for (int ks = 0; ks < 4; ks++)
            LDSM_X4(aQh[ks][0], aQh[ks][1], aQh[ks][2], aQh[ks][3], sQh + a_ld + ks * 32);
    }

    const uint32_t b_ldK = (uint32_t)(((lane & 7) + ((lane >> 4) << 3)) * AST
                                      + ((lane >> 3) & 1) * 8) * 2;
    const uint32_t v_ld  = (uint32_t)((lane & 15) * AST + ((lane >> 4) << 3)) * 2;

    float O[8][4];
#pragma unroll
    for (int t = 0; t < 8; t++)
#pragma unroll
        for (int e = 0; e < 4; e++) O[t][e] = 0.f;
    float m1 = NEG_INF, m2 = NEG_INF, l1 = 0.f, l2 = 0.f;

    const int rowg1 = qb * 128 + wid * 16 + (lane >> 2);   // global query row (e<2)
    const int colb  = (lane & 3) * 2;

    for (int kt = 0; kt < nt; kt++) {
        const uint32_t sb  = sKV + (uint32_t)(kt & 1) * (2 * ATILE_B);
        const uint32_t sKh = sb;
        const uint32_t sVh = sb + ATILE_B;

        float S[8][4];
#pragma unroll
        for (int t = 0; t < 8; t++)
#pragma unroll
            for (int e = 0; e < 4; e++) S[t][e] = 0.f;

        // ---- S = Q K^T : 1-pass
#pragma unroll
        for (int ks = 0; ks < 4; ks++) {
            uint32_t fKh[4][4];
#pragma unroll
            for (int np = 0; np < 4; np++) {
                const uint32_t off = (uint32_t)(np * 16 * AST) * 2 + ks * 32;
                LDSM_X4(fKh[np][0], fKh[np][1], fKh[np][2], fKh[np][3], sKh + b_ldK + off);
            }
#pragma unroll
            for (int np = 0; np < 4; np++) {
                uint32_t b0[2] = {fKh[np][0], fKh[np][1]};
                MMA_F16(S[2 * np], aQh[ks], b0);
            }
#pragma unroll
            for (int np = 0; np < 4; np++) {
                uint32_t b1[2] = {fKh[np][2], fKh[np][3]};
                MMA_F16(S[2 * np + 1], aQh[ks], b1);
            }
        }

        // ---- causal mask (last two tiles cross the diagonal for this CTA)
        if (kt >= nt - 2) {
#pragma unroll
            for (int t = 0; t < 8; t++) {
#pragma unroll
                for (int e = 0; e < 4; e++) {
                    const int col = kt * 64 + t * 8 + colb + (e & 1);
                    const int row = rowg1 + (e >> 1) * 8;
                    if (col > row) S[t][e] = NEG_INF;
                }
            }
        }

        // ---- online softmax
        float mx1 = NEG_INF, mx2 = NEG_INF;
#pragma unroll
        for (int t = 0; t < 8; t++) {
            mx1 = fmaxf(mx1, fmaxf(S[t][0], S[t][1]));
            mx2 = fmaxf(mx2, fmaxf(S[t][2], S[t][3]));
        }
        mx1 = fmaxf(mx1, __shfl_xor_sync(0xffffffffu, mx1, 1));
        mx1 = fmaxf(mx1, __shfl_xor_sync(0xffffffffu, mx1, 2));
        mx2 = fmaxf(mx2, __shfl_xor_sync(0xffffffffu, mx2, 1));
        mx2 = fmaxf(mx2, __shfl_xor_sync(0xffffffffu, mx2, 2));

        const float mn1 = fmaxf(m1, mx1);
        const float mn2 = fmaxf(m2, mx2);
        const float c1 = __expf(m1 - mn1);
        const float c2 = __expf(m2 - mn2);
        l1 *= c1; l2 *= c2;
#pragma unroll
        for (int t = 0; t < 8; t++) {
            O[t][0] *= c1; O[t][1] *= c1;
            O[t][2] *= c2; O[t][3] *= c2;
        }
        float rs1 = 0.f, rs2 = 0.f;
#pragma unroll
        for (int t = 0; t < 8; t++) {
            S[t][0] = __expf(S[t][0] - mn1); rs1 += S[t][0];
            S[t][1] = __expf(S[t][1] - mn1); rs1 += S[t][1];
            S[t][2] = __expf(S[t][2] - mn2); rs2 += S[t][2];
            S[t][3] = __expf(S[t][3] - mn2); rs2 += S[t][3];
        }
        rs1 += __shfl_xor_sync(0xffffffffu, rs1, 1);
        rs1 += __shfl_xor_sync(0xffffffffu, rs1, 2);
        rs2 += __shfl_xor_sync(0xffffffffu, rs2, 1);
        rs2 += __shfl_xor_sync(0xffffffffu, rs2, 2);
        l1 += rs1; l2 += rs2;
        m1 = mn1; m2 = mn2;

        // ---- O += P V : 1-pass (P hi x V hi)
#pragma unroll
        for (int ks = 0; ks < 4; ks++) {
            uint32_t aPh[4];
            aPh[0] = pack_f16(S[2 * ks][0],     S[2 * ks][1]);
            aPh[1] = pack_f16(S[2 * ks][2],     S[2 * ks][3]);
            aPh[2] = pack_f16(S[2 * ks + 1][0], S[2 * ks + 1][1]);
            aPh[3] = pack_f16(S[2 * ks + 1][2], S[2 * ks + 1][3]);
            uint32_t fVh[4][4];
#pragma unroll
            for (int np = 0; np < 4; np++) {
                const uint32_t off = (uint32_t)(ks * 16 * AST) * 2 + np * 32;
                LDSM_X4_T(fVh[np][0], fVh[np][1], fVh[np][2], fVh[np][3], sVh + v_ld + off);
            }
#pragma unroll
            for (int np = 0; np < 4; np++) {
                uint32_t b0[2] = {fVh[np][0], fVh[np][1]};
                MMA_F16(O[2 * np], aPh, b0);
            }
#pragma unroll
            for (int np = 0; np < 4; np++) {
                uint32_t b1[2] = {fVh[np][2], fVh[np][3]};
                MMA_F16(O[2 * np + 1], aPh, b1);
            }
        }

        // ---- pipeline advance
        if (kt + 1 < nt) {
            __syncthreads();
            if (kt + 2 < nt) { load_kv(kt & 1, kt + 2); CP_WAIT(1); }
            else             { CP_WAIT(0); }
            __syncthreads();
        }
    }

    // ---- epilogue: write f16 hi into (B,T,D)
    const float inv1 = 1.f / l1;
    const float inv2 = 1.f / l2;
    const size_t obase = (size_t)b * T_SEQ * D_MODEL + (size_t)h * 64;
#pragma unroll
    for (int t = 0; t < 8; t++) {
        const int d = t * 8 + colb;
        size_t i1 = obase + (size_t)rowg1 * D_MODEL + d;
        *(uint32_t*)&oh[i1] = pack_f16(O[t][0] * inv1, O[t][1] * inv1);
        size_t i2 = obase + (size_t)(rowg1 + 8) * D_MODEL + d;
        *(uint32_t*)&oh[i2] = pack_f16(O[t][2] * inv2, O[t][3] * inv2);
    }
}

// ---------------------------------------------------------------------------
extern "C" void kernel_launch(void* const* d_in, const int* in_sizes, int n_in,
                              void* d_out, int out_size)
{
    const float* x  = (const float*)d_in[0];
    const float* Wq = (const float*)d_in[1];
    const float* Wk = (const float*)d_in[2];
    const float* Wv = (const float*)d_in[3];
    const float* Wo = (const float*)d_in[4];

    float* out  = (float*)d_out;
    float* kout = out  + (size_t)M_ROWS * D_MODEL;
    float* vout = kout + (size_t)M_ROWS * D_MODEL;

    __half *xh, *wqh, *wql, *wkh, *wvh, *woh;
    __half *qhp, *khp, *vhp, *ahp;
    cudaGetSymbolAddress((void**)&xh,  g_xh);
    cudaGetSymbolAddress((void**)&wqh, g_wqh);
    cudaGetSymbolAddress((void**)&wql, g_wql);
    cudaGetSymbolAddress((void**)&wkh, g_wkh);
    cudaGetSymbolAddress((void**)&wvh, g_wvh);
    cudaGetSymbolAddress((void**)&woh, g_woh);
    cudaGetSymbolAddress((void**)&qhp, g_qh);
    cudaGetSymbolAddress((void**)&khp, g_kh);
    cudaGetSymbolAddress((void**)&vhp, g_vh);
    cudaGetSymbolAddress((void**)&ahp, g_ah);

    cudaFuncSetAttribute(gemm_f16, cudaFuncAttributeMaxDynamicSharedMemorySize,
                         GEMM_SMEM_BYTES);
    cudaFuncSetAttribute(attn_mma, cudaFuncAttributeMaxDynamicSharedMemorySize,
                         ASMEM_BYTES);

    const int nx4 = M_ROWS * D_MODEL / 4;
    const int nw4 = D_MODEL * D_MODEL / 4;

    // x + Wk + Wv + Wo -> f16 hi only (merged, grid.z=4 with per-z sizes via max)
    cvt_f16<<<(nx4 + 255) / 256, 256>>>(x, xh, nx4);
    CvtArgs ca;
    ca.src[0] = Wk; ca.hi[0] = wkh;
    ca.src[1] = Wv; ca.hi[1] = wvh;
    ca.src[2] = Wo; ca.hi[2] = woh;
    ca.src[3] = Wk; ca.hi[3] = wkh;   // unused slot (grid.z = 3)
    cvt_f16m<<<dim3((nw4 + 255) / 256, 1, 3), 256>>>(ca, nw4);
    // Wq -> hi/lo split (score path keeps exact Wq)
    split_f16w<<<(nw4 + 255) / 256, 256>>>(Wq, wqh, wql, nw4);

    // ---- merged QKV GEMM (grid.z: 0=Q 2-pass, 1=K 1-pass, 2=V 1-pass)
    GemmArgs qkv;
    qkv.Ah = xh;
    qkv.Bh[0] = wqh; qkv.Bl[0] = wql;
    qkv.Bh[1] = wkh; qkv.Bl[1] = nullptr;
    qkv.Bh[2] = wvh; qkv.Bl[2] = nullptr;
    qkv.Cf[0] = nullptr; qkv.Cf[1] = kout; qkv.Cf[2] = vout;
    qkv.Ch[0] = qhp; qkv.Cl[0] = nullptr;          // Q: hi only, pre-scaled
    qkv.Ch[1] = khp; qkv.Cl[1] = nullptr;          // K: hi only
    qkv.Ch[2] = vhp; qkv.Cl[2] = nullptr;          // V: hi only
    qkv.scale[0] = 0.125f; qkv.scale[1] = 1.f; qkv.scale[2] = 1.f;
    qkv.split = 1;
    gemm_f16<<<dim3(D_MODEL / BN, M_ROWS / BM, 3), 256, GEMM_SMEM_BYTES>>>(qkv);

    attn_mma<<<dim3(T_SEQ / 128, N_HEADS, B_SIZE), 256, ASMEM_BYTES>>>(
        qhp, khp, vhp, ahp);

    // ---- O projection: 1-pass (ah x Wo hi), fp32 output
    GemmArgs og;
    og.Ah = ahp;
    og.Bh[0] = woh; og.Bl[0] = nullptr;
    og.Cf[0] = out; og.Ch[0] = nullptr; og.Cl[0] = nullptr;
    og.scale[0] = 1.f; og.split = 0;
    og.Bh[1] = og.Bh[2] = nullptr; og.Bl[1] = og.Bl[2] = nullptr;
    og.Cf[1] = og.Cf[2] = nullptr; og.Ch[1] = og.Ch[2] = nullptr;
    og.Cl[1] = og.Cl[2] = nullptr; og.scale[1] = og.scale[2] = 1.f;
    gemm_f16<<<dim3(D_MODEL / BN, M_ROWS / BM, 1), 256, GEMM_SMEM_BYTES>>>(og);
}

// round 12
// speedup vs baseline: 7.4019x; 1.0349x over previous
#include <cuda_runtime.h>
#include <cuda_fp16.h>
#include <cstdint>
#include <math.h>

#define D_MODEL  1024
#define N_HEADS  16
#define HEAD_DIM 64
#define B_SIZE   4
#define T_SEQ    2048
#define M_ROWS   (B_SIZE * T_SEQ)   // 8192
#define KDIM     1024

#define NEG_INF  (__int_as_float(0xff800000))

// ---------------------------------------------------------------------------
// Scratch (device globals: no allocations allowed)
// ---------------------------------------------------------------------------
__device__ __half g_xh[(size_t)M_ROWS * D_MODEL];
__device__ __half g_wqh[(size_t)D_MODEL * D_MODEL];
__device__ __half g_wkh[(size_t)D_MODEL * D_MODEL];
__device__ __half g_wvh[(size_t)D_MODEL * D_MODEL];
__device__ __half g_woh[(size_t)D_MODEL * D_MODEL];

__device__ __half g_qh[(size_t)M_ROWS * D_MODEL];   // (B,H,T,hd), pre-scaled
__device__ __half g_kh[(size_t)M_ROWS * D_MODEL];
__device__ __half g_vh[(size_t)M_ROWS * D_MODEL];
__device__ __half g_ah[(size_t)M_ROWS * D_MODEL];   // attn out (B,T,D)

// ---------------------------------------------------------------------------
// PTX helpers (base ISA only)
// ---------------------------------------------------------------------------
__device__ __forceinline__ uint32_t smem_to_u32(const void* p) {
    uint32_t a;
    asm("{ .reg .u64 t; cvta.to.shared.u64 t, %1; cvt.u32.u64 %0, t; }"
        : "=r"(a) : "l"(p));
    return a;
}

#define CP_ASYNC16(dst, src) \
    asm volatile("cp.async.cg.shared.global [%0], [%1], 16;" :: "r"(dst), "l"(src))
#define CP_COMMIT() asm volatile("cp.async.commit_group;" ::: "memory")
#define CP_WAIT(n)  asm volatile("cp.async.wait_group %0;" :: "n"(n) : "memory")

#define LDSM_X4(r0, r1, r2, r3, addr) \
    asm volatile("ldmatrix.sync.aligned.m8n8.x4.shared.b16 {%0,%1,%2,%3}, [%4];" \
                 : "=r"(r0), "=r"(r1), "=r"(r2), "=r"(r3) : "r"(addr))
#define LDSM_X4_T(r0, r1, r2, r3, addr) \
    asm volatile("ldmatrix.sync.aligned.m8n8.x4.trans.shared.b16 {%0,%1,%2,%3}, [%4];" \
                 : "=r"(r0), "=r"(r1), "=r"(r2), "=r"(r3) : "r"(addr))

#define MMA_F16(c, a, b) \
    asm volatile("mma.sync.aligned.m16n8k16.row.col.f32.f16.f16.f32 " \
                 "{%0,%1,%2,%3}, {%4,%5,%6,%7}, {%8,%9}, {%0,%1,%2,%3};" \
                 : "+f"((c)[0]), "+f"((c)[1]), "+f"((c)[2]), "+f"((c)[3]) \
                 : "r"((a)[0]), "r"((a)[1]), "r"((a)[2]), "r"((a)[3]), \
                   "r"((b)[0]), "r"((b)[1]))

// pack two fp32 -> f16x2 reg: low half = x, high half = y
__device__ __forceinline__ uint32_t pack_f16(float x, float y) {
    uint32_t r;
    asm("cvt.rn.f16x2.f32 %0, %1, %2;" : "=r"(r) : "f"(y), "f"(x));
    return r;
}

// ---------------------------------------------------------------------------
// fp32 -> f16 converters
// ---------------------------------------------------------------------------
__global__ void __launch_bounds__(256) cvt_f16(const float* __restrict__ x,
                                               __half* __restrict__ hi, int n4)
{
    int i = blockIdx.x * blockDim.x + threadIdx.x;
    if (i >= n4) return;
    float4 v = ((const float4*)x)[i];
    ((uint32_t*)hi)[i * 2 + 0] = pack_f16(v.x, v.y);
    ((uint32_t*)hi)[i * 2 + 1] = pack_f16(v.z, v.w);
}

struct CvtArgs {
    const float* src[4];
    __half* hi[4];
};
__global__ void __launch_bounds__(256) cvt_f16m(const CvtArgs a, int n4)
{
    const int z = blockIdx.z;
    const float* x = a.src[z];
    __half* hi = a.hi[z];
    int i = blockIdx.x * blockDim.x + threadIdx.x;
    if (i >= n4) return;
    float4 v = ((const float4*)x)[i];
    ((uint32_t*)hi)[i * 2 + 0] = pack_f16(v.x, v.y);
    ((uint32_t*)hi)[i * 2 + 1] = pack_f16(v.z, v.w);
}

// ---------------------------------------------------------------------------
// mma.sync 1-pass f16 GEMM:  C(8192x1024) = A @ W^T
// 3-stage cp.async pipeline, one barrier per K-iter. grid.z picks slice.
// ---------------------------------------------------------------------------
#define BM 128
#define BN 128
#define BK 32
#define NKI (KDIM / BK)          // 32
#define SKP 40                   // smem row stride in f16
#define TILE_B (BM * SKP * 2)    // 10240 bytes per tile
#define STAGE_B (2 * TILE_B)     // Ah, Bh
#define GEMM_SMEM_BYTES (3 * STAGE_B)

struct GemmArgs {
    const __half* Ah;
    const __half* Bh[3];
    float*  Cf[3];
    __half* Ch[3];
    float   scale[3];
    int     split;      // 1 -> (B,H,T,hd) output layout
};

__global__ void __launch_bounds__(256) gemm_f16(const GemmArgs args)
{
    extern __shared__ char smem_raw[];
    const uint32_t smem = smem_to_u32(smem_raw);

    const int z = blockIdx.z;
    const __half* Ah = args.Ah;
    const __half* Bh = args.Bh[z];

    const int tid  = threadIdx.x;
    const int wid  = tid >> 5;
    const int lane = tid & 31;
    const int row0 = blockIdx.y * BM;
    const int col0 = blockIdx.x * BN;

    const int m0 = (wid & 1) * 64;
    const int n0 = (wid >> 1) * 32;

    const int lrow   = tid >> 1;
    const int lcol16 = (tid & 1) * 16;
    const size_t a_goff = (size_t)(row0 + lrow) * KDIM + lcol16;
    const size_t b_goff = (size_t)(col0 + lrow) * KDIM + lcol16;
    const uint32_t sdst0 = (uint32_t)(lrow * SKP + lcol16) * 2;

    auto load_stage = [&](int stage, int kt) {
        const uint32_t sb = smem + (uint32_t)stage * STAGE_B;
        const size_t ko = (size_t)kt * BK;
        const char* s0 = (const char*)(Ah + a_goff + ko);
        const char* s2 = (const char*)(Bh + b_goff + ko);
#pragma unroll
        for (int c = 0; c < 2; c++) {
            CP_ASYNC16(sb + 0 * TILE_B + sdst0 + c * 16, s0 + c * 16);
            CP_ASYNC16(sb + 1 * TILE_B + sdst0 + c * 16, s2 + c * 16);
        }
        CP_COMMIT();
    };

    const uint32_t a_ld = (uint32_t)((m0 + (lane & 15)) * SKP + (lane >> 4) * 8) * 2;
    const uint32_t b_ld = (uint32_t)((n0 + (lane & 7) + ((lane >> 4) << 3)) * SKP
                                     + (((lane >> 3) & 1) << 3)) * 2;

    float acc[4][4][4];
#pragma unroll
    for (int i = 0; i < 4; i++)
#pragma unroll
        for (int j = 0; j < 4; j++)
#pragma unroll
            for (int r = 0; r < 4; r++) acc[i][j][r] = 0.f;

    load_stage(0, 0);
    load_stage(1, 1);

    for (int kt = 0; kt < NKI; kt++) {
        if (kt + 1 < NKI) { CP_WAIT(1); } else { CP_WAIT(0); }
        __syncthreads();
        if (kt + 2 < NKI) load_stage((kt + 2) % 3, kt + 2);

        const uint32_t sb  = smem + (uint32_t)(kt % 3) * STAGE_B;
        const uint32_t sAh = sb + 0 * TILE_B;
        const uint32_t sBh = sb + 1 * TILE_B;

#pragma unroll
        for (int ks = 0; ks < 2; ks++) {
            const uint32_t kso = (uint32_t)(ks * 16) * 2;
            uint32_t fAh[4][4];
            uint32_t fBh[4][2];
#pragma unroll
            for (int am = 0; am < 4; am++) {
                const uint32_t off = (uint32_t)(am * 16 * SKP) * 2 + kso;
                LDSM_X4(fAh[am][0], fAh[am][1], fAh[am][2], fAh[am][3], sAh + a_ld + off);
            }
#pragma unroll
            for (int bp = 0; bp < 2; bp++) {
                const uint32_t off = (uint32_t)(bp * 16 * SKP) * 2 + kso;
                LDSM_X4(fBh[2 * bp][0], fBh[2 * bp][1], fBh[2 * bp + 1][0], fBh[2 * bp + 1][1],
                        sBh + b_ld + off);
            }
#pragma unroll
            for (int am = 0; am < 4; am++)
#pragma unroll
                for (int na = 0; na < 4; na++)
                    MMA_F16(acc[am][na], fAh[am], fBh[na]);
        }
    }

    float* Cf = args.Cf[z];
    __half* Ch = args.Ch[z];
    const float scale = args.scale[z];
    const int split = args.split;

    const int lr4 = lane >> 2;
    const int lc2 = (lane & 3) * 2;
#pragma unroll
    for (int am = 0; am < 4; am++) {
        const int mA = row0 + m0 + am * 16 + lr4;
#pragma unroll
        for (int na = 0; na < 4; na++) {
            const int n = col0 + n0 + na * 8 + lc2;
#pragma unroll
            for (int half_ = 0; half_ < 2; half_++) {
                const int m = mA + half_ * 8;
                float vx = acc[am][na][half_ * 2 + 0] * scale;
                float vy = acc[am][na][half_ * 2 + 1] * scale;
                size_t idx;
                if (split) {
                    const int bb = m >> 11, t = m & 2047;
                    const int hh = n >> 6, d = n & 63;
                    idx = (((size_t)bb * N_HEADS + hh) * T_SEQ + t) * HEAD_DIM + d;
                } else {
                    idx = (size_t)m * D_MODEL + n;
                }
                if (Cf) *(float2*)&Cf[idx] = make_float2(vx, vy);
                if (Ch) *(uint32_t*)&Ch[idx] = pack_f16(vx, vy);
            }
        }
    }
}

// ---------------------------------------------------------------------------
// mma.sync flash attention, causal. BQ=128 (8 warps x m16), BKV=64, 256 thr.
// All products 1-pass f16.  Output: f16, (B,T,D).
// ---------------------------------------------------------------------------
#define AST 72                        // smem row stride (f16 elems)
#define ATILE_B (64 * AST * 2)        // 9216 bytes (64-row K/V tile)
#define QTILE_B (128 * AST * 2)       // 18432 bytes (128-row Q tile)
#define ASMEM_BYTES (QTILE_B + 4 * ATILE_B)   // Q + 2 stages x {Kh,Vh}

__global__ void __launch_bounds__(256, 2) attn_mma(
    const __half* __restrict__ qh,
    const __half* __restrict__ kh,
    const __half* __restrict__ vh,
    __half* __restrict__ oh)
{
    extern __shared__ char smem_raw[];
    const uint32_t smem = smem_to_u32(smem_raw);
    const uint32_t sQh = smem;
    const uint32_t sKV = smem + QTILE_B;

    const int tid  = threadIdx.x;
    const int wid  = tid >> 5;
    const int lane = tid & 31;
    const int qb = gridDim.x - 1 - blockIdx.x;   // heaviest tiles first
    const int h = blockIdx.y, b = blockIdx.z;
    const size_t head_elem = ((size_t)b * N_HEADS + h) * T_SEQ * HEAD_DIM;

    { // Q tile loader: 128 rows, thread -> row tid/2, 32-half chunk
        const int qrow = tid >> 1;
        const int qc   = (tid & 1) * 32;
        const uint32_t qdst = (uint32_t)(qrow * AST + qc) * 2;
        const char* p0 = (const char*)(qh + head_elem + (size_t)(qb * 128 + qrow) * 64 + qc);
#pragma unroll
        for (int c = 0; c < 4; c++)
            CP_ASYNC16(sQh + qdst + c * 16, p0 + c * 16);
        CP_COMMIT();
    }

    // K/V loader: 64 rows, thread -> row tid/4, 16-half (32-byte) chunk
    const int lrow = tid >> 2;
    const int lc   = (tid & 3) * 16;
    const uint32_t sdst = (uint32_t)(lrow * AST + lc) * 2;

    auto load_kv = [&](int stage, int kb) {
        const size_t roff = head_elem + (size_t)(kb * 64 + lrow) * 64 + lc;
        const uint32_t sb = sKV + (uint32_t)stage * (2 * ATILE_B);
        const char* p0 = (const char*)(kh + roff);
        const char* p2 = (const char*)(vh + roff);
#pragma unroll
        for (int c = 0; c < 2; c++) {
            CP_ASYNC16(sb + 0 * ATILE_B + sdst + c * 16, p0 + c * 16);
            CP_ASYNC16(sb + 1 * ATILE_B + sdst + c * 16, p2 + c * 16);
        }
        CP_COMMIT();
    };

    const int nt = 2 * qb + 2;
    load_kv(0, 0);
    load_kv(1, 1);
    CP_WAIT(1);
    __syncthreads();

    // Q fragments: warp w -> rows w*16..w*16+15
    uint32_t aQh[4][4];
    {
        const uint32_t a_ld = (uint32_t)((wid * 16 + (lane & 15)) * AST + (lane >> 4) * 8) * 2;
#pragma unroll
        for (int ks = 0; ks < 4; ks++)
            LDSM_X4(aQh[ks][0], aQh[ks][1], aQh[ks][2], aQh[ks][3], sQh + a_ld + ks * 32);
    }

    const uint32_t b_ldK = (uint32_t)(((lane & 7) + ((lane >> 4) << 3)) * AST
                                      + ((lane >> 3) & 1) * 8) * 2;
    const uint32_t v_ld  = (uint32_t)((lane & 15) * AST + ((lane >> 4) << 3)) * 2;

    float O[8][4];
#pragma unroll
    for (int t = 0; t < 8; t++)
#pragma unroll
        for (int e = 0; e < 4; e++) O[t][e] = 0.f;
    float m1 = NEG_INF, m2 = NEG_INF, l1 = 0.f, l2 = 0.f;

    const int rowg1 = qb * 128 + wid * 16 + (lane >> 2);   // global query row (e<2)
    const int colb  = (lane & 3) * 2;

    for (int kt = 0; kt < nt; kt++) {
        const uint32_t sb  = sKV + (uint32_t)(kt & 1) * (2 * ATILE_B);
        const uint32_t sKh = sb;
        const uint32_t sVh = sb + ATILE_B;

        float S[8][4];
#pragma unroll
        for (int t = 0; t < 8; t++)
#pragma unroll
            for (int e = 0; e < 4; e++) S[t][e] = 0.f;

        // ---- S = Q K^T : 1-pass
#pragma unroll
        for (int ks = 0; ks < 4; ks++) {
            uint32_t fKh[4][4];
#pragma unroll
            for (int np = 0; np < 4; np++) {
                const uint32_t off = (uint32_t)(np * 16 * AST) * 2 + ks * 32;
                LDSM_X4(fKh[np][0], fKh[np][1], fKh[np][2], fKh[np][3], sKh + b_ldK + off);
            }
#pragma unroll
            for (int np = 0; np < 4; np++) {
                uint32_t b0[2] = {fKh[np][0], fKh[np][1]};
                MMA_F16(S[2 * np], aQh[ks], b0);
            }
#pragma unroll
            for (int np = 0; np < 4; np++) {
                uint32_t b1[2] = {fKh[np][2], fKh[np][3]};
                MMA_F16(S[2 * np + 1], aQh[ks], b1);
            }
        }

        // ---- causal mask (last two tiles cross the diagonal for this CTA)
        if (kt >= nt - 2) {
#pragma unroll
            for (int t = 0; t < 8; t++) {
#pragma unroll
                for (int e = 0; e < 4; e++) {
                    const int col = kt * 64 + t * 8 + colb + (e & 1);
                    const int row = rowg1 + (e >> 1) * 8;
                    if (col > row) S[t][e] = NEG_INF;
                }
            }
        }

        // ---- online softmax
        float mx1 = NEG_INF, mx2 = NEG_INF;
#pragma unroll
        for (int t = 0; t < 8; t++) {
            mx1 = fmaxf(mx1, fmaxf(S[t][0], S[t][1]));
            mx2 = fmaxf(mx2, fmaxf(S[t][2], S[t][3]));
        }
        mx1 = fmaxf(mx1, __shfl_xor_sync(0xffffffffu, mx1, 1));
        mx1 = fmaxf(mx1, __shfl_xor_sync(0xffffffffu, mx1, 2));
        mx2 = fmaxf(mx2, __shfl_xor_sync(0xffffffffu, mx2, 1));
        mx2 = fmaxf(mx2, __shfl_xor_sync(0xffffffffu, mx2, 2));

        const float mn1 = fmaxf(m1, mx1);
        const float mn2 = fmaxf(m2, mx2);
        const float c1 = __expf(m1 - mn1);
        const float c2 = __expf(m2 - mn2);
        l1 *= c1; l2 *= c2;
#pragma unroll
        for (int t = 0; t < 8; t++) {
            O[t][0] *= c1; O[t][1] *= c1;
            O[t][2] *= c2; O[t][3] *= c2;
        }
        float rs1 = 0.f, rs2 = 0.f;
#pragma unroll
        for (int t = 0; t < 8; t++) {
            S[t][0] = __expf(S[t][0] - mn1); rs1 += S[t][0];
            S[t][1] = __expf(S[t][1] - mn1); rs1 += S[t][1];
            S[t][2] = __expf(S[t][2] - mn2); rs2 += S[t][2];
            S[t][3] = __expf(S[t][3] - mn2); rs2 += S[t][3];
        }
        rs1 += __shfl_xor_sync(0xffffffffu, rs1, 1);
        rs1 += __shfl_xor_sync(0xffffffffu, rs1, 2);
        rs2 += __shfl_xor_sync(0xffffffffu, rs2, 1);
        rs2 += __shfl_xor_sync(0xffffffffu, rs2, 2);
        l1 += rs1; l2 += rs2;
        m1 = mn1; m2 = mn2;

        // ---- O += P V : 1-pass (P hi x V hi)
#pragma unroll
        for (int ks = 0; ks < 4; ks++) {
            uint32_t aPh[4];
            aPh[0] = pack_f16(S[2 * ks][0],     S[2 * ks][1]);
            aPh[1] = pack_f16(S[2 * ks][2],     S[2 * ks][3]);
            aPh[2] = pack_f16(S[2 * ks + 1][0], S[2 * ks + 1][1]);
            aPh[3] = pack_f16(S[2 * ks + 1][2], S[2 * ks + 1][3]);
            uint32_t fVh[4][4];
#pragma unroll
            for (int np = 0; np < 4; np++) {
                const uint32_t off = (uint32_t)(ks * 16 * AST) * 2 + np * 32;
                LDSM_X4_T(fVh[np][0], fVh[np][1], fVh[np][2], fVh[np][3], sVh + v_ld + off);
            }
#pragma unroll
            for (int np = 0; np < 4; np++) {
                uint32_t b0[2] = {fVh[np][0], fVh[np][1]};
                MMA_F16(O[2 * np], aPh, b0);
            }
#pragma unroll
            for (int np = 0; np < 4; np++) {
                uint32_t b1[2] = {fVh[np][2], fVh[np][3]};
                MMA_F16(O[2 * np + 1], aPh, b1);
            }
        }

        // ---- pipeline advance
        if (kt + 1 < nt) {
            __syncthreads();
            if (kt + 2 < nt) { load_kv(kt & 1, kt + 2); CP_WAIT(1); }
            else             { CP_WAIT(0); }
            __syncthreads();
        }
    }

    // ---- epilogue: write f16 into (B,T,D)
    const float inv1 = 1.f / l1;
    const float inv2 = 1.f / l2;
    const size_t obase = (size_t)b * T_SEQ * D_MODEL + (size_t)h * 64;
#pragma unroll
    for (int t = 0; t < 8; t++) {
        const int d = t * 8 + colb;
        size_t i1 = obase + (size_t)rowg1 * D_MODEL + d;
        *(uint32_t*)&oh[i1] = pack_f16(O[t][0] * inv1, O[t][1] * inv1);
        size_t i2 = obase + (size_t)(rowg1 + 8) * D_MODEL + d;
        *(uint32_t*)&oh[i2] = pack_f16(O[t][2] * inv2, O[t][3] * inv2);
    }
}

// ---------------------------------------------------------------------------
extern "C" void kernel_launch(void* const* d_in, const int* in_sizes, int n_in,
                              void* d_out, int out_size)
{
    const float* x  = (const float*)d_in[0];
    const float* Wq = (const float*)d_in[1];
    const float* Wk = (const float*)d_in[2];
    const float* Wv = (const float*)d_in[3];
    const float* Wo = (const float*)d_in[4];

    float* out  = (float*)d_out;
    float* kout = out  + (size_t)M_ROWS * D_MODEL;
    float* vout = kout + (size_t)M_ROWS * D_MODEL;

    __half *xh, *wqh, *wkh, *wvh, *woh;
    __half *qhp, *khp, *vhp, *ahp;
    cudaGetSymbolAddress((void**)&xh,  g_xh);
    cudaGetSymbolAddress((void**)&wqh, g_wqh);
    cudaGetSymbolAddress((void**)&wkh, g_wkh);
    cudaGetSymbolAddress((void**)&wvh, g_wvh);
    cudaGetSymbolAddress((void**)&woh, g_woh);
    cudaGetSymbolAddress((void**)&qhp, g_qh);
    cudaGetSymbolAddress((void**)&khp, g_kh);
    cudaGetSymbolAddress((void**)&vhp, g_vh);
    cudaGetSymbolAddress((void**)&ahp, g_ah);

    cudaFuncSetAttribute(gemm_f16, cudaFuncAttributeMaxDynamicSharedMemorySize,
                         GEMM_SMEM_BYTES);
    cudaFuncSetAttribute(attn_mma, cudaFuncAttributeMaxDynamicSharedMemorySize,
                         ASMEM_BYTES);

    const int nx4 = M_ROWS * D_MODEL / 4;
    const int nw4 = D_MODEL * D_MODEL / 4;

    cvt_f16<<<(nx4 + 255) / 256, 256>>>(x, xh, nx4);
    CvtArgs ca;
    ca.src[0] = Wq; ca.hi[0] = wqh;
    ca.src[1] = Wk; ca.hi[1] = wkh;
    ca.src[2] = Wv; ca.hi[2] = wvh;
    ca.src[3] = Wo; ca.hi[3] = woh;
    cvt_f16m<<<dim3((nw4 + 255) / 256, 1, 4), 256>>>(ca, nw4);

    // ---- merged QKV GEMM (grid.z: 0=Q, 1=K, 2=V; all 1-pass)
    GemmArgs qkv;
    qkv.Ah = xh;
    qkv.Bh[0] = wqh;
    qkv.Bh[1] = wkh;
    qkv.Bh[2] = wvh;
    qkv.Cf[0] = nullptr; qkv.Cf[1] = kout; qkv.Cf[2] = vout;
    qkv.Ch[0] = qhp;     qkv.Ch[1] = khp;  qkv.Ch[2] = vhp;
    qkv.scale[0] = 0.125f; qkv.scale[1] = 1.f; qkv.scale[2] = 1.f;
    qkv.split = 1;
    gemm_f16<<<dim3(D_MODEL / BN, M_ROWS / BM, 3), 256, GEMM_SMEM_BYTES>>>(qkv);

    attn_mma<<<dim3(T_SEQ / 128, N_HEADS, B_SIZE), 256, ASMEM_BYTES>>>(
        qhp, khp, vhp, ahp);

    // ---- O projection: 1-pass, fp32 output
    GemmArgs og;
    og.Ah = ahp;
    og.Bh[0] = woh;
    og.Cf[0] = out; og.Ch[0] = nullptr;
    og.scale[0] = 1.f; og.split = 0;
    og.Bh[1] = og.Bh[2] = nullptr;
    og.Cf[1] = og.Cf[2] = nullptr; og.Ch[1] = og.Ch[2] = nullptr;
    og.scale[1] = og.scale[2] = 1.f;
    gemm_f16<<<dim3(D_MODEL / BN, M_ROWS / BM, 1), 256, GEMM_SMEM_BYTES>>>(og);
}

// round 13
// speedup vs baseline: 7.7444x; 1.0463x over previous
#include <cuda_runtime.h>
#include <cuda_fp16.h>
#include <cstdint>
#include <math.h>

#define D_MODEL  1024
#define N_HEADS  16
#define HEAD_DIM 64
#define B_SIZE   4
#define T_SEQ    2048
#define M_ROWS   (B_SIZE * T_SEQ)   // 8192
#define KDIM     1024

#define NEG_INF  (__int_as_float(0xff800000))

// ---------------------------------------------------------------------------
// Scratch (device globals: no allocations allowed)
// ---------------------------------------------------------------------------
__device__ __half g_xh[(size_t)M_ROWS * D_MODEL];
__device__ __half g_wqh[(size_t)D_MODEL * D_MODEL];
__device__ __half g_wkh[(size_t)D_MODEL * D_MODEL];
__device__ __half g_wvh[(size_t)D_MODEL * D_MODEL];
__device__ __half g_woh[(size_t)D_MODEL * D_MODEL];

__device__ __half g_qh[(size_t)M_ROWS * D_MODEL];   // (B,H,T,hd), pre-scaled by 0.125*log2e
__device__ __half g_kh[(size_t)M_ROWS * D_MODEL];
__device__ __half g_vh[(size_t)M_ROWS * D_MODEL];
__device__ __half g_ah[(size_t)M_ROWS * D_MODEL];   // attn out (B,T,D)

// ---------------------------------------------------------------------------
// PTX helpers (base ISA only)
// ---------------------------------------------------------------------------
__device__ __forceinline__ uint32_t smem_to_u32(const void* p) {
    uint32_t a;
    asm("{ .reg .u64 t; cvta.to.shared.u64 t, %1; cvt.u32.u64 %0, t; }"
        : "=r"(a) : "l"(p));
    return a;
}

#define CP_ASYNC16(dst, src) \
    asm volatile("cp.async.cg.shared.global [%0], [%1], 16;" :: "r"(dst), "l"(src))
#define CP_COMMIT() asm volatile("cp.async.commit_group;" ::: "memory")
#define CP_WAIT(n)  asm volatile("cp.async.wait_group %0;" :: "n"(n) : "memory")

#define LDSM_X4(r0, r1, r2, r3, addr) \
    asm volatile("ldmatrix.sync.aligned.m8n8.x4.shared.b16 {%0,%1,%2,%3}, [%4];" \
                 : "=r"(r0), "=r"(r1), "=r"(r2), "=r"(r3) : "r"(addr))
#define LDSM_X4_T(r0, r1, r2, r3, addr) \
    asm volatile("ldmatrix.sync.aligned.m8n8.x4.trans.shared.b16 {%0,%1,%2,%3}, [%4];" \
                 : "=r"(r0), "=r"(r1), "=r"(r2), "=r"(r3) : "r"(addr))

#define MMA_F16(c, a, b) \
    asm volatile("mma.sync.aligned.m16n8k16.row.col.f32.f16.f16.f32 " \
                 "{%0,%1,%2,%3}, {%4,%5,%6,%7}, {%8,%9}, {%0,%1,%2,%3};" \
                 : "+f"((c)[0]), "+f"((c)[1]), "+f"((c)[2]), "+f"((c)[3]) \
                 : "r"((a)[0]), "r"((a)[1]), "r"((a)[2]), "r"((a)[3]), \
                   "r"((b)[0]), "r"((b)[1]))

// pack two fp32 -> f16x2 reg: low half = x, high half = y
__device__ __forceinline__ uint32_t pack_f16(float x, float y) {
    uint32_t r;
    asm("cvt.rn.f16x2.f32 %0, %1, %2;" : "=r"(r) : "f"(y), "f"(x));
    return r;
}
// hardware exp2 (same unit __expf lowers to, minus the log2e FMUL)
__device__ __forceinline__ float ex2(float x) {
    float r;
    asm("ex2.approx.ftz.f32 %0, %1;" : "=f"(r) : "f"(x));
    return r;
}

// ---------------------------------------------------------------------------
// fp32 -> f16 converters
// ---------------------------------------------------------------------------
__global__ void __launch_bounds__(256) cvt_f16(const float* __restrict__ x,
                                               __half* __restrict__ hi, int n4)
{
    int i = blockIdx.x * blockDim.x + threadIdx.x;
    if (i >= n4) return;
    float4 v = ((const float4*)x)[i];
    ((uint32_t*)hi)[i * 2 + 0] = pack_f16(v.x, v.y);
    ((uint32_t*)hi)[i * 2 + 1] = pack_f16(v.z, v.w);
}

struct CvtArgs {
    const float* src[4];
    __half* hi[4];
};
__global__ void __launch_bounds__(256) cvt_f16m(const CvtArgs a, int n4)
{
    const int z = blockIdx.z;
    const float* x = a.src[z];
    __half* hi = a.hi[z];
    int i = blockIdx.x * blockDim.x + threadIdx.x;
    if (i >= n4) return;
    float4 v = ((const float4*)x)[i];
    ((uint32_t*)hi)[i * 2 + 0] = pack_f16(v.x, v.y);
    ((uint32_t*)hi)[i * 2 + 1] = pack_f16(v.z, v.w);
}

// ---------------------------------------------------------------------------
// mma.sync 1-pass f16 GEMM:  C(8192x1024) = A @ W^T   (unchanged from R12)
// ---------------------------------------------------------------------------
#define BM 128
#define BN 128
#define BK 32
#define NKI (KDIM / BK)          // 32
#define SKP 40                   // smem row stride in f16
#define TILE_B (BM * SKP * 2)    // 10240 bytes per tile
#define STAGE_B (2 * TILE_B)     // Ah, Bh
#define GEMM_SMEM_BYTES (3 * STAGE_B)

struct GemmArgs {
    const __half* Ah;
    const __half* Bh[3];
    float*  Cf[3];
    __half* Ch[3];
    float   scale[3];
    int     split;      // 1 -> (B,H,T,hd) output layout
};

__global__ void __launch_bounds__(256) gemm_f16(const GemmArgs args)
{
    extern __shared__ char smem_raw[];
    const uint32_t smem = smem_to_u32(smem_raw);

    const int z = blockIdx.z;
    const __half* Ah = args.Ah;
    const __half* Bh = args.Bh[z];

    const int tid  = threadIdx.x;
    const int wid  = tid >> 5;
    const int lane = tid & 31;
    const int row0 = blockIdx.y * BM;
    const int col0 = blockIdx.x * BN;

    const int m0 = (wid & 1) * 64;
    const int n0 = (wid >> 1) * 32;

    const int lrow   = tid >> 1;
    const int lcol16 = (tid & 1) * 16;
    const size_t a_goff = (size_t)(row0 + lrow) * KDIM + lcol16;
    const size_t b_goff = (size_t)(col0 + lrow) * KDIM + lcol16;
    const uint32_t sdst0 = (uint32_t)(lrow * SKP + lcol16) * 2;

    auto load_stage = [&](int stage, int kt) {
        const uint32_t sb = smem + (uint32_t)stage * STAGE_B;
        const size_t ko = (size_t)kt * BK;
        const char* s0 = (const char*)(Ah + a_goff + ko);
        const char* s2 = (const char*)(Bh + b_goff + ko);
#pragma unroll
        for (int c = 0; c < 2; c++) {
            CP_ASYNC16(sb + 0 * TILE_B + sdst0 + c * 16, s0 + c * 16);
            CP_ASYNC16(sb + 1 * TILE_B + sdst0 + c * 16, s2 + c * 16);
        }
        CP_COMMIT();
    };

    const uint32_t a_ld = (uint32_t)((m0 + (lane & 15)) * SKP + (lane >> 4) * 8) * 2;
    const uint32_t b_ld = (uint32_t)((n0 + (lane & 7) + ((lane >> 4) << 3)) * SKP
                                     + (((lane >> 3) & 1) << 3)) * 2;

    float acc[4][4][4];
#pragma unroll
    for (int i = 0; i < 4; i++)
#pragma unroll
        for (int j = 0; j < 4; j++)
#pragma unroll
            for (int r = 0; r < 4; r++) acc[i][j][r] = 0.f;

    load_stage(0, 0);
    load_stage(1, 1);

    for (int kt = 0; kt < NKI; kt++) {
        if (kt + 1 < NKI) { CP_WAIT(1); } else { CP_WAIT(0); }
        __syncthreads();
        if (kt + 2 < NKI) load_stage((kt + 2) % 3, kt + 2);

        const uint32_t sb  = smem + (uint32_t)(kt % 3) * STAGE_B;
        const uint32_t sAh = sb + 0 * TILE_B;
        const uint32_t sBh = sb + 1 * TILE_B;

#pragma unroll
        for (int ks = 0; ks < 2; ks++) {
            const uint32_t kso = (uint32_t)(ks * 16) * 2;
            uint32_t fAh[4][4];
            uint32_t fBh[4][2];
#pragma unroll
            for (int am = 0; am < 4; am++) {
                const uint32_t off = (uint32_t)(am * 16 * SKP) * 2 + kso;
                LDSM_X4(fAh[am][0], fAh[am][1], fAh[am][2], fAh[am][3], sAh + a_ld + off);
            }
#pragma unroll
            for (int bp = 0; bp < 2; bp++) {
                const uint32_t off = (uint32_t)(bp * 16 * SKP) * 2 + kso;
                LDSM_X4(fBh[2 * bp][0], fBh[2 * bp][1], fBh[2 * bp + 1][0], fBh[2 * bp + 1][1],
                        sBh + b_ld + off);
            }
#pragma unroll
            for (int am = 0; am < 4; am++)
#pragma unroll
                for (int na = 0; na < 4; na++)
                    MMA_F16(acc[am][na], fAh[am], fBh[na]);
        }
    }

    float* Cf = args.Cf[z];
    __half* Ch = args.Ch[z];
    const float scale = args.scale[z];
    const int split = args.split;

    const int lr4 = lane >> 2;
    const int lc2 = (lane & 3) * 2;
#pragma unroll
    for (int am = 0; am < 4; am++) {
        const int mA = row0 + m0 + am * 16 + lr4;
#pragma unroll
        for (int na = 0; na < 4; na++) {
            const int n = col0 + n0 + na * 8 + lc2;
#pragma unroll
            for (int half_ = 0; half_ < 2; half_++) {
                const int m = mA + half_ * 8;
                float vx = acc[am][na][half_ * 2 + 0] * scale;
                float vy = acc[am][na][half_ * 2 + 1] * scale;
                size_t idx;
                if (split) {
                    const int bb = m >> 11, t = m & 2047;
                    const int hh = n >> 6, d = n & 63;
                    idx = (((size_t)bb * N_HEADS + hh) * T_SEQ + t) * HEAD_DIM + d;
                } else {
                    idx = (size_t)m * D_MODEL + n;
                }
                if (Cf) *(float2*)&Cf[idx] = make_float2(vx, vy);
                if (Ch) *(uint32_t*)&Ch[idx] = pack_f16(vx, vy);
            }
        }
    }
}

// ---------------------------------------------------------------------------
// mma.sync flash attention, causal. BQ=128 (8 warps x m16), BKV=64, 256 thr.
// Softmax in exp2 domain (q pre-scaled by 0.125*log2e).
// 3-stage K/V pipeline, ONE barrier per tile.
// ---------------------------------------------------------------------------
#define AST 72                        // smem row stride (f16 elems)
#define ATILE_B (64 * AST * 2)        // 9216 bytes (64-row K/V tile)
#define QTILE_B (128 * AST * 2)       // 18432 bytes (128-row Q tile)
#define ASMEM_BYTES (QTILE_B + 6 * ATILE_B)   // Q + 3 stages x {Kh,Vh}

__global__ void __launch_bounds__(256, 2) attn_mma(
    const __half* __restrict__ qh,
    const __half* __restrict__ kh,
    const __half* __restrict__ vh,
    __half* __restrict__ oh)
{
    extern __shared__ char smem_raw[];
    const uint32_t smem = smem_to_u32(smem_raw);
    const uint32_t sQh = smem;
    const uint32_t sKV = smem + QTILE_B;

    const int tid  = threadIdx.x;
    const int wid  = tid >> 5;
    const int lane = tid & 31;
    const int qb = gridDim.x - 1 - blockIdx.x;   // heaviest tiles first
    const int h = blockIdx.y, b = blockIdx.z;
    const size_t head_elem = ((size_t)b * N_HEADS + h) * T_SEQ * HEAD_DIM;

    { // Q tile loader: 128 rows, thread -> row tid/2, 32-half chunk
        const int qrow = tid >> 1;
        const int qc   = (tid & 1) * 32;
        const uint32_t qdst = (uint32_t)(qrow * AST + qc) * 2;
        const char* p0 = (const char*)(qh + head_elem + (size_t)(qb * 128 + qrow) * 64 + qc);
#pragma unroll
        for (int c = 0; c < 4; c++)
            CP_ASYNC16(sQh + qdst + c * 16, p0 + c * 16);
        CP_COMMIT();
    }

    // K/V loader: 64 rows, thread -> row tid/4, 16-half (32-byte) chunk
    const int lrow = tid >> 2;
    const int lc   = (tid & 3) * 16;
    const uint32_t sdst = (uint32_t)(lrow * AST + lc) * 2;

    auto load_kv = [&](int stage, int kb) {
        const size_t roff = head_elem + (size_t)(kb * 64 + lrow) * 64 + lc;
        const uint32_t sb = sKV + (uint32_t)stage * (2 * ATILE_B);
        const char* p0 = (const char*)(kh + roff);
        const char* p2 = (const char*)(vh + roff);
#pragma unroll
        for (int c = 0; c < 2; c++) {
            CP_ASYNC16(sb + 0 * ATILE_B + sdst + c * 16, p0 + c * 16);
            CP_ASYNC16(sb + 1 * ATILE_B + sdst + c * 16, p2 + c * 16);
        }
        CP_COMMIT();
    };

    const int nt = 2 * qb + 2;
    load_kv(0, 0);
    load_kv(1, 1);
    // first CP_WAIT(1) in the loop covers Q (group 0) + tile 0 (group 1)

    // --- these fragment loads need Q in smem: wait + sync once before loop
    CP_WAIT(1);
    __syncthreads();

    uint32_t aQh[4][4];
    {
        const uint32_t a_ld = (uint32_t)((wid * 16 + (lane & 15)) * AST + (lane >> 4) * 8) * 2;
#pragma unroll
        for (int ks = 0; ks < 4; ks++)
            LDSM_X4(aQh[ks][0], aQh[ks][1], aQh[ks][2], aQh[ks][3], sQh + a_ld + ks * 32);
    }

    const uint32_t b_ldK = (uint32_t)(((lane & 7) + ((lane >> 4) << 3)) * AST
                                      + ((lane >> 3) & 1) * 8) * 2;
    const uint32_t v_ld  = (uint32_t)((lane & 15) * AST + ((lane >> 4) << 3)) * 2;

    float O[8][4];
#pragma unroll
    for (int t = 0; t < 8; t++)
#pragma unroll
        for (int e = 0; e < 4; e++) O[t][e] = 0.f;
    float m1 = NEG_INF, m2 = NEG_INF, l1 = 0.f, l2 = 0.f;

    const int rowg1 = qb * 128 + wid * 16 + (lane >> 2);   // global query row (e<2)
    const int colb  = (lane & 3) * 2;

    for (int kt = 0; kt < nt; kt++) {
        // 3-stage pipeline: kt's data already awaited (prologue / previous iter)
        if (kt + 2 < nt) load_kv((kt + 2) % 3, kt + 2);

        const uint32_t sb  = sKV + (uint32_t)(kt % 3) * (2 * ATILE_B);
        const uint32_t sKh = sb;
        const uint32_t sVh = sb + ATILE_B;

        float S[8][4];
#pragma unroll
        for (int t = 0; t < 8; t++)
#pragma unroll
            for (int e = 0; e < 4; e++) S[t][e] = 0.f;

        // ---- S = Q K^T : 1-pass
#pragma unroll
        for (int ks = 0; ks < 4; ks++) {
            uint32_t fKh[4][4];
#pragma unroll
            for (int np = 0; np < 4; np++) {
                const uint32_t off = (uint32_t)(np * 16 * AST) * 2 + ks * 32;
                LDSM_X4(fKh[np][0], fKh[np][1], fKh[np][2], fKh[np][3], sKh + b_ldK + off);
            }
#pragma unroll
            for (int np = 0; np < 4; np++) {
                uint32_t b0[2] = {fKh[np][0], fKh[np][1]};
                MMA_F16(S[2 * np], aQh[ks], b0);
            }
#pragma unroll
            for (int np = 0; np < 4; np++) {
                uint32_t b1[2] = {fKh[np][2], fKh[np][3]};
                MMA_F16(S[2 * np + 1], aQh[ks], b1);
            }
        }

        // ---- causal mask (last two tiles cross the diagonal for this CTA)
        if (kt >= nt - 2) {
#pragma unroll
            for (int t = 0; t < 8; t++) {
#pragma unroll
                for (int e = 0; e < 4; e++) {
                    const int col = kt * 64 + t * 8 + colb + (e & 1);
                    const int row = rowg1 + (e >> 1) * 8;
                    if (col > row) S[t][e] = NEG_INF;
                }
            }
        }

        // ---- online softmax (exp2 domain)
        float mx1 = NEG_INF, mx2 = NEG_INF;
#pragma unroll
        for (int t = 0; t < 8; t++) {
            mx1 = fmaxf(mx1, fmaxf(S[t][0], S[t][1]));
            mx2 = fmaxf(mx2, fmaxf(S[t][2], S[t][3]));
        }
        mx1 = fmaxf(mx1, __shfl_xor_sync(0xffffffffu, mx1, 1));
        mx1 = fmaxf(mx1, __shfl_xor_sync(0xffffffffu, mx1, 2));
        mx2 = fmaxf(mx2, __shfl_xor_sync(0xffffffffu, mx2, 1));
        mx2 = fmaxf(mx2, __shfl_xor_sync(0xffffffffu, mx2, 2));

        const float mn1 = fmaxf(m1, mx1);
        const float mn2 = fmaxf(m2, mx2);
        const float c1 = ex2(m1 - mn1);
        const float c2 = ex2(m2 - mn2);
        l1 *= c1; l2 *= c2;
#pragma unroll
        for (int t = 0; t < 8; t++) {
            O[t][0] *= c1; O[t][1] *= c1;
            O[t][2] *= c2; O[t][3] *= c2;
        }
        float rs1 = 0.f, rs2 = 0.f;
#pragma unroll
        for (int t = 0; t < 8; t++) {
            S[t][0] = ex2(S[t][0] - mn1); rs1 += S[t][0];
            S[t][1] = ex2(S[t][1] - mn1); rs1 += S[t][1];
            S[t][2] = ex2(S[t][2] - mn2); rs2 += S[t][2];
            S[t][3] = ex2(S[t][3] - mn2); rs2 += S[t][3];
        }
        rs1 += __shfl_xor_sync(0xffffffffu, rs1, 1);
        rs1 += __shfl_xor_sync(0xffffffffu, rs1, 2);
        rs2 += __shfl_xor_sync(0xffffffffu, rs2, 1);
        rs2 += __shfl_xor_sync(0xffffffffu, rs2, 2);
        l1 += rs1; l2 += rs2;
        m1 = mn1; m2 = mn2;

        // ---- O += P V : 1-pass (P hi x V hi)
#pragma unroll
        for (int ks = 0; ks < 4; ks++) {
            uint32_t aPh[4];
            aPh[0] = pack_f16(S[2 * ks][0],     S[2 * ks][1]);
            aPh[1] = pack_f16(S[2 * ks][2],     S[2 * ks][3]);
            aPh[2] = pack_f16(S[2 * ks + 1][0], S[2 * ks + 1][1]);
            aPh[3] = pack_f16(S[2 * ks + 1][2], S[2 * ks + 1][3]);
            uint32_t fVh[4][4];
#pragma unroll
            for (int np = 0; np < 4; np++) {
                const uint32_t off = (uint32_t)(ks * 16 * AST) * 2 + np * 32;
                LDSM_X4_T(fVh[np][0], fVh[np][1], fVh[np][2], fVh[np][3], sVh + v_ld + off);
            }
#pragma unroll
            for (int np = 0; np < 4; np++) {
                uint32_t b0[2] = {fVh[np][0], fVh[np][1]};
                MMA_F16(O[2 * np], aPh, b0);
            }
#pragma unroll
            for (int np = 0; np < 4; np++) {
                uint32_t b1[2] = {fVh[np][2], fVh[np][3]};
                MMA_F16(O[2 * np + 1], aPh, b1);
            }
        }

        // ---- pipeline advance: single barrier per tile
        if (kt + 1 < nt) {
            if (kt + 2 < nt) { CP_WAIT(1); } else { CP_WAIT(0); }
            __syncthreads();
        }
    }

    // ---- epilogue: write f16 into (B,T,D)
    const float inv1 = 1.f / l1;
    const float inv2 = 1.f / l2;
    const size_t obase = (size_t)b * T_SEQ * D_MODEL + (size_t)h * 64;
#pragma unroll
    for (int t = 0; t < 8; t++) {
        const int d = t * 8 + colb;
        size_t i1 = obase + (size_t)rowg1 * D_MODEL + d;
        *(uint32_t*)&oh[i1] = pack_f16(O[t][0] * inv1, O[t][1] * inv1);
        size_t i2 = obase + (size_t)(rowg1 + 8) * D_MODEL + d;
        *(uint32_t*)&oh[i2] = pack_f16(O[t][2] * inv2, O[t][3] * inv2);
    }
}

// ---------------------------------------------------------------------------
extern "C" void kernel_launch(void* const* d_in, const int* in_sizes, int n_in,
                              void* d_out, int out_size)
{
    const float* x  = (const float*)d_in[0];
    const float* Wq = (const float*)d_in[1];
    const float* Wk = (const float*)d_in[2];
    const float* Wv = (const float*)d_in[3];
    const float* Wo = (const float*)d_in[4];

    float* out  = (float*)d_out;
    float* kout = out  + (size_t)M_ROWS * D_MODEL;
    float* vout = kout + (size_t)M_ROWS * D_MODEL;

    __half *xh, *wqh, *wkh, *wvh, *woh;
    __half *qhp, *khp, *vhp, *ahp;
    cudaGetSymbolAddress((void**)&xh,  g_xh);
    cudaGetSymbolAddress((void**)&wqh, g_wqh);
    cudaGetSymbolAddress((void**)&wkh, g_wkh);
    cudaGetSymbolAddress((void**)&wvh, g_wvh);
    cudaGetSymbolAddress((void**)&woh, g_woh);
    cudaGetSymbolAddress((void**)&qhp, g_qh);
    cudaGetSymbolAddress((void**)&khp, g_kh);
    cudaGetSymbolAddress((void**)&vhp, g_vh);
    cudaGetSymbolAddress((void**)&ahp, g_ah);

    cudaFuncSetAttribute(gemm_f16, cudaFuncAttributeMaxDynamicSharedMemorySize,
                         GEMM_SMEM_BYTES);
    cudaFuncSetAttribute(attn_mma, cudaFuncAttributeMaxDynamicSharedMemorySize,
                         ASMEM_BYTES);

    const int nx4 = M_ROWS * D_MODEL / 4;
    const int nw4 = D_MODEL * D_MODEL / 4;

    cvt_f16<<<(nx4 + 255) / 256, 256>>>(x, xh, nx4);
    CvtArgs ca;
    ca.src[0] = Wq; ca.hi[0] = wqh;
    ca.src[1] = Wk; ca.hi[1] = wkh;
    ca.src[2] = Wv; ca.hi[2] = wvh;
    ca.src[3] = Wo; ca.hi[3] = woh;
    cvt_f16m<<<dim3((nw4 + 255) / 256, 1, 4), 256>>>(ca, nw4);

    // ---- merged QKV GEMM (grid.z: 0=Q, 1=K, 2=V; all 1-pass)
    // Q pre-scale folds softmax 1/sqrt(hd) AND log2(e) for the exp2-domain softmax.
    GemmArgs qkv;
    qkv.Ah = xh;
    qkv.Bh[0] = wqh;
    qkv.Bh[1] = wkh;
    qkv.Bh[2] = wvh;
    qkv.Cf[0] = nullptr; qkv.Cf[1] = kout; qkv.Cf[2] = vout;
    qkv.Ch[0] = qhp;     qkv.Ch[1] = khp;  qkv.Ch[2] = vhp;
    qkv.scale[0] = 0.125f * 1.44269504f;   // 0.18033688
    qkv.scale[1] = 1.f; qkv.scale[2] = 1.f;
    qkv.split = 1;
    gemm_f16<<<dim3(D_MODEL / BN, M_ROWS / BM, 3), 256, GEMM_SMEM_BYTES>>>(qkv);

    attn_mma<<<dim3(T_SEQ / 128, N_HEADS, B_SIZE), 256, ASMEM_BYTES>>>(
        qhp, khp, vhp, ahp);

    // ---- O projection: 1-pass, fp32 output
    GemmArgs og;
    og.Ah = ahp;
    og.Bh[0] = woh;
    og.Cf[0] = out; og.Ch[0] = nullptr;
    og.scale[0] = 1.f; og.split = 0;
    og.Bh[1] = og.Bh[2] = nullptr;
    og.Cf[1] = og.Cf[2] = nullptr; og.Ch[1] = og.Ch[2] = nullptr;
    og.scale[1] = og.scale[2] = 1.f;
    gemm_f16<<<dim3(D_MODEL / BN, M_ROWS / BM, 1), 256, GEMM_SMEM_BYTES>>>(og);
}